// round 3
// baseline (speedup 1.0000x reference)
#include <cuda_runtime.h>
#include <math.h>

// ---------------- problem constants ----------------
#define BB      4
#define NH      16
#define NKV     4
#define HDIM    128
#define DMODEL  2048
#define SQV     1024
#define SQA     64
#define SCACHE  256
#define STOT    1344          // SCACHE + SQV + SQA
#define NQROWS  (BB*NH*SQA)   // 4096 action query rows

// ---------------- device scratch ----------------
__device__ float g_K[BB*NKV*STOT*HDIM];        // unified keys   [b][kv][s][d]
__device__ float g_V[BB*NKV*STOT*HDIM];        // unified values [b][kv][s][d]
__device__ float g_q[BB*NH*SQA*HDIM];          // action queries [b][h][s][d]
__device__ float g_scores[NQROWS*STOT];        // attention probs scratch
__device__ float g_attn[BB*SQA*NH*HDIM];       // attention out  [(b*64+s)][h*128+d]

// ---------------- zero-init all atomic-accumulated buffers ----------------
__global__ void zero_kernel(float* out)
{
    int tid = blockIdx.x*blockDim.x + threadIdx.x;
    int stride = gridDim.x*blockDim.x;
    const int nK = BB*NKV*STOT*HDIM;       // 2752512
    const int nq = BB*NH*SQA*HDIM;         // 524288
    const int na = BB*SQA*NH*HDIM;         // 524288
    const int no = BB*SQA*DMODEL;          // 524288
    for (int i = tid; i < nK; i += stride) { g_K[i] = 0.f; g_V[i] = 0.f; }
    for (int i = tid; i < nq; i += stride) g_q[i] = 0.f;
    for (int i = tid; i < na; i += stride) g_attn[i] = 0.f;
    for (int i = tid; i < no; i += stride) out[i] = 0.f;
}

// ---------------- output index mapping for GEMM epilogues ----------------
// map 0: plain row-major r*N+c
// map 1: kv-vlm   rows r=b*1024+s, cols c=kv*128+d  -> seq offset 256
// map 2: kv-act   rows r=b*64+s,   cols c=kv*128+d  -> seq offset 1280
// map 3: q-act    rows r=b*64+s,   cols c=h*128+d   -> g_q
__device__ __forceinline__ int out_index(int map, int r, int c, int N) {
    switch (map) {
        case 1: { int b=r>>10, s=r&1023, kv=c>>7, d=c&127;
                  return (((b*NKV+kv)*STOT) + SCACHE + s)*HDIM + d; }
        case 2: { int b=r>>6, s=r&63, kv=c>>7, d=c&127;
                  return (((b*NKV+kv)*STOT) + (SCACHE+SQV) + s)*HDIM + d; }
        case 3: { int b=r>>6, s=r&63, h=c>>7, d=c&127;
                  return (((b*NH+h)*SQA) + s)*HDIM + d; }
        default: return r*N + c;
    }
}

// ---------------- fp32 SGEMM with split-K: 128x128 tile, 8x8 microtile ----------------
// dest: 0 -> g_K, 1 -> g_V, 2 -> g_q, 3 -> Cext.  asrc: 1 -> A = g_attn.
// blockIdx.z selects K-slab of length klen; gridDim.z>1 => atomicAdd epilogue.
__global__ __launch_bounds__(256) void sgemm_kernel(
    const float* __restrict__ Aext, const float* __restrict__ W,
    float* Cext, int M, int N, int K, int map, int dest, int asrc, int klen)
{
    __shared__ float As[128][8];
    __shared__ float Bs[8][128];

    const float* A = asrc ? g_attn : Aext;
    int tid = threadIdx.x;
    int tx = tid & 15, ty = tid >> 4;
    int m0 = blockIdx.y * 128, n0 = blockIdx.x * 128;
    int kstart = blockIdx.z * klen;
    int kend   = kstart + klen;

    float acc[8][8];
#pragma unroll
    for (int i = 0; i < 8; i++)
#pragma unroll
        for (int j = 0; j < 8; j++) acc[i][j] = 0.f;

    int ar = tid >> 1, ac = (tid & 1) * 4;     // A tile: 128 rows x 8 cols
    int br = tid >> 5, bc = (tid & 31) * 4;    // B tile: 8 rows x 128 cols

    // register-prefetch pipeline over K slabs of 8
    float4 av = *(const float4*)&A[(size_t)(m0 + ar) * K + kstart + ac];
    float4 bv = *(const float4*)&W[(size_t)(kstart + br) * N + n0 + bc];

    for (int k0 = kstart; k0 < kend; k0 += 8) {
        *(float4*)&As[ar][ac] = av;
        *(float4*)&Bs[br][bc] = bv;
        __syncthreads();
        if (k0 + 8 < kend) {
            av = *(const float4*)&A[(size_t)(m0 + ar) * K + k0 + 8 + ac];
            bv = *(const float4*)&W[(size_t)(k0 + 8 + br) * N + n0 + bc];
        }
#pragma unroll
        for (int kk = 0; kk < 8; kk++) {
            float a[8], b[8];
#pragma unroll
            for (int i = 0; i < 8; i++) a[i] = As[ty*8 + i][kk];
            float4 b0 = *(const float4*)&Bs[kk][tx*8];
            float4 b1 = *(const float4*)&Bs[kk][tx*8 + 4];
            b[0]=b0.x; b[1]=b0.y; b[2]=b0.z; b[3]=b0.w;
            b[4]=b1.x; b[5]=b1.y; b[6]=b1.z; b[7]=b1.w;
#pragma unroll
            for (int i = 0; i < 8; i++)
#pragma unroll
                for (int j = 0; j < 8; j++)
                    acc[i][j] += a[i] * b[j];
        }
        __syncthreads();
    }

    float* C = (dest == 0) ? g_K : (dest == 1) ? g_V : (dest == 2) ? g_q : Cext;
    bool split = (gridDim.z > 1);
#pragma unroll
    for (int i = 0; i < 8; i++) {
        int r = m0 + ty*8 + i;
#pragma unroll
        for (int j = 0; j < 8; j++) {
            int c = n0 + tx*8 + j;
            int idx = out_index(map, r, c, N);
            if (split) atomicAdd(&C[idx], acc[i][j]);
            else       C[idx] = acc[i][j];
        }
    }
}

// ---------------- copy KV cache into unified K/V (seq [0,256)) ----------------
__global__ void copy_cache_kernel(const float* __restrict__ kc, const float* __restrict__ vc)
{
    const int n = BB*NKV*SCACHE*HDIM;  // 524288
    for (int i = blockIdx.x*blockDim.x + threadIdx.x; i < n; i += gridDim.x*blockDim.x) {
        int d  = i & 127;
        int s  = (i >> 7) & 255;
        int bk = i >> 15;                         // b*NKV + kv
        int dst = (bk*STOT + s)*HDIM + d;
        g_K[dst] = kc[i];
        g_V[dst] = vc[i];
    }
}

// ---------------- RoPE (in place), fast-math-safe range reduction ----------------
// which: 0 -> g_K (stot=1344), 1 -> g_q (stot=64)
__global__ void rope_kernel(int which, const int* __restrict__ pos,
                            int nh, int seqlen, int s_off, int total)
{
    int idx = blockIdx.x*blockDim.x + threadIdx.x;
    if (idx >= total) return;
    int i = idx & 63;
    int rest = idx >> 6;
    int s = rest % seqlen; rest /= seqlen;
    int hh = rest % nh;
    int b  = rest / nh;

    float* X = (which == 0) ? g_K : g_q;
    int stot = (which == 0) ? STOT : SQA;

    int p = pos[b*seqlen + s];
    float inv = exp2f(-0.20762050593046868f * (float)i);   // 10000^(-i/64)
    float ang = (float)p * inv;                            // fp32 round like reference
    double ad  = (double)ang;
    double red = ad - rint(ad * 0.15915494309189535) * 6.283185307179586;
    float c  = cosf((float)red);
    float sn = sinf((float)red);

    size_t base = ((size_t)((b*nh + hh)*stot + s_off + s)) * HDIM;
    float x1 = X[base + i], x2 = X[base + 64 + i];
    X[base + i]      = x1*c - x2*sn;
    X[base + 64 + i] = x2*c + x1*sn;
}

// ---------------- scores = softcap(QK^T/sqrt(d)) + mask ----------------
__global__ __launch_bounds__(256) void score_kernel(const float* __restrict__ mask)
{
    __shared__ float Qs[16][65];
    __shared__ float Ks[16][65];

    int bh = blockIdx.y;
    int b = bh >> 4, h = bh & 15, kv = h >> 2;
    int s0 = blockIdx.x * 64;

    const float* Q  = g_q + (size_t)bh * SQA * HDIM;
    const float* Kp = g_K + (size_t)(b*NKV + kv) * STOT * HDIM;

    int tid = threadIdx.x;
    int tx = tid & 15, ty = tid >> 4;
    int row = tid >> 2, c4 = (tid & 3) * 4;

    float acc[4][4];
#pragma unroll
    for (int i = 0; i < 4; i++)
#pragma unroll
        for (int j = 0; j < 4; j++) acc[i][j] = 0.f;

    for (int d0 = 0; d0 < HDIM; d0 += 16) {
        float4 qv = *(const float4*)&Q[row*HDIM + d0 + c4];
        float4 kk4 = *(const float4*)&Kp[(size_t)(s0 + row)*HDIM + d0 + c4];
        Qs[c4+0][row]=qv.x;  Qs[c4+1][row]=qv.y;  Qs[c4+2][row]=qv.z;  Qs[c4+3][row]=qv.w;
        Ks[c4+0][row]=kk4.x; Ks[c4+1][row]=kk4.y; Ks[c4+2][row]=kk4.z; Ks[c4+3][row]=kk4.w;
        __syncthreads();
#pragma unroll
        for (int kk = 0; kk < 16; kk++) {
            float a[4], bb[4];
#pragma unroll
            for (int i = 0; i < 4; i++) a[i]  = Qs[kk][ty*4 + i];
#pragma unroll
            for (int j = 0; j < 4; j++) bb[j] = Ks[kk][tx*4 + j];
#pragma unroll
            for (int i = 0; i < 4; i++)
#pragma unroll
                for (int j = 0; j < 4; j++)
                    acc[i][j] += a[i] * bb[j];
        }
        __syncthreads();
    }

    const float scale = 0.08838834764831845f;  // 1/sqrt(128)
#pragma unroll
    for (int i = 0; i < 4; i++) {
        int q = ty*4 + i;
#pragma unroll
        for (int j = 0; j < 4; j++) {
            int s = s0 + tx*4 + j;
            float v = acc[i][j] * scale;
            v = tanhf(v * 0.02f) * 50.0f
              + mask[(size_t)b*(1088*1344) + (size_t)(1024 + q)*1344 + s];
            g_scores[(size_t)(bh*SQA + q)*STOT + s] = v;
        }
    }
}

// ---------------- row softmax, 1 warp per row (1344 = 42*32) ----------------
__global__ void softmax_kernel()
{
    int row  = blockIdx.x*4 + (threadIdx.x >> 5);   // 0..4095
    int lane = threadIdx.x & 31;
    float* p = g_scores + (size_t)row * STOT;

    float vals[42];
    float m = -1e30f;
#pragma unroll
    for (int i = 0; i < 42; i++) { vals[i] = p[i*32 + lane]; m = fmaxf(m, vals[i]); }
#pragma unroll
    for (int off = 16; off > 0; off >>= 1) m = fmaxf(m, __shfl_xor_sync(0xffffffffu, m, off));
    float sum = 0.f;
#pragma unroll
    for (int i = 0; i < 42; i++) { vals[i] = __expf(vals[i] - m); sum += vals[i]; }
#pragma unroll
    for (int off = 16; off > 0; off >>= 1) sum += __shfl_xor_sync(0xffffffffu, sum, off);
    float invs = 1.0f / sum;
#pragma unroll
    for (int i = 0; i < 42; i++) p[i*32 + lane] = vals[i] * invs;
}

// ---------------- out = P @ V, split over keys: grid (64 bh, 6 k-chunks of 224) ----------------
__global__ __launch_bounds__(256) void pv_kernel()
{
    __shared__ float Vs[32][128];
    __shared__ float Ws[64][36];

    int bh = blockIdx.x;
    int b = bh >> 4, h = bh & 15, kv = h >> 2;
    int kbase = blockIdx.y * 224;
    const float* Vp = g_V + (size_t)(b*NKV + kv) * STOT * HDIM;
    const float* Wp = g_scores + (size_t)bh * SQA * STOT;

    int tid = threadIdx.x;
    int tx = tid & 31, ty = tid >> 5;      // tx: d/4 group, ty: q/8 group

    float acc[8][4];
#pragma unroll
    for (int i = 0; i < 8; i++)
#pragma unroll
        for (int j = 0; j < 4; j++) acc[i][j] = 0.f;

    int wq = tid >> 2, wc = (tid & 3) * 8;  // score tile load coords

    for (int kk0 = 0; kk0 < 224; kk0 += 32) {
        int k0 = kbase + kk0;
#pragma unroll
        for (int it = 0; it < 4; it++) {
            int idx = tid + it*256;
            int r = idx >> 5, cc = (idx & 31) * 4;
            *(float4*)&Vs[r][cc] = *(const float4*)&Vp[(size_t)(k0 + r)*HDIM + cc];
        }
        *(float4*)&Ws[wq][wc]     = *(const float4*)&Wp[(size_t)wq*STOT + k0 + wc];
        *(float4*)&Ws[wq][wc + 4] = *(const float4*)&Wp[(size_t)wq*STOT + k0 + wc + 4];
        __syncthreads();
#pragma unroll
        for (int kk = 0; kk < 32; kk++) {
            float4 v4 = *(const float4*)&Vs[kk][tx*4];
#pragma unroll
            for (int i = 0; i < 8; i++) {
                float w = Ws[ty*8 + i][kk];
                acc[i][0] += w * v4.x;
                acc[i][1] += w * v4.y;
                acc[i][2] += w * v4.z;
                acc[i][3] += w * v4.w;
            }
        }
        __syncthreads();
    }

#pragma unroll
    for (int i = 0; i < 8; i++) {
        int q = ty*8 + i;
        float* dst = &g_attn[(size_t)(b*SQA + q)*(NH*HDIM) + h*HDIM + tx*4];
        atomicAdd(&dst[0], acc[i][0]);
        atomicAdd(&dst[1], acc[i][1]);
        atomicAdd(&dst[2], acc[i][2]);
        atomicAdd(&dst[3], acc[i][3]);
    }
}

// ---------------- launch ----------------
extern "C" void kernel_launch(void* const* d_in, const int* in_sizes, int n_in,
                              void* d_out, int out_size)
{
    (void)in_sizes; (void)n_in; (void)out_size;
    const float* mask    = (const float*)d_in[0];
    const int*   pos_vlm = (const int*)  d_in[1];
    const int*   pos_act = (const int*)  d_in[2];
    const float* h_vlm   = (const float*)d_in[3];
    const float* h_act   = (const float*)d_in[4];
    const float* k_cache = (const float*)d_in[5];
    const float* v_cache = (const float*)d_in[6];
    // d_in[7] = Wq_vlm: unused (q_vlm rows are discarded by reference)
    const float* Wk_vlm  = (const float*)d_in[8];
    const float* Wv_vlm  = (const float*)d_in[9];
    const float* Wq_act  = (const float*)d_in[10];
    const float* Wk_act  = (const float*)d_in[11];
    const float* Wv_act  = (const float*)d_in[12];
    const float* Wo_act  = (const float*)d_in[13];
    float* out = (float*)d_out;

    // zero all atomically-accumulated buffers, then copy cache
    zero_kernel<<<1024, 256>>>(out);
    copy_cache_kernel<<<512, 256>>>(k_cache, v_cache);

    // projections: split-K for full-chip parallelism
    sgemm_kernel<<<dim3(4, 32, 2), 256>>>(h_vlm, Wk_vlm, nullptr, 4096,  512, 2048, 1, 0, 0, 1024);
    sgemm_kernel<<<dim3(4, 32, 2), 256>>>(h_vlm, Wv_vlm, nullptr, 4096,  512, 2048, 1, 1, 0, 1024);
    sgemm_kernel<<<dim3(16, 2, 8), 256>>>(h_act, Wq_act, nullptr,  256, 2048, 2048, 3, 2, 0,  256);
    sgemm_kernel<<<dim3(4, 2, 32), 256>>>(h_act, Wk_act, nullptr,  256,  512, 2048, 2, 0, 0,   64);
    sgemm_kernel<<<dim3(4, 2, 32), 256>>>(h_act, Wv_act, nullptr,  256,  512, 2048, 2, 1, 0,   64);

    // RoPE (k_vlm, k_act, q_act) — cache keys are NOT roped (matches reference)
    {
        int tot = BB*NKV*SQV*64;
        rope_kernel<<<(tot + 255)/256, 256>>>(0, pos_vlm, NKV, SQV, SCACHE, tot);
    }
    {
        int tot = BB*NKV*SQA*64;
        rope_kernel<<<(tot + 255)/256, 256>>>(0, pos_act, NKV, SQA, SCACHE + SQV, tot);
    }
    {
        int tot = BB*NH*SQA*64;
        rope_kernel<<<(tot + 255)/256, 256>>>(1, pos_act, NH, SQA, 0, tot);
    }

    // attention (action queries only)
    score_kernel<<<dim3(21, 64), 256>>>(mask);
    softmax_kernel<<<1024, 128>>>();
    pv_kernel<<<dim3(64, 6), 256>>>();

    // output projection: (256 x 2048) @ Wo_act -> d_out, split-K 8
    sgemm_kernel<<<dim3(16, 2, 8), 256>>>(nullptr, Wo_act, out, 256, 2048, 2048, 0, 3, 1, 256);
}

// round 8
// speedup vs baseline: 1.5889x; 1.5889x over previous
#include <cuda_runtime.h>
#include <cuda_bf16.h>
#include <math.h>
#include <stdint.h>

// ---------------- problem constants ----------------
#define BB      4
#define NH      16
#define NKV     4
#define HDIM    128
#define DMODEL  2048
#define SQV     1024
#define SQA     64
#define SCACHE  256
#define STOT    1344
#define NQROWS  (BB*NH*SQA)

// ---------------- fp32 scratch ----------------
__device__ float g_K[BB*NKV*STOT*HDIM];
__device__ float g_V[BB*NKV*STOT*HDIM];
__device__ float g_q[BB*NH*SQA*HDIM];
__device__ float g_scores[NQROWS*STOT];
__device__ float g_attn[BB*SQA*NH*HDIM];

// ---------------- bf16 split operands (hi + lo) ----------------
__device__ __nv_bfloat16 g_hv_hi[4096*2048], g_hv_lo[4096*2048];
__device__ __nv_bfloat16 g_ha_hi[256*2048],  g_ha_lo[256*2048];
__device__ __nv_bfloat16 g_at_hi[256*2048],  g_at_lo[256*2048];
__device__ __nv_bfloat16 g_wkv_hi[512*2048], g_wkv_lo[512*2048];   // Wk_vlm^T [N][K]
__device__ __nv_bfloat16 g_wvv_hi[512*2048], g_wvv_lo[512*2048];   // Wv_vlm^T
__device__ __nv_bfloat16 g_wq_hi[2048*2048], g_wq_lo[2048*2048];   // Wq_act^T
__device__ __nv_bfloat16 g_wka_hi[512*2048], g_wka_lo[512*2048];   // Wk_act^T
__device__ __nv_bfloat16 g_wva_hi[512*2048], g_wva_lo[512*2048];   // Wv_act^T
__device__ __nv_bfloat16 g_wo_hi[2048*2048], g_wo_lo[2048*2048];   // Wo_act^T

// ================= PTX helpers (sm_80-baseline only: no tcgen05) =================
__device__ __forceinline__ uint32_t smem_to_u32(const void* p) {
    uint32_t a;
    asm("{ .reg .u64 t; cvta.to.shared.u64 t, %1; cvt.u32.u64 %0, t; }" : "=r"(a) : "l"(p));
    return a;
}
#define CP_ASYNC16(sm, gm) \
    asm volatile("cp.async.cg.shared.global [%0], [%1], 16;" :: "r"(sm), "l"(gm))
#define CP_COMMIT() asm volatile("cp.async.commit_group;" ::: "memory")
#define CP_WAIT(n)  asm volatile("cp.async.wait_group %0;" :: "n"(n) : "memory")

__device__ __forceinline__ void ldsm_x4(uint32_t* r, uint32_t addr) {
    asm volatile("ldmatrix.sync.aligned.m8n8.x4.shared.b16 {%0,%1,%2,%3}, [%4];"
        : "=r"(r[0]), "=r"(r[1]), "=r"(r[2]), "=r"(r[3]) : "r"(addr));
}
__device__ __forceinline__ void mma_bf16(float* d, const uint32_t* a, const uint32_t* b) {
    asm volatile("mma.sync.aligned.m16n8k16.row.col.f32.bf16.bf16.f32 "
        "{%0,%1,%2,%3}, {%4,%5,%6,%7}, {%8,%9}, {%0,%1,%2,%3};"
        : "+f"(d[0]), "+f"(d[1]), "+f"(d[2]), "+f"(d[3])
        : "r"(a[0]), "r"(a[1]), "r"(a[2]), "r"(a[3]), "r"(b[0]), "r"(b[1]));
}
// swizzle<3,4,3>: XOR bits[6:4] with bits[9:7] (128B rows)
__device__ __forceinline__ uint32_t swz(uint32_t off) { return off ^ ((off >> 3) & 0x70); }

// ---------------- output index mapping ----------------
__device__ __forceinline__ int out_index(int map, int r, int c, int N) {
    switch (map) {
        case 1: { int b=r>>10, s=r&1023, kv=c>>7, d=c&127;
                  return (((b*NKV+kv)*STOT) + SCACHE + s)*HDIM + d; }
        case 2: { int b=r>>6, s=r&63, kv=c>>7, d=c&127;
                  return (((b*NKV+kv)*STOT) + (SCACHE+SQV) + s)*HDIM + d; }
        case 3: { int b=r>>6, s=r&63, h=c>>7, d=c&127;
                  return (((b*NH+h)*SQA) + s)*HDIM + d; }
        default: return r*N + c;
    }
}

// ---------------- HMMA bf16-split GEMM: C = A @ B^T ----------------
// A: [M][K] bf16 hi/lo.  B: [N][K] bf16 hi/lo (weights pre-transposed).
// CTA tile 128x128, K-chunk 64, double-buffered cp.async.
// 8 warps: wm = wid&1 (64 rows), wn = wid>>1 (32 cols); warp tile 64x32.
// dest: 0->g_K 1->g_V 2->g_q 3->Cext.  split-K via blockIdx.z.
#define TCG_SMEM_BYTES (131072)
__global__ void __launch_bounds__(256) tc_gemm(
    const __nv_bfloat16* __restrict__ Ahi, const __nv_bfloat16* __restrict__ Alo,
    const __nv_bfloat16* __restrict__ Bhi, const __nv_bfloat16* __restrict__ Blo,
    float* Cext, int M, int N, int K, int map, int dest, int klen)
{
    extern __shared__ char smem[];
    uint32_t sbase = smem_to_u32(smem);

    const int tid = threadIdx.x, lane = tid & 31, wid = tid >> 5;
    const int wm = wid & 1, wn = wid >> 1;
    const int m0 = blockIdx.y * 128, n0 = blockIdx.x * 128;
    const int kstart = blockIdx.z * klen;
    const int nch = klen >> 6;

    const __nv_bfloat16* s0 = Ahi; const __nv_bfloat16* s1 = Alo;
    const __nv_bfloat16* s2 = Bhi; const __nv_bfloat16* s3 = Blo;

    // stage layout: [stage][tile] each 16KB; tile rows 128 x 64 bf16 (128B rows)
    auto load_stage = [&](int stage, int kof) {
        uint32_t stbase = sbase + stage * 65536;
#pragma unroll
        for (int t = 0; t < 4; ++t) {
            const __nv_bfloat16* src = (t == 0) ? s0 : (t == 1) ? s1 : (t == 2) ? s2 : s3;
            int row0 = (t < 2) ? m0 : n0;
#pragma unroll
            for (int it = 0; it < 4; ++it) {
                int idx = tid + it * 256;
                int r = idx >> 3, ch = idx & 7;
                uint32_t so = stbase + t * 16384 + swz((uint32_t)(r * 128 + ch * 16));
                const __nv_bfloat16* gp = src + (size_t)(row0 + r) * K + kof + ch * 8;
                CP_ASYNC16(so, gp);
            }
        }
    };

    float acc[4][4][4];
#pragma unroll
    for (int i = 0; i < 4; ++i)
#pragma unroll
        for (int j = 0; j < 4; ++j)
#pragma unroll
            for (int k = 0; k < 4; ++k) acc[i][j][k] = 0.f;

    load_stage(0, kstart);
    CP_COMMIT();

    // fragment address components (within a 128x64bf16 tile)
    const uint32_t aRow = wm * 64 + (lane & 15);
    const uint32_t aKof = (lane >> 4) * 8;            // bf16 units
    const uint32_t bRow = wn * 32 + ((lane >> 4) * 8) + (lane & 7);
    const uint32_t bKof = ((lane >> 3) & 1) * 8;

    for (int c = 0; c < nch; ++c) {
        if (c + 1 < nch) { load_stage((c + 1) & 1, kstart + (c + 1) * 64); CP_COMMIT(); CP_WAIT(1); }
        else             { CP_WAIT(0); }
        __syncthreads();

        uint32_t st = sbase + (c & 1) * 65536;
        uint32_t tAhi = st, tAlo = st + 16384, tBhi = st + 32768, tBlo = st + 49152;

#pragma unroll
        for (int ks = 0; ks < 4; ++ks) {
            uint32_t ahi[4][4], alo[4][4];
#pragma unroll
            for (int mt = 0; mt < 4; ++mt) {
                uint32_t off = swz((aRow + mt * 16) * 128 + (ks * 16 + aKof) * 2);
                ldsm_x4(ahi[mt], tAhi + off);
                ldsm_x4(alo[mt], tAlo + off);
            }
            uint32_t bhi[2][4], blo[2][4];
#pragma unroll
            for (int g = 0; g < 2; ++g) {
                uint32_t off = swz((bRow + g * 16) * 128 + (ks * 16 + bKof) * 2);
                ldsm_x4(bhi[g], tBhi + off);
                ldsm_x4(blo[g], tBlo + off);
            }
#pragma unroll
            for (int mt = 0; mt < 4; ++mt)
#pragma unroll
                for (int nt = 0; nt < 4; ++nt) {
                    const uint32_t* bh = &bhi[nt >> 1][(nt & 1) * 2];
                    const uint32_t* bl = &blo[nt >> 1][(nt & 1) * 2];
                    mma_bf16(acc[mt][nt], ahi[mt], bh);
                    mma_bf16(acc[mt][nt], ahi[mt], bl);
                    mma_bf16(acc[mt][nt], alo[mt], bh);
                }
        }
        __syncthreads();
    }

    // epilogue
    float* C = (dest == 0) ? g_K : (dest == 1) ? g_V : (dest == 2) ? g_q : Cext;
    bool split = (gridDim.z > 1);
#pragma unroll
    for (int mt = 0; mt < 4; ++mt)
#pragma unroll
        for (int nt = 0; nt < 4; ++nt) {
            int mrow = m0 + wm * 64 + mt * 16 + (lane >> 2);
            int ncol = n0 + wn * 32 + nt * 8 + 2 * (lane & 3);
#pragma unroll
            for (int e = 0; e < 4; ++e) {
                int r = mrow + (e >> 1) * 8;
                int cc = ncol + (e & 1);
                int idx = out_index(map, r, cc, N);
                if (split) atomicAdd(&C[idx], acc[mt][nt][e]);
                else       C[idx] = acc[mt][nt][e];
            }
        }
}

// ---------------- conversions ----------------
__global__ void convA_kernel(const float4* __restrict__ x,
                             __nv_bfloat162* __restrict__ hi,
                             __nv_bfloat162* __restrict__ lo, int n4)
{
    int i = blockIdx.x*blockDim.x + threadIdx.x;
    if (i >= n4) return;
    float4 v = x[i];
    __nv_bfloat16 h0 = __float2bfloat16(v.x), h1 = __float2bfloat16(v.y);
    __nv_bfloat16 h2 = __float2bfloat16(v.z), h3 = __float2bfloat16(v.w);
    __nv_bfloat16 l0 = __float2bfloat16(v.x - __bfloat162float(h0));
    __nv_bfloat16 l1 = __float2bfloat16(v.y - __bfloat162float(h1));
    __nv_bfloat16 l2 = __float2bfloat16(v.z - __bfloat162float(h2));
    __nv_bfloat16 l3 = __float2bfloat16(v.w - __bfloat162float(h3));
    hi[i*2+0] = __halves2bfloat162(h0, h1);
    hi[i*2+1] = __halves2bfloat162(h2, h3);
    lo[i*2+0] = __halves2bfloat162(l0, l1);
    lo[i*2+1] = __halves2bfloat162(l2, l3);
}

__global__ void convWT_kernel(const float* __restrict__ W,
                              __nv_bfloat16* __restrict__ bhi,
                              __nv_bfloat16* __restrict__ blo, int Kd, int Nd)
{
    __shared__ float t[32][33];
    int k0 = blockIdx.y*32, n0 = blockIdx.x*32;
    int tx = threadIdx.x, ty = threadIdx.y;   // (32, 8)
#pragma unroll
    for (int i = 0; i < 4; ++i)
        t[ty + i*8][tx] = W[(size_t)(k0 + ty + i*8)*Nd + n0 + tx];
    __syncthreads();
#pragma unroll
    for (int i = 0; i < 4; ++i) {
        int n = ty + i*8;
        float v = t[tx][n];
        __nv_bfloat16 h = __float2bfloat16(v);
        __nv_bfloat16 l = __float2bfloat16(v - __bfloat162float(h));
        size_t o = (size_t)(n0 + n)*Kd + k0 + tx;
        bhi[o] = h; blo[o] = l;
    }
}

// ---------------- zero-init ALL atomically-accumulated buffers ----------------
// g_q (split-K q_act GEMM), g_attn (pv), out (Wo GEMM), AND the action seq rows
// [1280,1344) of g_K/g_V (split-K k_act/v_act GEMMs atomicAdd there).
__global__ void zero_kernel(float* out)
{
    int tid = blockIdx.x*blockDim.x + threadIdx.x;
    int stride = gridDim.x*blockDim.x;
    const int nq = BB*NH*SQA*HDIM;
    const int na = BB*SQA*NH*HDIM;
    const int no = BB*SQA*DMODEL;
    const int nact = BB*NKV*SQA*HDIM;   // 131072 action K/V elements
    for (int i = tid; i < nq; i += stride) g_q[i] = 0.f;
    for (int i = tid; i < na; i += stride) g_attn[i] = 0.f;
    for (int i = tid; i < no; i += stride) out[i] = 0.f;
    for (int i = tid; i < nact; i += stride) {
        int d  = i & 127;
        int s  = (i >> 7) & 63;
        int bk = i >> 13;                       // b*NKV + kv
        int idx = (bk*STOT + (SCACHE + SQV) + s)*HDIM + d;
        g_K[idx] = 0.f;
        g_V[idx] = 0.f;
    }
}

// ---------------- copy KV cache into unified K/V ----------------
__global__ void copy_cache_kernel(const float* __restrict__ kc, const float* __restrict__ vc)
{
    const int n = BB*NKV*SCACHE*HDIM;
    for (int i = blockIdx.x*blockDim.x + threadIdx.x; i < n; i += gridDim.x*blockDim.x) {
        int d  = i & 127;
        int s  = (i >> 7) & 255;
        int bk = i >> 15;
        int dst = (bk*STOT + s)*HDIM + d;
        g_K[dst] = kc[i];
        g_V[dst] = vc[i];
    }
}

// ---------------- RoPE (in place) ----------------
__global__ void rope_kernel(int which, const int* __restrict__ pos,
                            int nh, int seqlen, int s_off, int total)
{
    int idx = blockIdx.x*blockDim.x + threadIdx.x;
    if (idx >= total) return;
    int i = idx & 63;
    int rest = idx >> 6;
    int s = rest % seqlen; rest /= seqlen;
    int hh = rest % nh;
    int b  = rest / nh;

    float* X = (which == 0) ? g_K : g_q;
    int stot = (which == 0) ? STOT : SQA;

    int p = pos[b*seqlen + s];
    float inv = exp2f(-0.20762050593046868f * (float)i);
    float ang = (float)p * inv;
    double ad  = (double)ang;
    double red = ad - rint(ad * 0.15915494309189535) * 6.283185307179586;
    float c  = cosf((float)red);
    float sn = sinf((float)red);

    size_t base = ((size_t)((b*nh + hh)*stot + s_off + s)) * HDIM;
    float x1 = X[base + i], x2 = X[base + 64 + i];
    X[base + i]      = x1*c - x2*sn;
    X[base + 64 + i] = x2*c + x1*sn;
}

// ---------------- scores = softcap(QK^T/sqrt(d)) + mask ----------------
__global__ __launch_bounds__(256) void score_kernel(const float* __restrict__ mask)
{
    __shared__ float Qs[16][65];
    __shared__ float Ks[16][65];

    int bh = blockIdx.y;
    int b = bh >> 4, h = bh & 15, kv = h >> 2;
    int s0 = blockIdx.x * 64;

    const float* Q  = g_q + (size_t)bh * SQA * HDIM;
    const float* Kp = g_K + (size_t)(b*NKV + kv) * STOT * HDIM;

    int tid = threadIdx.x;
    int tx = tid & 15, ty = tid >> 4;
    int row = tid >> 2, c4 = (tid & 3) * 4;

    float acc[4][4];
#pragma unroll
    for (int i = 0; i < 4; i++)
#pragma unroll
        for (int j = 0; j < 4; j++) acc[i][j] = 0.f;

    for (int d0 = 0; d0 < HDIM; d0 += 16) {
        float4 qv  = *(const float4*)&Q[row*HDIM + d0 + c4];
        float4 kk4 = *(const float4*)&Kp[(size_t)(s0 + row)*HDIM + d0 + c4];
        Qs[c4+0][row]=qv.x;  Qs[c4+1][row]=qv.y;  Qs[c4+2][row]=qv.z;  Qs[c4+3][row]=qv.w;
        Ks[c4+0][row]=kk4.x; Ks[c4+1][row]=kk4.y; Ks[c4+2][row]=kk4.z; Ks[c4+3][row]=kk4.w;
        __syncthreads();
#pragma unroll
        for (int kk = 0; kk < 16; kk++) {
            float a[4], bb[4];
#pragma unroll
            for (int i = 0; i < 4; i++) a[i]  = Qs[kk][ty*4 + i];
#pragma unroll
            for (int j = 0; j < 4; j++) bb[j] = Ks[kk][tx*4 + j];
#pragma unroll
            for (int i = 0; i < 4; i++)
#pragma unroll
                for (int j = 0; j < 4; j++)
                    acc[i][j] += a[i] * bb[j];
        }
        __syncthreads();
    }

    const float scale = 0.08838834764831845f;
#pragma unroll
    for (int i = 0; i < 4; i++) {
        int q = ty*4 + i;
#pragma unroll
        for (int j = 0; j < 4; j++) {
            int s = s0 + tx*4 + j;
            float v = acc[i][j] * scale;
            v = tanhf(v * 0.02f) * 50.0f
              + mask[(size_t)b*(1088*1344) + (size_t)(1024 + q)*1344 + s];
            g_scores[(size_t)(bh*SQA + q)*STOT + s] = v;
        }
    }
}

// ---------------- row softmax ----------------
__global__ void softmax_kernel()
{
    int row  = blockIdx.x*4 + (threadIdx.x >> 5);
    int lane = threadIdx.x & 31;
    float* p = g_scores + (size_t)row * STOT;

    float vals[42];
    float m = -1e30f;
#pragma unroll
    for (int i = 0; i < 42; i++) { vals[i] = p[i*32 + lane]; m = fmaxf(m, vals[i]); }
#pragma unroll
    for (int off = 16; off > 0; off >>= 1) m = fmaxf(m, __shfl_xor_sync(0xffffffffu, m, off));
    float sum = 0.f;
#pragma unroll
    for (int i = 0; i < 42; i++) { vals[i] = __expf(vals[i] - m); sum += vals[i]; }
#pragma unroll
    for (int off = 16; off > 0; off >>= 1) sum += __shfl_xor_sync(0xffffffffu, sum, off);
    float invs = 1.0f / sum;
#pragma unroll
    for (int i = 0; i < 42; i++) p[i*32 + lane] = vals[i] * invs;
}

// ---------------- out = P @ V, split over keys ----------------
__global__ __launch_bounds__(256) void pv_kernel()
{
    __shared__ float Vs[32][128];
    __shared__ float Ws[64][36];

    int bh = blockIdx.x;
    int b = bh >> 4, h = bh & 15, kv = h >> 2;
    int kbase = blockIdx.y * 224;
    const float* Vp = g_V + (size_t)(b*NKV + kv) * STOT * HDIM;
    const float* Wp = g_scores + (size_t)bh * SQA * STOT;

    int tid = threadIdx.x;
    int tx = tid & 31, ty = tid >> 5;

    float acc[8][4];
#pragma unroll
    for (int i = 0; i < 8; i++)
#pragma unroll
        for (int j = 0; j < 4; j++) acc[i][j] = 0.f;

    int wq = tid >> 2, wc = (tid & 3) * 8;

    for (int kk0 = 0; kk0 < 224; kk0 += 32) {
        int k0 = kbase + kk0;
#pragma unroll
        for (int it = 0; it < 4; it++) {
            int idx = tid + it*256;
            int r = idx >> 5, cc = (idx & 31) * 4;
            *(float4*)&Vs[r][cc] = *(const float4*)&Vp[(size_t)(k0 + r)*HDIM + cc];
        }
        *(float4*)&Ws[wq][wc]     = *(const float4*)&Wp[(size_t)wq*STOT + k0 + wc];
        *(float4*)&Ws[wq][wc + 4] = *(const float4*)&Wp[(size_t)wq*STOT + k0 + wc + 4];
        __syncthreads();
#pragma unroll
        for (int kk = 0; kk < 32; kk++) {
            float4 v4 = *(const float4*)&Vs[kk][tx*4];
#pragma unroll
            for (int i = 0; i < 8; i++) {
                float w = Ws[ty*8 + i][kk];
                acc[i][0] += w * v4.x;
                acc[i][1] += w * v4.y;
                acc[i][2] += w * v4.z;
                acc[i][3] += w * v4.w;
            }
        }
        __syncthreads();
    }

#pragma unroll
    for (int i = 0; i < 8; i++) {
        int q = ty*8 + i;
        float* dst = &g_attn[(size_t)(b*SQA + q)*(NH*HDIM) + h*HDIM + tx*4];
        atomicAdd(&dst[0], acc[i][0]);
        atomicAdd(&dst[1], acc[i][1]);
        atomicAdd(&dst[2], acc[i][2]);
        atomicAdd(&dst[3], acc[i][3]);
    }
}

// ---------------- launch ----------------
extern "C" void kernel_launch(void* const* d_in, const int* in_sizes, int n_in,
                              void* d_out, int out_size)
{
    (void)in_sizes; (void)n_in; (void)out_size;
    const float* mask    = (const float*)d_in[0];
    const int*   pos_vlm = (const int*)  d_in[1];
    const int*   pos_act = (const int*)  d_in[2];
    const float* h_vlm   = (const float*)d_in[3];
    const float* h_act   = (const float*)d_in[4];
    const float* k_cache = (const float*)d_in[5];
    const float* v_cache = (const float*)d_in[6];
    // d_in[7] = Wq_vlm: unused (q_vlm rows are discarded by reference)
    const float* Wk_vlm  = (const float*)d_in[8];
    const float* Wv_vlm  = (const float*)d_in[9];
    const float* Wq_act  = (const float*)d_in[10];
    const float* Wk_act  = (const float*)d_in[11];
    const float* Wv_act  = (const float*)d_in[12];
    const float* Wo_act  = (const float*)d_in[13];
    float* out = (float*)d_out;

    void *p_hv_hi, *p_hv_lo, *p_ha_hi, *p_ha_lo, *p_at_hi, *p_at_lo;
    void *p_wkv_hi, *p_wkv_lo, *p_wvv_hi, *p_wvv_lo, *p_wq_hi, *p_wq_lo;
    void *p_wka_hi, *p_wka_lo, *p_wva_hi, *p_wva_lo, *p_wo_hi, *p_wo_lo, *p_attn;
    cudaGetSymbolAddress(&p_hv_hi, g_hv_hi);   cudaGetSymbolAddress(&p_hv_lo, g_hv_lo);
    cudaGetSymbolAddress(&p_ha_hi, g_ha_hi);   cudaGetSymbolAddress(&p_ha_lo, g_ha_lo);
    cudaGetSymbolAddress(&p_at_hi, g_at_hi);   cudaGetSymbolAddress(&p_at_lo, g_at_lo);
    cudaGetSymbolAddress(&p_wkv_hi, g_wkv_hi); cudaGetSymbolAddress(&p_wkv_lo, g_wkv_lo);
    cudaGetSymbolAddress(&p_wvv_hi, g_wvv_hi); cudaGetSymbolAddress(&p_wvv_lo, g_wvv_lo);
    cudaGetSymbolAddress(&p_wq_hi, g_wq_hi);   cudaGetSymbolAddress(&p_wq_lo, g_wq_lo);
    cudaGetSymbolAddress(&p_wka_hi, g_wka_hi); cudaGetSymbolAddress(&p_wka_lo, g_wka_lo);
    cudaGetSymbolAddress(&p_wva_hi, g_wva_hi); cudaGetSymbolAddress(&p_wva_lo, g_wva_lo);
    cudaGetSymbolAddress(&p_wo_hi, g_wo_hi);   cudaGetSymbolAddress(&p_wo_lo, g_wo_lo);
    cudaGetSymbolAddress(&p_attn, g_attn);

    cudaFuncSetAttribute(tc_gemm, cudaFuncAttributeMaxDynamicSharedMemorySize, TCG_SMEM_BYTES);

    zero_kernel<<<1024, 256>>>(out);
    copy_cache_kernel<<<512, 256>>>(k_cache, v_cache);

    // conversions
    convA_kernel<<<(4096*2048/4 + 255)/256, 256>>>((const float4*)h_vlm,
        (__nv_bfloat162*)p_hv_hi, (__nv_bfloat162*)p_hv_lo, 4096*2048/4);
    convA_kernel<<<(256*2048/4 + 255)/256, 256>>>((const float4*)h_act,
        (__nv_bfloat162*)p_ha_hi, (__nv_bfloat162*)p_ha_lo, 256*2048/4);
    convWT_kernel<<<dim3(16, 64), dim3(32, 8)>>>(Wk_vlm, (__nv_bfloat16*)p_wkv_hi, (__nv_bfloat16*)p_wkv_lo, 2048, 512);
    convWT_kernel<<<dim3(16, 64), dim3(32, 8)>>>(Wv_vlm, (__nv_bfloat16*)p_wvv_hi, (__nv_bfloat16*)p_wvv_lo, 2048, 512);
    convWT_kernel<<<dim3(64, 64), dim3(32, 8)>>>(Wq_act, (__nv_bfloat16*)p_wq_hi,  (__nv_bfloat16*)p_wq_lo,  2048, 2048);
    convWT_kernel<<<dim3(16, 64), dim3(32, 8)>>>(Wk_act, (__nv_bfloat16*)p_wka_hi, (__nv_bfloat16*)p_wka_lo, 2048, 512);
    convWT_kernel<<<dim3(16, 64), dim3(32, 8)>>>(Wv_act, (__nv_bfloat16*)p_wva_hi, (__nv_bfloat16*)p_wva_lo, 2048, 512);
    convWT_kernel<<<dim3(64, 64), dim3(32, 8)>>>(Wo_act, (__nv_bfloat16*)p_wo_hi,  (__nv_bfloat16*)p_wo_lo,  2048, 2048);

    // projections on HMMA
    tc_gemm<<<dim3(4, 32, 1), 256, TCG_SMEM_BYTES>>>(
        (const __nv_bfloat16*)p_hv_hi, (const __nv_bfloat16*)p_hv_lo,
        (const __nv_bfloat16*)p_wkv_hi, (const __nv_bfloat16*)p_wkv_lo,
        nullptr, 4096, 512, 2048, 1, 0, 2048);
    tc_gemm<<<dim3(4, 32, 1), 256, TCG_SMEM_BYTES>>>(
        (const __nv_bfloat16*)p_hv_hi, (const __nv_bfloat16*)p_hv_lo,
        (const __nv_bfloat16*)p_wvv_hi, (const __nv_bfloat16*)p_wvv_lo,
        nullptr, 4096, 512, 2048, 1, 1, 2048);
    tc_gemm<<<dim3(16, 2, 4), 256, TCG_SMEM_BYTES>>>(
        (const __nv_bfloat16*)p_ha_hi, (const __nv_bfloat16*)p_ha_lo,
        (const __nv_bfloat16*)p_wq_hi, (const __nv_bfloat16*)p_wq_lo,
        nullptr, 256, 2048, 2048, 3, 2, 512);
    tc_gemm<<<dim3(4, 2, 16), 256, TCG_SMEM_BYTES>>>(
        (const __nv_bfloat16*)p_ha_hi, (const __nv_bfloat16*)p_ha_lo,
        (const __nv_bfloat16*)p_wka_hi, (const __nv_bfloat16*)p_wka_lo,
        nullptr, 256, 512, 2048, 2, 0, 128);
    tc_gemm<<<dim3(4, 2, 16), 256, TCG_SMEM_BYTES>>>(
        (const __nv_bfloat16*)p_ha_hi, (const __nv_bfloat16*)p_ha_lo,
        (const __nv_bfloat16*)p_wva_hi, (const __nv_bfloat16*)p_wva_lo,
        nullptr, 256, 512, 2048, 2, 1, 128);

    // RoPE
    {
        int tot = BB*NKV*SQV*64;
        rope_kernel<<<(tot + 255)/256, 256>>>(0, pos_vlm, NKV, SQV, SCACHE, tot);
    }
    {
        int tot = BB*NKV*SQA*64;
        rope_kernel<<<(tot + 255)/256, 256>>>(0, pos_act, NKV, SQA, SCACHE + SQV, tot);
    }
    {
        int tot = BB*NH*SQA*64;
        rope_kernel<<<(tot + 255)/256, 256>>>(1, pos_act, NH, SQA, 0, tot);
    }

    // attention
    score_kernel<<<dim3(21, 64), 256>>>(mask);
    softmax_kernel<<<1024, 128>>>();
    pv_kernel<<<dim3(64, 6), 256>>>();

    // output projection: convert attn, then HMMA GEMM
    convA_kernel<<<(256*2048/4 + 255)/256, 256>>>((const float4*)p_attn,
        (__nv_bfloat162*)p_at_hi, (__nv_bfloat162*)p_at_lo, 256*2048/4);
    tc_gemm<<<dim3(16, 2, 4), 256, TCG_SMEM_BYTES>>>(
        (const __nv_bfloat16*)p_at_hi, (const __nv_bfloat16*)p_at_lo,
        (const __nv_bfloat16*)p_wo_hi, (const __nv_bfloat16*)p_wo_lo,
        out, 256, 2048, 2048, 0, 3, 512);
}

// round 9
// speedup vs baseline: 2.7858x; 1.7533x over previous
#include <cuda_runtime.h>
#include <cuda_bf16.h>
#include <math.h>
#include <stdint.h>

// ---------------- problem constants ----------------
#define BB      4
#define NH      16
#define NKV     4
#define HDIM    128
#define DMODEL  2048
#define SQV     1024
#define SQA     64
#define SCACHE  256
#define STOT    1344
#define NQROWS  (BB*NH*SQA)

// ---------------- fp32 scratch ----------------
__device__ float g_K[BB*NKV*STOT*HDIM];
__device__ float g_V[BB*NKV*STOT*HDIM];
__device__ float g_q[BB*NH*SQA*HDIM];
__device__ float g_scores[NQROWS*STOT];
__device__ float g_attn[BB*SQA*NH*HDIM];

// ---------------- bf16 split operands (hi + lo) ----------------
__device__ __nv_bfloat16 g_hv_hi[4096*2048], g_hv_lo[4096*2048];
__device__ __nv_bfloat16 g_ha_hi[256*2048],  g_ha_lo[256*2048];
__device__ __nv_bfloat16 g_at_hi[256*2048],  g_at_lo[256*2048];
__device__ __nv_bfloat16 g_wkv_hi[512*2048], g_wkv_lo[512*2048];
__device__ __nv_bfloat16 g_wvv_hi[512*2048], g_wvv_lo[512*2048];
__device__ __nv_bfloat16 g_wq_hi[2048*2048], g_wq_lo[2048*2048];
__device__ __nv_bfloat16 g_wka_hi[512*2048], g_wka_lo[512*2048];
__device__ __nv_bfloat16 g_wva_hi[512*2048], g_wva_lo[512*2048];
__device__ __nv_bfloat16 g_wo_hi[2048*2048], g_wo_lo[2048*2048];

// attention bf16 operands
__device__ __nv_bfloat16 g_qh[BB*NH*SQA*HDIM],  g_ql[BB*NH*SQA*HDIM];
__device__ __nv_bfloat16 g_Kh[BB*NKV*STOT*HDIM], g_Kl[BB*NKV*STOT*HDIM];
__device__ __nv_bfloat16 g_Vth[BB*NKV*HDIM*STOT], g_Vtl[BB*NKV*HDIM*STOT];  // V^T [d][s]
__device__ __nv_bfloat16 g_Ph[NQROWS*STOT], g_Pl[NQROWS*STOT];

// ================= PTX helpers (sm_80-baseline only: no tcgen05) =================
__device__ __forceinline__ uint32_t smem_to_u32(const void* p) {
    uint32_t a;
    asm("{ .reg .u64 t; cvta.to.shared.u64 t, %1; cvt.u32.u64 %0, t; }" : "=r"(a) : "l"(p));
    return a;
}
#define CP_ASYNC16(sm, gm) \
    asm volatile("cp.async.cg.shared.global [%0], [%1], 16;" :: "r"(sm), "l"(gm))
#define CP_COMMIT() asm volatile("cp.async.commit_group;" ::: "memory")
#define CP_WAIT(n)  asm volatile("cp.async.wait_group %0;" :: "n"(n) : "memory")

__device__ __forceinline__ void ldsm_x4(uint32_t* r, uint32_t addr) {
    asm volatile("ldmatrix.sync.aligned.m8n8.x4.shared.b16 {%0,%1,%2,%3}, [%4];"
        : "=r"(r[0]), "=r"(r[1]), "=r"(r[2]), "=r"(r[3]) : "r"(addr));
}
__device__ __forceinline__ void mma_bf16(float* d, const uint32_t* a, const uint32_t* b) {
    asm volatile("mma.sync.aligned.m16n8k16.row.col.f32.bf16.bf16.f32 "
        "{%0,%1,%2,%3}, {%4,%5,%6,%7}, {%8,%9}, {%0,%1,%2,%3};"
        : "+f"(d[0]), "+f"(d[1]), "+f"(d[2]), "+f"(d[3])
        : "r"(a[0]), "r"(a[1]), "r"(a[2]), "r"(a[3]), "r"(b[0]), "r"(b[1]));
}
__device__ __forceinline__ uint32_t swz(uint32_t off) { return off ^ ((off >> 3) & 0x70); }

// ---------------- output index mapping ----------------
__device__ __forceinline__ int out_index(int map, int r, int c, int N) {
    switch (map) {
        case 1: { int b=r>>10, s=r&1023, kv=c>>7, d=c&127;
                  return (((b*NKV+kv)*STOT) + SCACHE + s)*HDIM + d; }
        case 2: { int b=r>>6, s=r&63, kv=c>>7, d=c&127;
                  return (((b*NKV+kv)*STOT) + (SCACHE+SQV) + s)*HDIM + d; }
        case 3: { int b=r>>6, s=r&63, h=c>>7, d=c&127;
                  return (((b*NH+h)*SQA) + s)*HDIM + d; }
        default: return r*N + c;
    }
}

// ---------------- HMMA bf16-split GEMM: C = A @ B^T (validated) ----------------
#define TCG_SMEM_BYTES (131072)
__global__ void __launch_bounds__(256) tc_gemm(
    const __nv_bfloat16* __restrict__ Ahi, const __nv_bfloat16* __restrict__ Alo,
    const __nv_bfloat16* __restrict__ Bhi, const __nv_bfloat16* __restrict__ Blo,
    float* Cext, int M, int N, int K, int map, int dest, int klen)
{
    extern __shared__ char smem[];
    uint32_t sbase = smem_to_u32(smem);

    const int tid = threadIdx.x, lane = tid & 31, wid = tid >> 5;
    const int wm = wid & 1, wn = wid >> 1;
    const int m0 = blockIdx.y * 128, n0 = blockIdx.x * 128;
    const int kstart = blockIdx.z * klen;
    const int nch = klen >> 6;

    const __nv_bfloat16* s0 = Ahi; const __nv_bfloat16* s1 = Alo;
    const __nv_bfloat16* s2 = Bhi; const __nv_bfloat16* s3 = Blo;

    auto load_stage = [&](int stage, int kof) {
        uint32_t stbase = sbase + stage * 65536;
#pragma unroll
        for (int t = 0; t < 4; ++t) {
            const __nv_bfloat16* src = (t == 0) ? s0 : (t == 1) ? s1 : (t == 2) ? s2 : s3;
            int row0 = (t < 2) ? m0 : n0;
#pragma unroll
            for (int it = 0; it < 4; ++it) {
                int idx = tid + it * 256;
                int r = idx >> 3, ch = idx & 7;
                uint32_t so = stbase + t * 16384 + swz((uint32_t)(r * 128 + ch * 16));
                const __nv_bfloat16* gp = src + (size_t)(row0 + r) * K + kof + ch * 8;
                CP_ASYNC16(so, gp);
            }
        }
    };

    float acc[4][4][4];
#pragma unroll
    for (int i = 0; i < 4; ++i)
#pragma unroll
        for (int j = 0; j < 4; ++j)
#pragma unroll
            for (int k = 0; k < 4; ++k) acc[i][j][k] = 0.f;

    load_stage(0, kstart);
    CP_COMMIT();

    const uint32_t aRow = wm * 64 + (lane & 15);
    const uint32_t aKof = (lane >> 4) * 8;
    const uint32_t bRow = wn * 32 + ((lane >> 4) * 8) + (lane & 7);
    const uint32_t bKof = ((lane >> 3) & 1) * 8;

    for (int c = 0; c < nch; ++c) {
        if (c + 1 < nch) { load_stage((c + 1) & 1, kstart + (c + 1) * 64); CP_COMMIT(); CP_WAIT(1); }
        else             { CP_WAIT(0); }
        __syncthreads();

        uint32_t st = sbase + (c & 1) * 65536;
        uint32_t tAhi = st, tAlo = st + 16384, tBhi = st + 32768, tBlo = st + 49152;

#pragma unroll
        for (int ks = 0; ks < 4; ++ks) {
            uint32_t ahi[4][4], alo[4][4];
#pragma unroll
            for (int mt = 0; mt < 4; ++mt) {
                uint32_t off = swz((aRow + mt * 16) * 128 + (ks * 16 + aKof) * 2);
                ldsm_x4(ahi[mt], tAhi + off);
                ldsm_x4(alo[mt], tAlo + off);
            }
            uint32_t bhi[2][4], blo[2][4];
#pragma unroll
            for (int g = 0; g < 2; ++g) {
                uint32_t off = swz((bRow + g * 16) * 128 + (ks * 16 + bKof) * 2);
                ldsm_x4(bhi[g], tBhi + off);
                ldsm_x4(blo[g], tBlo + off);
            }
#pragma unroll
            for (int mt = 0; mt < 4; ++mt)
#pragma unroll
                for (int nt = 0; nt < 4; ++nt) {
                    const uint32_t* bh = &bhi[nt >> 1][(nt & 1) * 2];
                    const uint32_t* bl = &blo[nt >> 1][(nt & 1) * 2];
                    mma_bf16(acc[mt][nt], ahi[mt], bh);
                    mma_bf16(acc[mt][nt], ahi[mt], bl);
                    mma_bf16(acc[mt][nt], alo[mt], bh);
                }
        }
        __syncthreads();
    }

    float* C = (dest == 0) ? g_K : (dest == 1) ? g_V : (dest == 2) ? g_q : Cext;
    bool split = (gridDim.z > 1);
#pragma unroll
    for (int mt = 0; mt < 4; ++mt)
#pragma unroll
        for (int nt = 0; nt < 4; ++nt) {
            int mrow = m0 + wm * 64 + mt * 16 + (lane >> 2);
            int ncol = n0 + wn * 32 + nt * 8 + 2 * (lane & 3);
#pragma unroll
            for (int e = 0; e < 4; ++e) {
                int r = mrow + (e >> 1) * 8;
                int cc = ncol + (e & 1);
                int idx = out_index(map, r, cc, N);
                if (split) atomicAdd(&C[idx], acc[mt][nt][e]);
                else       C[idx] = acc[mt][nt][e];
            }
        }
}

// ---------------- HMMA attention scores: softcap(QK^T/sqrt(d)) + mask ----------------
// grid (21 s-chunks, 64 bh), block 256. Tile 64q x 64s, K=128 (2 chunks of 64).
// smem 8 tiles x 8KB: [qh c0][qh c1][ql c0][ql c1][Kh c0][Kh c1][Kl c0][Kl c1]
__global__ void __launch_bounds__(256) score_hmma(const float* __restrict__ mask)
{
    extern __shared__ char smem[];
    uint32_t sbase = smem_to_u32(smem);

    const int tid = threadIdx.x, lane = tid & 31, wid = tid >> 5;
    const int wm = wid & 1, wn = wid >> 1;          // wm: 32q, wn: 16s
    int bh = blockIdx.y;
    int b = bh >> 4, h = bh & 15, kv = h >> 2;
    int s0 = blockIdx.x * 64;
    (void)h;

#pragma unroll
    for (int it = 0; it < 2; ++it) {
        int idx = tid + it * 256;
        int r = idx >> 3, ch = idx & 7;
        uint32_t so = swz((uint32_t)(r * 128 + ch * 16));
        size_t qoff = (size_t)(bh * 64 + r) * HDIM;
        size_t koff = (size_t)((b * NKV + kv) * STOT + s0 + r) * HDIM;
#pragma unroll
        for (int c = 0; c < 2; ++c) {
            CP_ASYNC16(sbase + (0 + c) * 8192 + so, g_qh + qoff + c * 64 + ch * 8);
            CP_ASYNC16(sbase + (2 + c) * 8192 + so, g_ql + qoff + c * 64 + ch * 8);
            CP_ASYNC16(sbase + (4 + c) * 8192 + so, g_Kh + koff + c * 64 + ch * 8);
            CP_ASYNC16(sbase + (6 + c) * 8192 + so, g_Kl + koff + c * 64 + ch * 8);
        }
    }
    CP_COMMIT();
    CP_WAIT(0);
    __syncthreads();

    float acc[2][2][4];
#pragma unroll
    for (int i = 0; i < 2; ++i)
#pragma unroll
        for (int j = 0; j < 2; ++j)
#pragma unroll
            for (int k = 0; k < 4; ++k) acc[i][j][k] = 0.f;

    const uint32_t aRow = wm * 32 + (lane & 15);
    const uint32_t aKof = (lane >> 4) * 8;
    const uint32_t bRow = wn * 16 + ((lane >> 4) * 8) + (lane & 7);
    const uint32_t bKof = ((lane >> 3) & 1) * 8;

#pragma unroll
    for (int c = 0; c < 2; ++c) {
        uint32_t tqh = sbase + (0 + c) * 8192, tql = sbase + (2 + c) * 8192;
        uint32_t tkh = sbase + (4 + c) * 8192, tkl = sbase + (6 + c) * 8192;
#pragma unroll
        for (int ks = 0; ks < 4; ++ks) {
            uint32_t ahi[2][4], alo[2][4];
#pragma unroll
            for (int mt = 0; mt < 2; ++mt) {
                uint32_t off = swz((aRow + mt * 16) * 128 + (ks * 16 + aKof) * 2);
                ldsm_x4(ahi[mt], tqh + off);
                ldsm_x4(alo[mt], tql + off);
            }
            uint32_t bh4[4], bl4[4];
            {
                uint32_t off = swz(bRow * 128 + (ks * 16 + bKof) * 2);
                ldsm_x4(bh4, tkh + off);
                ldsm_x4(bl4, tkl + off);
            }
#pragma unroll
            for (int mt = 0; mt < 2; ++mt)
#pragma unroll
                for (int nt = 0; nt < 2; ++nt) {
                    mma_bf16(acc[mt][nt], ahi[mt], &bh4[nt * 2]);
                    mma_bf16(acc[mt][nt], ahi[mt], &bl4[nt * 2]);
                    mma_bf16(acc[mt][nt], alo[mt], &bh4[nt * 2]);
                }
        }
    }

    const float scale = 0.08838834764831845f;
#pragma unroll
    for (int mt = 0; mt < 2; ++mt)
#pragma unroll
        for (int nt = 0; nt < 2; ++nt)
#pragma unroll
            for (int e = 0; e < 4; ++e) {
                int q = wm * 32 + mt * 16 + (lane >> 2) + (e >> 1) * 8;
                int s = s0 + wn * 16 + nt * 8 + 2 * (lane & 3) + (e & 1);
                float v = acc[mt][nt][e] * scale;
                v = tanhf(v * 0.02f) * 50.0f
                  + mask[(size_t)b * (1088 * 1344) + (size_t)(1024 + q) * 1344 + s];
                g_scores[(size_t)(bh * 64 + q) * STOT + s] = v;
            }
}

// ---------------- HMMA P @ V: grid (64 bh, 7 k-chunks of 192) ----------------
// Tile 64q x 128d. smem stage 48KB: Ph@0, Pl@8K, Vth@16K, Vtl@32K. Double-buffered.
__global__ void __launch_bounds__(256) pv_hmma()
{
    extern __shared__ char smem[];
    uint32_t sbase = smem_to_u32(smem);

    const int tid = threadIdx.x, lane = tid & 31, wid = tid >> 5;
    const int wm = wid & 1, wn = wid >> 1;          // wm: 32q, wn: 32d
    int bh = blockIdx.x;
    int b = bh >> 4, h = bh & 15, kv = h >> 2;
    int kc0 = blockIdx.y * 192;

    size_t prow0 = (size_t)bh * 64;
    size_t vrow0 = (size_t)(b * NKV + kv) * HDIM;

    auto load_sub = [&](int stage, int kc) {
        uint32_t stb = sbase + stage * 49152;
#pragma unroll
        for (int it = 0; it < 2; ++it) {
            int idx = tid + it * 256;
            int r = idx >> 3, ch = idx & 7;
            uint32_t so = swz((uint32_t)(r * 128 + ch * 16));
            const __nv_bfloat16* ph = g_Ph + (prow0 + r) * STOT + kc + ch * 8;
            const __nv_bfloat16* pl = g_Pl + (prow0 + r) * STOT + kc + ch * 8;
            CP_ASYNC16(stb + so, ph);
            CP_ASYNC16(stb + 8192 + so, pl);
        }
#pragma unroll
        for (int it = 0; it < 4; ++it) {
            int idx = tid + it * 256;
            int r = idx >> 3, ch = idx & 7;
            uint32_t so = swz((uint32_t)(r * 128 + ch * 16));
            const __nv_bfloat16* vh = g_Vth + (vrow0 + r) * STOT + kc + ch * 8;
            const __nv_bfloat16* vl = g_Vtl + (vrow0 + r) * STOT + kc + ch * 8;
            CP_ASYNC16(stb + 16384 + so, vh);
            CP_ASYNC16(stb + 32768 + so, vl);
        }
    };

    float acc[2][4][4];
#pragma unroll
    for (int i = 0; i < 2; ++i)
#pragma unroll
        for (int j = 0; j < 4; ++j)
#pragma unroll
            for (int k = 0; k < 4; ++k) acc[i][j][k] = 0.f;

    load_sub(0, kc0);
    CP_COMMIT();

    const uint32_t aRow = wm * 32 + (lane & 15);
    const uint32_t aKof = (lane >> 4) * 8;
    const uint32_t bRow = wn * 32 + ((lane >> 4) * 8) + (lane & 7);
    const uint32_t bKof = ((lane >> 3) & 1) * 8;

    for (int sub = 0; sub < 3; ++sub) {
        if (sub + 1 < 3) { load_sub((sub + 1) & 1, kc0 + (sub + 1) * 64); CP_COMMIT(); CP_WAIT(1); }
        else             { CP_WAIT(0); }
        __syncthreads();

        uint32_t st = sbase + (sub & 1) * 49152;
        uint32_t tph = st, tpl = st + 8192, tvh = st + 16384, tvl = st + 32768;

#pragma unroll
        for (int ks = 0; ks < 4; ++ks) {
            uint32_t ahi[2][4], alo[2][4];
#pragma unroll
            for (int mt = 0; mt < 2; ++mt) {
                uint32_t off = swz((aRow + mt * 16) * 128 + (ks * 16 + aKof) * 2);
                ldsm_x4(ahi[mt], tph + off);
                ldsm_x4(alo[mt], tpl + off);
            }
            uint32_t bhi[2][4], blo[2][4];
#pragma unroll
            for (int g = 0; g < 2; ++g) {
                uint32_t off = swz((bRow + g * 16) * 128 + (ks * 16 + bKof) * 2);
                ldsm_x4(bhi[g], tvh + off);
                ldsm_x4(blo[g], tvl + off);
            }
#pragma unroll
            for (int mt = 0; mt < 2; ++mt)
#pragma unroll
                for (int nt = 0; nt < 4; ++nt) {
                    const uint32_t* bh4 = &bhi[nt >> 1][(nt & 1) * 2];
                    const uint32_t* bl4 = &blo[nt >> 1][(nt & 1) * 2];
                    mma_bf16(acc[mt][nt], ahi[mt], bh4);
                    mma_bf16(acc[mt][nt], ahi[mt], bl4);
                    mma_bf16(acc[mt][nt], alo[mt], bh4);
                }
        }
        __syncthreads();
    }

#pragma unroll
    for (int mt = 0; mt < 2; ++mt)
#pragma unroll
        for (int nt = 0; nt < 4; ++nt)
#pragma unroll
            for (int e = 0; e < 4; ++e) {
                int q = wm * 32 + mt * 16 + (lane >> 2) + (e >> 1) * 8;
                int d = wn * 32 + nt * 8 + 2 * (lane & 3) + (e & 1);
                atomicAdd(&g_attn[(size_t)(b * SQA + q) * (NH * HDIM) + h * HDIM + d],
                          acc[mt][nt][e]);
            }
}

// ---------------- conversions ----------------
__global__ void convA_kernel(const float4* __restrict__ x,
                             __nv_bfloat162* __restrict__ hi,
                             __nv_bfloat162* __restrict__ lo, int n4)
{
    int i = blockIdx.x*blockDim.x + threadIdx.x;
    if (i >= n4) return;
    float4 v = x[i];
    __nv_bfloat16 h0 = __float2bfloat16(v.x), h1 = __float2bfloat16(v.y);
    __nv_bfloat16 h2 = __float2bfloat16(v.z), h3 = __float2bfloat16(v.w);
    __nv_bfloat16 l0 = __float2bfloat16(v.x - __bfloat162float(h0));
    __nv_bfloat16 l1 = __float2bfloat16(v.y - __bfloat162float(h1));
    __nv_bfloat16 l2 = __float2bfloat16(v.z - __bfloat162float(h2));
    __nv_bfloat16 l3 = __float2bfloat16(v.w - __bfloat162float(h3));
    hi[i*2+0] = __halves2bfloat162(h0, h1);
    hi[i*2+1] = __halves2bfloat162(h2, h3);
    lo[i*2+0] = __halves2bfloat162(l0, l1);
    lo[i*2+1] = __halves2bfloat162(l2, l3);
}

__global__ void convWT_kernel(const float* __restrict__ W,
                              __nv_bfloat16* __restrict__ bhi,
                              __nv_bfloat16* __restrict__ blo, int Kd, int Nd)
{
    __shared__ float t[32][33];
    int k0 = blockIdx.y*32, n0 = blockIdx.x*32;
    int tx = threadIdx.x, ty = threadIdx.y;
#pragma unroll
    for (int i = 0; i < 4; ++i)
        t[ty + i*8][tx] = W[(size_t)(k0 + ty + i*8)*Nd + n0 + tx];
    __syncthreads();
#pragma unroll
    for (int i = 0; i < 4; ++i) {
        int n = ty + i*8;
        float v = t[tx][n];
        __nv_bfloat16 h = __float2bfloat16(v);
        __nv_bfloat16 l = __float2bfloat16(v - __bfloat162float(h));
        size_t o = (size_t)(n0 + n)*Kd + k0 + tx;
        bhi[o] = h; blo[o] = l;
    }
}

// V [bk][s][d] -> V^T [bk][d][s] bf16 hi/lo
__global__ void convVT_kernel()
{
    __shared__ float t[32][33];
    int z  = blockIdx.z;              // b*NKV + kv
    int s0 = blockIdx.y*32;
    int d0 = blockIdx.x*32;
    int tx = threadIdx.x, ty = threadIdx.y;
    const float* V = g_V + (size_t)z*STOT*HDIM;
#pragma unroll
    for (int i = 0; i < 4; ++i)
        t[ty + i*8][tx] = V[(size_t)(s0 + ty + i*8)*HDIM + d0 + tx];
    __syncthreads();
#pragma unroll
    for (int i = 0; i < 4; ++i) {
        int d = ty + i*8;
        float v = t[tx][d];
        __nv_bfloat16 h = __float2bfloat16(v);
        __nv_bfloat16 l = __float2bfloat16(v - __bfloat162float(h));
        size_t o = (size_t)z*HDIM*STOT + (size_t)(d0 + d)*STOT + s0 + tx;
        g_Vth[o] = h; g_Vtl[o] = l;
    }
}

// ---------------- zero-init ALL atomically-accumulated buffers ----------------
__global__ void zero_kernel(float* out)
{
    int tid = blockIdx.x*blockDim.x + threadIdx.x;
    int stride = gridDim.x*blockDim.x;
    const int nq = BB*NH*SQA*HDIM;
    const int na = BB*SQA*NH*HDIM;
    const int no = BB*SQA*DMODEL;
    const int nact = BB*NKV*SQA*HDIM;
    for (int i = tid; i < nq; i += stride) g_q[i] = 0.f;
    for (int i = tid; i < na; i += stride) g_attn[i] = 0.f;
    for (int i = tid; i < no; i += stride) out[i] = 0.f;
    for (int i = tid; i < nact; i += stride) {
        int d  = i & 127;
        int s  = (i >> 7) & 63;
        int bk = i >> 13;
        int idx = (bk*STOT + (SCACHE + SQV) + s)*HDIM + d;
        g_K[idx] = 0.f;
        g_V[idx] = 0.f;
    }
}

// ---------------- copy KV cache into unified K/V ----------------
__global__ void copy_cache_kernel(const float* __restrict__ kc, const float* __restrict__ vc)
{
    const int n = BB*NKV*SCACHE*HDIM;
    for (int i = blockIdx.x*blockDim.x + threadIdx.x; i < n; i += gridDim.x*blockDim.x) {
        int d  = i & 127;
        int s  = (i >> 7) & 255;
        int bk = i >> 15;
        int dst = (bk*STOT + s)*HDIM + d;
        g_K[dst] = kc[i];
        g_V[dst] = vc[i];
    }
}

// ---------------- RoPE (in place) ----------------
__global__ void rope_kernel(int which, const int* __restrict__ pos,
                            int nh, int seqlen, int s_off, int total)
{
    int idx = blockIdx.x*blockDim.x + threadIdx.x;
    if (idx >= total) return;
    int i = idx & 63;
    int rest = idx >> 6;
    int s = rest % seqlen; rest /= seqlen;
    int hh = rest % nh;
    int b  = rest / nh;

    float* X = (which == 0) ? g_K : g_q;
    int stot = (which == 0) ? STOT : SQA;

    int p = pos[b*seqlen + s];
    float inv = exp2f(-0.20762050593046868f * (float)i);
    float ang = (float)p * inv;
    double ad  = (double)ang;
    double red = ad - rint(ad * 0.15915494309189535) * 6.283185307179586;
    float c  = cosf((float)red);
    float sn = sinf((float)red);

    size_t base = ((size_t)((b*nh + hh)*stot + s_off + s)) * HDIM;
    float x1 = X[base + i], x2 = X[base + 64 + i];
    X[base + i]      = x1*c - x2*sn;
    X[base + 64 + i] = x2*c + x1*sn;
}

// ---------------- row softmax: also emit P as bf16 hi/lo ----------------
__global__ void softmax_kernel()
{
    int row  = blockIdx.x*4 + (threadIdx.x >> 5);
    int lane = threadIdx.x & 31;
    const float* p = g_scores + (size_t)row * STOT;

    float vals[42];
    float m = -1e30f;
#pragma unroll
    for (int i = 0; i < 42; i++) { vals[i] = p[i*32 + lane]; m = fmaxf(m, vals[i]); }
#pragma unroll
    for (int off = 16; off > 0; off >>= 1) m = fmaxf(m, __shfl_xor_sync(0xffffffffu, m, off));
    float sum = 0.f;
#pragma unroll
    for (int i = 0; i < 42; i++) { vals[i] = __expf(vals[i] - m); sum += vals[i]; }
#pragma unroll
    for (int off = 16; off > 0; off >>= 1) sum += __shfl_xor_sync(0xffffffffu, sum, off);
    float invs = 1.0f / sum;
    __nv_bfloat16* ph = g_Ph + (size_t)row * STOT;
    __nv_bfloat16* pl = g_Pl + (size_t)row * STOT;
#pragma unroll
    for (int i = 0; i < 42; i++) {
        float v = vals[i] * invs;
        __nv_bfloat16 h = __float2bfloat16(v);
        ph[i*32 + lane] = h;
        pl[i*32 + lane] = __float2bfloat16(v - __bfloat162float(h));
    }
}

// ---------------- launch ----------------
extern "C" void kernel_launch(void* const* d_in, const int* in_sizes, int n_in,
                              void* d_out, int out_size)
{
    (void)in_sizes; (void)n_in; (void)out_size;
    const float* mask    = (const float*)d_in[0];
    const int*   pos_vlm = (const int*)  d_in[1];
    const int*   pos_act = (const int*)  d_in[2];
    const float* h_vlm   = (const float*)d_in[3];
    const float* h_act   = (const float*)d_in[4];
    const float* k_cache = (const float*)d_in[5];
    const float* v_cache = (const float*)d_in[6];
    // d_in[7] = Wq_vlm: unused (q_vlm rows are discarded by reference)
    const float* Wk_vlm  = (const float*)d_in[8];
    const float* Wv_vlm  = (const float*)d_in[9];
    const float* Wq_act  = (const float*)d_in[10];
    const float* Wk_act  = (const float*)d_in[11];
    const float* Wv_act  = (const float*)d_in[12];
    const float* Wo_act  = (const float*)d_in[13];
    float* out = (float*)d_out;

    void *p_hv_hi, *p_hv_lo, *p_ha_hi, *p_ha_lo, *p_at_hi, *p_at_lo;
    void *p_wkv_hi, *p_wkv_lo, *p_wvv_hi, *p_wvv_lo, *p_wq_hi, *p_wq_lo;
    void *p_wka_hi, *p_wka_lo, *p_wva_hi, *p_wva_lo, *p_wo_hi, *p_wo_lo, *p_attn;
    void *p_K, *p_q, *p_Kh, *p_Kl, *p_qh, *p_ql;
    cudaGetSymbolAddress(&p_hv_hi, g_hv_hi);   cudaGetSymbolAddress(&p_hv_lo, g_hv_lo);
    cudaGetSymbolAddress(&p_ha_hi, g_ha_hi);   cudaGetSymbolAddress(&p_ha_lo, g_ha_lo);
    cudaGetSymbolAddress(&p_at_hi, g_at_hi);   cudaGetSymbolAddress(&p_at_lo, g_at_lo);
    cudaGetSymbolAddress(&p_wkv_hi, g_wkv_hi); cudaGetSymbolAddress(&p_wkv_lo, g_wkv_lo);
    cudaGetSymbolAddress(&p_wvv_hi, g_wvv_hi); cudaGetSymbolAddress(&p_wvv_lo, g_wvv_lo);
    cudaGetSymbolAddress(&p_wq_hi, g_wq_hi);   cudaGetSymbolAddress(&p_wq_lo, g_wq_lo);
    cudaGetSymbolAddress(&p_wka_hi, g_wka_hi); cudaGetSymbolAddress(&p_wka_lo, g_wka_lo);
    cudaGetSymbolAddress(&p_wva_hi, g_wva_hi); cudaGetSymbolAddress(&p_wva_lo, g_wva_lo);
    cudaGetSymbolAddress(&p_wo_hi, g_wo_hi);   cudaGetSymbolAddress(&p_wo_lo, g_wo_lo);
    cudaGetSymbolAddress(&p_attn, g_attn);
    cudaGetSymbolAddress(&p_K, g_K);   cudaGetSymbolAddress(&p_q, g_q);
    cudaGetSymbolAddress(&p_Kh, g_Kh); cudaGetSymbolAddress(&p_Kl, g_Kl);
    cudaGetSymbolAddress(&p_qh, g_qh); cudaGetSymbolAddress(&p_ql, g_ql);

    cudaFuncSetAttribute(tc_gemm,    cudaFuncAttributeMaxDynamicSharedMemorySize, TCG_SMEM_BYTES);
    cudaFuncSetAttribute(score_hmma, cudaFuncAttributeMaxDynamicSharedMemorySize, 65536);
    cudaFuncSetAttribute(pv_hmma,    cudaFuncAttributeMaxDynamicSharedMemorySize, 98304);

    zero_kernel<<<1024, 256>>>(out);
    copy_cache_kernel<<<512, 256>>>(k_cache, v_cache);

    // conversions (projection operands)
    convA_kernel<<<(4096*2048/4 + 255)/256, 256>>>((const float4*)h_vlm,
        (__nv_bfloat162*)p_hv_hi, (__nv_bfloat162*)p_hv_lo, 4096*2048/4);
    convA_kernel<<<(256*2048/4 + 255)/256, 256>>>((const float4*)h_act,
        (__nv_bfloat162*)p_ha_hi, (__nv_bfloat162*)p_ha_lo, 256*2048/4);
    convWT_kernel<<<dim3(16, 64), dim3(32, 8)>>>(Wk_vlm, (__nv_bfloat16*)p_wkv_hi, (__nv_bfloat16*)p_wkv_lo, 2048, 512);
    convWT_kernel<<<dim3(16, 64), dim3(32, 8)>>>(Wv_vlm, (__nv_bfloat16*)p_wvv_hi, (__nv_bfloat16*)p_wvv_lo, 2048, 512);
    convWT_kernel<<<dim3(64, 64), dim3(32, 8)>>>(Wq_act, (__nv_bfloat16*)p_wq_hi,  (__nv_bfloat16*)p_wq_lo,  2048, 2048);
    convWT_kernel<<<dim3(16, 64), dim3(32, 8)>>>(Wk_act, (__nv_bfloat16*)p_wka_hi, (__nv_bfloat16*)p_wka_lo, 2048, 512);
    convWT_kernel<<<dim3(16, 64), dim3(32, 8)>>>(Wv_act, (__nv_bfloat16*)p_wva_hi, (__nv_bfloat16*)p_wva_lo, 2048, 512);
    convWT_kernel<<<dim3(64, 64), dim3(32, 8)>>>(Wo_act, (__nv_bfloat16*)p_wo_hi,  (__nv_bfloat16*)p_wo_lo,  2048, 2048);

    // projections on HMMA
    tc_gemm<<<dim3(4, 32, 1), 256, TCG_SMEM_BYTES>>>(
        (const __nv_bfloat16*)p_hv_hi, (const __nv_bfloat16*)p_hv_lo,
        (const __nv_bfloat16*)p_wkv_hi, (const __nv_bfloat16*)p_wkv_lo,
        nullptr, 4096, 512, 2048, 1, 0, 2048);
    tc_gemm<<<dim3(4, 32, 1), 256, TCG_SMEM_BYTES>>>(
        (const __nv_bfloat16*)p_hv_hi, (const __nv_bfloat16*)p_hv_lo,
        (const __nv_bfloat16*)p_wvv_hi, (const __nv_bfloat16*)p_wvv_lo,
        nullptr, 4096, 512, 2048, 1, 1, 2048);
    tc_gemm<<<dim3(16, 2, 4), 256, TCG_SMEM_BYTES>>>(
        (const __nv_bfloat16*)p_ha_hi, (const __nv_bfloat16*)p_ha_lo,
        (const __nv_bfloat16*)p_wq_hi, (const __nv_bfloat16*)p_wq_lo,
        nullptr, 256, 2048, 2048, 3, 2, 512);
    tc_gemm<<<dim3(4, 2, 16), 256, TCG_SMEM_BYTES>>>(
        (const __nv_bfloat16*)p_ha_hi, (const __nv_bfloat16*)p_ha_lo,
        (const __nv_bfloat16*)p_wka_hi, (const __nv_bfloat16*)p_wka_lo,
        nullptr, 256, 512, 2048, 2, 0, 128);
    tc_gemm<<<dim3(4, 2, 16), 256, TCG_SMEM_BYTES>>>(
        (const __nv_bfloat16*)p_ha_hi, (const __nv_bfloat16*)p_ha_lo,
        (const __nv_bfloat16*)p_wva_hi, (const __nv_bfloat16*)p_wva_lo,
        nullptr, 256, 512, 2048, 2, 1, 128);

    // RoPE
    {
        int tot = BB*NKV*SQV*64;
        rope_kernel<<<(tot + 255)/256, 256>>>(0, pos_vlm, NKV, SQV, SCACHE, tot);
    }
    {
        int tot = BB*NKV*SQA*64;
        rope_kernel<<<(tot + 255)/256, 256>>>(0, pos_act, NKV, SQA, SCACHE + SQV, tot);
    }
    {
        int tot = BB*NH*SQA*64;
        rope_kernel<<<(tot + 255)/256, 256>>>(1, pos_act, NH, SQA, 0, tot);
    }

    // attention operand conversions
    convA_kernel<<<(BB*NKV*STOT*HDIM/4 + 255)/256, 256>>>((const float4*)p_K,
        (__nv_bfloat162*)p_Kh, (__nv_bfloat162*)p_Kl, BB*NKV*STOT*HDIM/4);
    convA_kernel<<<(BB*NH*SQA*HDIM/4 + 255)/256, 256>>>((const float4*)p_q,
        (__nv_bfloat162*)p_qh, (__nv_bfloat162*)p_ql, BB*NH*SQA*HDIM/4);
    convVT_kernel<<<dim3(4, 42, 16), dim3(32, 8)>>>();

    // attention on HMMA
    score_hmma<<<dim3(21, 64), 256, 65536>>>(mask);
    softmax_kernel<<<1024, 128>>>();
    pv_hmma<<<dim3(64, 7), 256, 98304>>>();

    // output projection: convert attn, then HMMA GEMM
    convA_kernel<<<(256*2048/4 + 255)/256, 256>>>((const float4*)p_attn,
        (__nv_bfloat162*)p_at_hi, (__nv_bfloat162*)p_at_lo, 256*2048/4);
    tc_gemm<<<dim3(16, 2, 4), 256, TCG_SMEM_BYTES>>>(
        (const __nv_bfloat16*)p_at_hi, (const __nv_bfloat16*)p_at_lo,
        (const __nv_bfloat16*)p_wo_hi, (const __nv_bfloat16*)p_wo_lo,
        out, 256, 2048, 2048, 0, 3, 512);
}

// round 10
// speedup vs baseline: 2.9118x; 1.0452x over previous
#include <cuda_runtime.h>
#include <cuda_bf16.h>
#include <math.h>
#include <stdint.h>

// ---------------- problem constants ----------------
#define BB      4
#define NH      16
#define NKV     4
#define HDIM    128
#define DMODEL  2048
#define SQV     1024
#define SQA     64
#define SCACHE  256
#define STOT    1344
#define NQROWS  (BB*NH*SQA)

// ---------------- fp32 scratch ----------------
__device__ float g_K[BB*NKV*STOT*HDIM];
__device__ float g_V[BB*NKV*STOT*HDIM];
__device__ float g_q[BB*NH*SQA*HDIM];
__device__ float g_scores[NQROWS*STOT];
__device__ float g_attn[BB*SQA*NH*HDIM];

// ---------------- bf16 split operands (hi + lo) ----------------
__device__ __nv_bfloat16 g_hv_hi[4096*2048], g_hv_lo[4096*2048];
__device__ __nv_bfloat16 g_ha_hi[256*2048],  g_ha_lo[256*2048];
__device__ __nv_bfloat16 g_at_hi[256*2048],  g_at_lo[256*2048];
__device__ __nv_bfloat16 g_wkv_hi[512*2048], g_wkv_lo[512*2048];
__device__ __nv_bfloat16 g_wvv_hi[512*2048], g_wvv_lo[512*2048];
__device__ __nv_bfloat16 g_wq_hi[2048*2048], g_wq_lo[2048*2048];
__device__ __nv_bfloat16 g_wka_hi[512*2048], g_wka_lo[512*2048];
__device__ __nv_bfloat16 g_wva_hi[512*2048], g_wva_lo[512*2048];
__device__ __nv_bfloat16 g_wo_hi[2048*2048], g_wo_lo[2048*2048];

// attention bf16 operands
__device__ __nv_bfloat16 g_qh[BB*NH*SQA*HDIM],  g_ql[BB*NH*SQA*HDIM];
__device__ __nv_bfloat16 g_Kh[BB*NKV*STOT*HDIM], g_Kl[BB*NKV*STOT*HDIM];
__device__ __nv_bfloat16 g_Vth[BB*NKV*HDIM*STOT], g_Vtl[BB*NKV*HDIM*STOT];
__device__ __nv_bfloat16 g_Ph[NQROWS*STOT], g_Pl[NQROWS*STOT];

// ================= PTX helpers (sm_80-baseline only: no tcgen05) =================
__device__ __forceinline__ uint32_t smem_to_u32(const void* p) {
    uint32_t a;
    asm("{ .reg .u64 t; cvta.to.shared.u64 t, %1; cvt.u32.u64 %0, t; }" : "=r"(a) : "l"(p));
    return a;
}
#define CP_ASYNC16(sm, gm) \
    asm volatile("cp.async.cg.shared.global [%0], [%1], 16;" :: "r"(sm), "l"(gm))
#define CP_COMMIT() asm volatile("cp.async.commit_group;" ::: "memory")
#define CP_WAIT(n)  asm volatile("cp.async.wait_group %0;" :: "n"(n) : "memory")

__device__ __forceinline__ void ldsm_x4(uint32_t* r, uint32_t addr) {
    asm volatile("ldmatrix.sync.aligned.m8n8.x4.shared.b16 {%0,%1,%2,%3}, [%4];"
        : "=r"(r[0]), "=r"(r[1]), "=r"(r[2]), "=r"(r[3]) : "r"(addr));
}
__device__ __forceinline__ void mma_bf16(float* d, const uint32_t* a, const uint32_t* b) {
    asm volatile("mma.sync.aligned.m16n8k16.row.col.f32.bf16.bf16.f32 "
        "{%0,%1,%2,%3}, {%4,%5,%6,%7}, {%8,%9}, {%0,%1,%2,%3};"
        : "+f"(d[0]), "+f"(d[1]), "+f"(d[2]), "+f"(d[3])
        : "r"(a[0]), "r"(a[1]), "r"(a[2]), "r"(a[3]), "r"(b[0]), "r"(b[1]));
}
__device__ __forceinline__ uint32_t swz(uint32_t off) { return off ^ ((off >> 3) & 0x70); }

// ---------------- output index mapping ----------------
__device__ __forceinline__ int out_index(int map, int r, int c, int N) {
    switch (map) {
        case 1: { int b=r>>10, s=r&1023, kv=c>>7, d=c&127;
                  return (((b*NKV+kv)*STOT) + SCACHE + s)*HDIM + d; }
        case 2: { int b=r>>6, s=r&63, kv=c>>7, d=c&127;
                  return (((b*NKV+kv)*STOT) + (SCACHE+SQV) + s)*HDIM + d; }
        case 3: { int b=r>>6, s=r&63, h=c>>7, d=c&127;
                  return (((b*NH+h)*SQA) + s)*HDIM + d; }
        default: return r*N + c;
    }
}

// ---------------- HMMA bf16-split GEMM with up to 3 fused N-ranges ----------------
// C = A @ B^T. A: [M][K] hi/lo. Each range i: Bi [Ni][K] hi/lo + (map,dest).
// Block's n0 selects range. CTA tile 128x128, K-chunk 64, double-buffered cp.async.
#define TCG_SMEM_BYTES (131072)
__global__ void __launch_bounds__(256) tc_gemm_multi(
    const __nv_bfloat16* __restrict__ Ahi, const __nv_bfloat16* __restrict__ Alo,
    const __nv_bfloat16* B0h, const __nv_bfloat16* B0l, int N0, int map0, int dest0,
    const __nv_bfloat16* B1h, const __nv_bfloat16* B1l, int N1, int map1, int dest1,
    const __nv_bfloat16* B2h, const __nv_bfloat16* B2l, int N2, int map2, int dest2,
    float* Cext, int M, int K, int klen)
{
    extern __shared__ char smem[];
    uint32_t sbase = smem_to_u32(smem);

    const int tid = threadIdx.x, lane = tid & 31, wid = tid >> 5;
    const int wm = wid & 1, wn = wid >> 1;
    const int m0 = blockIdx.y * 128;
    const int n0g = blockIdx.x * 128;
    const int kstart = blockIdx.z * klen;
    const int nch = klen >> 6;

    // range selection
    const __nv_bfloat16 *Bh, *Bl;
    int nbase, map, dest, Nl;
    if (n0g < N0)            { Bh = B0h; Bl = B0l; nbase = 0;        map = map0; dest = dest0; Nl = N0; }
    else if (n0g < N0 + N1)  { Bh = B1h; Bl = B1l; nbase = N0;       map = map1; dest = dest1; Nl = N1; }
    else                     { Bh = B2h; Bl = B2l; nbase = N0 + N1;  map = map2; dest = dest2; Nl = N2; }
    const int n0 = n0g - nbase;

    auto load_stage = [&](int stage, int kof) {
        uint32_t stbase = sbase + stage * 65536;
#pragma unroll
        for (int t = 0; t < 4; ++t) {
            const __nv_bfloat16* src = (t == 0) ? Ahi : (t == 1) ? Alo : (t == 2) ? Bh : Bl;
            int row0 = (t < 2) ? m0 : n0;
#pragma unroll
            for (int it = 0; it < 4; ++it) {
                int idx = tid + it * 256;
                int r = idx >> 3, ch = idx & 7;
                uint32_t so = stbase + t * 16384 + swz((uint32_t)(r * 128 + ch * 16));
                const __nv_bfloat16* gp = src + (size_t)(row0 + r) * K + kof + ch * 8;
                CP_ASYNC16(so, gp);
            }
        }
    };

    float acc[4][4][4];
#pragma unroll
    for (int i = 0; i < 4; ++i)
#pragma unroll
        for (int j = 0; j < 4; ++j)
#pragma unroll
            for (int k = 0; k < 4; ++k) acc[i][j][k] = 0.f;

    load_stage(0, kstart);
    CP_COMMIT();

    const uint32_t aRow = wm * 64 + (lane & 15);
    const uint32_t aKof = (lane >> 4) * 8;
    const uint32_t bRow = wn * 32 + ((lane >> 4) * 8) + (lane & 7);
    const uint32_t bKof = ((lane >> 3) & 1) * 8;

    for (int c = 0; c < nch; ++c) {
        if (c + 1 < nch) { load_stage((c + 1) & 1, kstart + (c + 1) * 64); CP_COMMIT(); CP_WAIT(1); }
        else             { CP_WAIT(0); }
        __syncthreads();

        uint32_t st = sbase + (c & 1) * 65536;
        uint32_t tAhi = st, tAlo = st + 16384, tBhi = st + 32768, tBlo = st + 49152;

#pragma unroll
        for (int ks = 0; ks < 4; ++ks) {
            uint32_t ahi[4][4], alo[4][4];
#pragma unroll
            for (int mt = 0; mt < 4; ++mt) {
                uint32_t off = swz((aRow + mt * 16) * 128 + (ks * 16 + aKof) * 2);
                ldsm_x4(ahi[mt], tAhi + off);
                ldsm_x4(alo[mt], tAlo + off);
            }
            uint32_t bhi[2][4], blo[2][4];
#pragma unroll
            for (int g = 0; g < 2; ++g) {
                uint32_t off = swz((bRow + g * 16) * 128 + (ks * 16 + bKof) * 2);
                ldsm_x4(bhi[g], tBhi + off);
                ldsm_x4(blo[g], tBlo + off);
            }
#pragma unroll
            for (int mt = 0; mt < 4; ++mt)
#pragma unroll
                for (int nt = 0; nt < 4; ++nt) {
                    const uint32_t* bh = &bhi[nt >> 1][(nt & 1) * 2];
                    const uint32_t* bl = &blo[nt >> 1][(nt & 1) * 2];
                    mma_bf16(acc[mt][nt], ahi[mt], bh);
                    mma_bf16(acc[mt][nt], ahi[mt], bl);
                    mma_bf16(acc[mt][nt], alo[mt], bh);
                }
        }
        __syncthreads();
    }

    float* C = (dest == 0) ? g_K : (dest == 1) ? g_V : (dest == 2) ? g_q : Cext;
    bool split = (gridDim.z > 1);
#pragma unroll
    for (int mt = 0; mt < 4; ++mt)
#pragma unroll
        for (int nt = 0; nt < 4; ++nt) {
            int mrow = m0 + wm * 64 + mt * 16 + (lane >> 2);
            int ncol = n0 + wn * 32 + nt * 8 + 2 * (lane & 3);
#pragma unroll
            for (int e = 0; e < 4; ++e) {
                int r = mrow + (e >> 1) * 8;
                int cc = ncol + (e & 1);
                int idx = out_index(map, r, cc, Nl);
                if (split) atomicAdd(&C[idx], acc[mt][nt][e]);
                else       C[idx] = acc[mt][nt][e];
            }
        }
}

// ---------------- HMMA attention scores (validated) ----------------
__global__ void __launch_bounds__(256) score_hmma(const float* __restrict__ mask)
{
    extern __shared__ char smem[];
    uint32_t sbase = smem_to_u32(smem);

    const int tid = threadIdx.x, lane = tid & 31, wid = tid >> 5;
    const int wm = wid & 1, wn = wid >> 1;
    int bh = blockIdx.y;
    int b = bh >> 4, h = bh & 15, kv = h >> 2;
    int s0 = blockIdx.x * 64;
    (void)h;

#pragma unroll
    for (int it = 0; it < 2; ++it) {
        int idx = tid + it * 256;
        int r = idx >> 3, ch = idx & 7;
        uint32_t so = swz((uint32_t)(r * 128 + ch * 16));
        size_t qoff = (size_t)(bh * 64 + r) * HDIM;
        size_t koff = (size_t)((b * NKV + kv) * STOT + s0 + r) * HDIM;
#pragma unroll
        for (int c = 0; c < 2; ++c) {
            CP_ASYNC16(sbase + (0 + c) * 8192 + so, g_qh + qoff + c * 64 + ch * 8);
            CP_ASYNC16(sbase + (2 + c) * 8192 + so, g_ql + qoff + c * 64 + ch * 8);
            CP_ASYNC16(sbase + (4 + c) * 8192 + so, g_Kh + koff + c * 64 + ch * 8);
            CP_ASYNC16(sbase + (6 + c) * 8192 + so, g_Kl + koff + c * 64 + ch * 8);
        }
    }
    CP_COMMIT();
    CP_WAIT(0);
    __syncthreads();

    float acc[2][2][4];
#pragma unroll
    for (int i = 0; i < 2; ++i)
#pragma unroll
        for (int j = 0; j < 2; ++j)
#pragma unroll
            for (int k = 0; k < 4; ++k) acc[i][j][k] = 0.f;

    const uint32_t aRow = wm * 32 + (lane & 15);
    const uint32_t aKof = (lane >> 4) * 8;
    const uint32_t bRow = wn * 16 + ((lane >> 4) * 8) + (lane & 7);
    const uint32_t bKof = ((lane >> 3) & 1) * 8;

#pragma unroll
    for (int c = 0; c < 2; ++c) {
        uint32_t tqh = sbase + (0 + c) * 8192, tql = sbase + (2 + c) * 8192;
        uint32_t tkh = sbase + (4 + c) * 8192, tkl = sbase + (6 + c) * 8192;
#pragma unroll
        for (int ks = 0; ks < 4; ++ks) {
            uint32_t ahi[2][4], alo[2][4];
#pragma unroll
            for (int mt = 0; mt < 2; ++mt) {
                uint32_t off = swz((aRow + mt * 16) * 128 + (ks * 16 + aKof) * 2);
                ldsm_x4(ahi[mt], tqh + off);
                ldsm_x4(alo[mt], tql + off);
            }
            uint32_t bh4[4], bl4[4];
            {
                uint32_t off = swz(bRow * 128 + (ks * 16 + bKof) * 2);
                ldsm_x4(bh4, tkh + off);
                ldsm_x4(bl4, tkl + off);
            }
#pragma unroll
            for (int mt = 0; mt < 2; ++mt)
#pragma unroll
                for (int nt = 0; nt < 2; ++nt) {
                    mma_bf16(acc[mt][nt], ahi[mt], &bh4[nt * 2]);
                    mma_bf16(acc[mt][nt], ahi[mt], &bl4[nt * 2]);
                    mma_bf16(acc[mt][nt], alo[mt], &bh4[nt * 2]);
                }
        }
    }

    const float scale = 0.08838834764831845f;
#pragma unroll
    for (int mt = 0; mt < 2; ++mt)
#pragma unroll
        for (int nt = 0; nt < 2; ++nt)
#pragma unroll
            for (int e = 0; e < 4; ++e) {
                int q = wm * 32 + mt * 16 + (lane >> 2) + (e >> 1) * 8;
                int s = s0 + wn * 16 + nt * 8 + 2 * (lane & 3) + (e & 1);
                float v = acc[mt][nt][e] * scale;
                v = tanhf(v * 0.02f) * 50.0f
                  + mask[(size_t)b * (1088 * 1344) + (size_t)(1024 + q) * 1344 + s];
                g_scores[(size_t)(bh * 64 + q) * STOT + s] = v;
            }
}

// ---------------- HMMA P @ V (validated) ----------------
__global__ void __launch_bounds__(256) pv_hmma()
{
    extern __shared__ char smem[];
    uint32_t sbase = smem_to_u32(smem);

    const int tid = threadIdx.x, lane = tid & 31, wid = tid >> 5;
    const int wm = wid & 1, wn = wid >> 1;
    int bh = blockIdx.x;
    int b = bh >> 4, h = bh & 15, kv = h >> 2;
    int kc0 = blockIdx.y * 192;

    size_t prow0 = (size_t)bh * 64;
    size_t vrow0 = (size_t)(b * NKV + kv) * HDIM;

    auto load_sub = [&](int stage, int kc) {
        uint32_t stb = sbase + stage * 49152;
#pragma unroll
        for (int it = 0; it < 2; ++it) {
            int idx = tid + it * 256;
            int r = idx >> 3, ch = idx & 7;
            uint32_t so = swz((uint32_t)(r * 128 + ch * 16));
            CP_ASYNC16(stb + so,        g_Ph + (prow0 + r) * STOT + kc + ch * 8);
            CP_ASYNC16(stb + 8192 + so, g_Pl + (prow0 + r) * STOT + kc + ch * 8);
        }
#pragma unroll
        for (int it = 0; it < 4; ++it) {
            int idx = tid + it * 256;
            int r = idx >> 3, ch = idx & 7;
            uint32_t so = swz((uint32_t)(r * 128 + ch * 16));
            CP_ASYNC16(stb + 16384 + so, g_Vth + (vrow0 + r) * STOT + kc + ch * 8);
            CP_ASYNC16(stb + 32768 + so, g_Vtl + (vrow0 + r) * STOT + kc + ch * 8);
        }
    };

    float acc[2][4][4];
#pragma unroll
    for (int i = 0; i < 2; ++i)
#pragma unroll
        for (int j = 0; j < 4; ++j)
#pragma unroll
            for (int k = 0; k < 4; ++k) acc[i][j][k] = 0.f;

    load_sub(0, kc0);
    CP_COMMIT();

    const uint32_t aRow = wm * 32 + (lane & 15);
    const uint32_t aKof = (lane >> 4) * 8;
    const uint32_t bRow = wn * 32 + ((lane >> 4) * 8) + (lane & 7);
    const uint32_t bKof = ((lane >> 3) & 1) * 8;

    for (int sub = 0; sub < 3; ++sub) {
        if (sub + 1 < 3) { load_sub((sub + 1) & 1, kc0 + (sub + 1) * 64); CP_COMMIT(); CP_WAIT(1); }
        else             { CP_WAIT(0); }
        __syncthreads();

        uint32_t st = sbase + (sub & 1) * 49152;
        uint32_t tph = st, tpl = st + 8192, tvh = st + 16384, tvl = st + 32768;

#pragma unroll
        for (int ks = 0; ks < 4; ++ks) {
            uint32_t ahi[2][4], alo[2][4];
#pragma unroll
            for (int mt = 0; mt < 2; ++mt) {
                uint32_t off = swz((aRow + mt * 16) * 128 + (ks * 16 + aKof) * 2);
                ldsm_x4(ahi[mt], tph + off);
                ldsm_x4(alo[mt], tpl + off);
            }
            uint32_t bhi[2][4], blo[2][4];
#pragma unroll
            for (int g = 0; g < 2; ++g) {
                uint32_t off = swz((bRow + g * 16) * 128 + (ks * 16 + bKof) * 2);
                ldsm_x4(bhi[g], tvh + off);
                ldsm_x4(blo[g], tvl + off);
            }
#pragma unroll
            for (int mt = 0; mt < 2; ++mt)
#pragma unroll
                for (int nt = 0; nt < 4; ++nt) {
                    const uint32_t* bh4 = &bhi[nt >> 1][(nt & 1) * 2];
                    const uint32_t* bl4 = &blo[nt >> 1][(nt & 1) * 2];
                    mma_bf16(acc[mt][nt], ahi[mt], bh4);
                    mma_bf16(acc[mt][nt], ahi[mt], bl4);
                    mma_bf16(acc[mt][nt], alo[mt], bh4);
                }
        }
        __syncthreads();
    }

#pragma unroll
    for (int mt = 0; mt < 2; ++mt)
#pragma unroll
        for (int nt = 0; nt < 4; ++nt)
#pragma unroll
            for (int e = 0; e < 4; ++e) {
                int q = wm * 32 + mt * 16 + (lane >> 2) + (e >> 1) * 8;
                int d = wn * 32 + nt * 8 + 2 * (lane & 3) + (e & 1);
                atomicAdd(&g_attn[(size_t)(b * SQA + q) * (NH * HDIM) + h * HDIM + d],
                          acc[mt][nt][e]);
            }
}

// ---------------- batched 2-tensor fp32 -> bf16 hi/lo conversion ----------------
__global__ void convA2_kernel(
    const float4* __restrict__ x0, __nv_bfloat162* hi0, __nv_bfloat162* lo0, int n40,
    const float4* __restrict__ x1, __nv_bfloat162* hi1, __nv_bfloat162* lo1, int n41)
{
    int i = blockIdx.x*blockDim.x + threadIdx.x;
    const float4* x; __nv_bfloat162 *hi, *lo;
    if (i < n40) { x = x0; hi = hi0; lo = lo0; }
    else if (i < n40 + n41) { i -= n40; x = x1; hi = hi1; lo = lo1; }
    else return;
    float4 v = x[i];
    __nv_bfloat16 h0 = __float2bfloat16(v.x), h1 = __float2bfloat16(v.y);
    __nv_bfloat16 h2 = __float2bfloat16(v.z), h3 = __float2bfloat16(v.w);
    __nv_bfloat16 l0 = __float2bfloat16(v.x - __bfloat162float(h0));
    __nv_bfloat16 l1 = __float2bfloat16(v.y - __bfloat162float(h1));
    __nv_bfloat16 l2 = __float2bfloat16(v.z - __bfloat162float(h2));
    __nv_bfloat16 l3 = __float2bfloat16(v.w - __bfloat162float(h3));
    hi[i*2+0] = __halves2bfloat162(h0, h1);
    hi[i*2+1] = __halves2bfloat162(h2, h3);
    lo[i*2+0] = __halves2bfloat162(l0, l1);
    lo[i*2+1] = __halves2bfloat162(l2, l3);
}

// ---------------- batched weight transpose+convert: all 6 weights ----------------
// block ranges (each block does a 32x32 tile): computed on host side layout below.
__device__ __forceinline__ void wt_tile(const float* __restrict__ W,
                                        __nv_bfloat16* bhi, __nv_bfloat16* blo,
                                        int Nd, int k0, int n0, int tx, int ty,
                                        float t[32][33])
{
#pragma unroll
    for (int i = 0; i < 4; ++i)
        t[ty + i*8][tx] = W[(size_t)(k0 + ty + i*8)*Nd + n0 + tx];
    __syncthreads();
#pragma unroll
    for (int i = 0; i < 4; ++i) {
        int n = ty + i*8;
        float v = t[tx][n];
        __nv_bfloat16 h = __float2bfloat16(v);
        __nv_bfloat16 l = __float2bfloat16(v - __bfloat162float(h));
        size_t o = (size_t)(n0 + n)*2048 + k0 + tx;   // Kd = 2048 always
        bhi[o] = h; blo[o] = l;
    }
}

__global__ void convWT_all(
    const float* Wkv, const float* Wvv, const float* Wq,
    const float* Wka, const float* Wva, const float* Wo,
    __nv_bfloat16* kv_h, __nv_bfloat16* kv_l, __nv_bfloat16* vv_h, __nv_bfloat16* vv_l,
    __nv_bfloat16* q_h,  __nv_bfloat16* q_l,  __nv_bfloat16* ka_h, __nv_bfloat16* ka_l,
    __nv_bfloat16* va_h, __nv_bfloat16* va_l, __nv_bfloat16* o_h,  __nv_bfloat16* o_l)
{
    __shared__ float t[32][33];
    int bx = blockIdx.x;
    int tx = threadIdx.x, ty = threadIdx.y;
    // ranges: wkv [0,1024) wvv [1024,2048) wq [2048,6144) wka [6144,7168)
    //         wva [7168,8192) wo [8192,12288)
    if (bx < 1024)       { int l = bx;        wt_tile(Wkv, kv_h, kv_l,  512, (l>>4)*32, (l&15)*32, tx, ty, t); }
    else if (bx < 2048)  { int l = bx - 1024; wt_tile(Wvv, vv_h, vv_l,  512, (l>>4)*32, (l&15)*32, tx, ty, t); }
    else if (bx < 6144)  { int l = bx - 2048; wt_tile(Wq,  q_h,  q_l,  2048, (l>>6)*32, (l&63)*32, tx, ty, t); }
    else if (bx < 7168)  { int l = bx - 6144; wt_tile(Wka, ka_h, ka_l,  512, (l>>4)*32, (l&15)*32, tx, ty, t); }
    else if (bx < 8192)  { int l = bx - 7168; wt_tile(Wva, va_h, va_l,  512, (l>>4)*32, (l&15)*32, tx, ty, t); }
    else                 { int l = bx - 8192; wt_tile(Wo,  o_h,  o_l,  2048, (l>>6)*32, (l&63)*32, tx, ty, t); }
}

// V [bk][s][d] -> V^T [bk][d][s] bf16 hi/lo
__global__ void convVT_kernel()
{
    __shared__ float t[32][33];
    int z  = blockIdx.z;
    int s0 = blockIdx.y*32;
    int d0 = blockIdx.x*32;
    int tx = threadIdx.x, ty = threadIdx.y;
    const float* V = g_V + (size_t)z*STOT*HDIM;
#pragma unroll
    for (int i = 0; i < 4; ++i)
        t[ty + i*8][tx] = V[(size_t)(s0 + ty + i*8)*HDIM + d0 + tx];
    __syncthreads();
#pragma unroll
    for (int i = 0; i < 4; ++i) {
        int d = ty + i*8;
        float v = t[tx][d];
        __nv_bfloat16 h = __float2bfloat16(v);
        __nv_bfloat16 l = __float2bfloat16(v - __bfloat162float(h));
        size_t o = (size_t)z*HDIM*STOT + (size_t)(d0 + d)*STOT + s0 + tx;
        g_Vth[o] = h; g_Vtl[o] = l;
    }
}

// ---------------- zero-init + cache copy (merged) ----------------
__global__ void zero_copy_kernel(float* out, const float* __restrict__ kc,
                                 const float* __restrict__ vc)
{
    int tid = blockIdx.x*blockDim.x + threadIdx.x;
    int stride = gridDim.x*blockDim.x;
    const int nq = BB*NH*SQA*HDIM;
    const int na = BB*SQA*NH*HDIM;
    const int no = BB*SQA*DMODEL;
    const int nact = BB*NKV*SQA*HDIM;
    const int ncache = BB*NKV*SCACHE*HDIM;
    for (int i = tid; i < nq; i += stride) g_q[i] = 0.f;
    for (int i = tid; i < na; i += stride) g_attn[i] = 0.f;
    for (int i = tid; i < no; i += stride) out[i] = 0.f;
    for (int i = tid; i < nact; i += stride) {
        int d  = i & 127;
        int s  = (i >> 7) & 63;
        int bk = i >> 13;
        int idx = (bk*STOT + (SCACHE + SQV) + s)*HDIM + d;
        g_K[idx] = 0.f;
        g_V[idx] = 0.f;
    }
    for (int i = tid; i < ncache; i += stride) {
        int d  = i & 127;
        int s  = (i >> 7) & 255;
        int bk = i >> 15;
        int dst = (bk*STOT + s)*HDIM + d;
        g_K[dst] = kc[i];
        g_V[dst] = vc[i];
    }
}

// ---------------- fused RoPE: all 3 segments in one launch ----------------
#define ROPE_T0 (BB*NKV*SQV*64)     // 1048576: k_vlm
#define ROPE_T1 (BB*NKV*SQA*64)     // 65536:   k_act
#define ROPE_T2 (BB*NH*SQA*64)      // 262144:  q_act
__global__ void rope_all(const int* __restrict__ pos_vlm, const int* __restrict__ pos_act)
{
    int idx = blockIdx.x*blockDim.x + threadIdx.x;
    int which, nh, seqlen, s_off;
    const int* pos;
    if (idx < ROPE_T0) { which = 0; pos = pos_vlm; nh = NKV; seqlen = SQV; s_off = SCACHE; }
    else if (idx < ROPE_T0 + ROPE_T1) {
        idx -= ROPE_T0; which = 0; pos = pos_act; nh = NKV; seqlen = SQA; s_off = SCACHE + SQV;
    }
    else if (idx < ROPE_T0 + ROPE_T1 + ROPE_T2) {
        idx -= ROPE_T0 + ROPE_T1; which = 1; pos = pos_act; nh = NH; seqlen = SQA; s_off = 0;
    }
    else return;

    int i = idx & 63;
    int rest = idx >> 6;
    int s = rest % seqlen; rest /= seqlen;
    int hh = rest % nh;
    int b  = rest / nh;

    float* X = (which == 0) ? g_K : g_q;
    int stot = (which == 0) ? STOT : SQA;

    int p = pos[b*seqlen + s];
    float inv = exp2f(-0.20762050593046868f * (float)i);
    float ang = (float)p * inv;
    double ad  = (double)ang;
    double red = ad - rint(ad * 0.15915494309189535) * 6.283185307179586;
    float c  = cosf((float)red);
    float sn = sinf((float)red);

    size_t base = ((size_t)((b*nh + hh)*stot + s_off + s)) * HDIM;
    float x1 = X[base + i], x2 = X[base + 64 + i];
    X[base + i]      = x1*c - x2*sn;
    X[base + 64 + i] = x2*c + x1*sn;
}

// ---------------- row softmax -> P bf16 hi/lo ----------------
__global__ void softmax_kernel()
{
    int row  = blockIdx.x*4 + (threadIdx.x >> 5);
    int lane = threadIdx.x & 31;
    const float* p = g_scores + (size_t)row * STOT;

    float vals[42];
    float m = -1e30f;
#pragma unroll
    for (int i = 0; i < 42; i++) { vals[i] = p[i*32 + lane]; m = fmaxf(m, vals[i]); }
#pragma unroll
    for (int off = 16; off > 0; off >>= 1) m = fmaxf(m, __shfl_xor_sync(0xffffffffu, m, off));
    float sum = 0.f;
#pragma unroll
    for (int i = 0; i < 42; i++) { vals[i] = __expf(vals[i] - m); sum += vals[i]; }
#pragma unroll
    for (int off = 16; off > 0; off >>= 1) sum += __shfl_xor_sync(0xffffffffu, sum, off);
    float invs = 1.0f / sum;
    __nv_bfloat16* ph = g_Ph + (size_t)row * STOT;
    __nv_bfloat16* pl = g_Pl + (size_t)row * STOT;
#pragma unroll
    for (int i = 0; i < 42; i++) {
        float v = vals[i] * invs;
        __nv_bfloat16 h = __float2bfloat16(v);
        ph[i*32 + lane] = h;
        pl[i*32 + lane] = __float2bfloat16(v - __bfloat162float(h));
    }
}

// ---------------- launch ----------------
extern "C" void kernel_launch(void* const* d_in, const int* in_sizes, int n_in,
                              void* d_out, int out_size)
{
    (void)in_sizes; (void)n_in; (void)out_size;
    const float* mask    = (const float*)d_in[0];
    const int*   pos_vlm = (const int*)  d_in[1];
    const int*   pos_act = (const int*)  d_in[2];
    const float* h_vlm   = (const float*)d_in[3];
    const float* h_act   = (const float*)d_in[4];
    const float* k_cache = (const float*)d_in[5];
    const float* v_cache = (const float*)d_in[6];
    // d_in[7] = Wq_vlm: unused (q_vlm rows are discarded by reference)
    const float* Wk_vlm  = (const float*)d_in[8];
    const float* Wv_vlm  = (const float*)d_in[9];
    const float* Wq_act  = (const float*)d_in[10];
    const float* Wk_act  = (const float*)d_in[11];
    const float* Wv_act  = (const float*)d_in[12];
    const float* Wo_act  = (const float*)d_in[13];
    float* out = (float*)d_out;

    void *p_hv_hi, *p_hv_lo, *p_ha_hi, *p_ha_lo, *p_at_hi, *p_at_lo;
    void *p_wkv_hi, *p_wkv_lo, *p_wvv_hi, *p_wvv_lo, *p_wq_hi, *p_wq_lo;
    void *p_wka_hi, *p_wka_lo, *p_wva_hi, *p_wva_lo, *p_wo_hi, *p_wo_lo, *p_attn;
    void *p_K, *p_q, *p_Kh, *p_Kl, *p_qh, *p_ql;
    cudaGetSymbolAddress(&p_hv_hi, g_hv_hi);   cudaGetSymbolAddress(&p_hv_lo, g_hv_lo);
    cudaGetSymbolAddress(&p_ha_hi, g_ha_hi);   cudaGetSymbolAddress(&p_ha_lo, g_ha_lo);
    cudaGetSymbolAddress(&p_at_hi, g_at_hi);   cudaGetSymbolAddress(&p_at_lo, g_at_lo);
    cudaGetSymbolAddress(&p_wkv_hi, g_wkv_hi); cudaGetSymbolAddress(&p_wkv_lo, g_wkv_lo);
    cudaGetSymbolAddress(&p_wvv_hi, g_wvv_hi); cudaGetSymbolAddress(&p_wvv_lo, g_wvv_lo);
    cudaGetSymbolAddress(&p_wq_hi, g_wq_hi);   cudaGetSymbolAddress(&p_wq_lo, g_wq_lo);
    cudaGetSymbolAddress(&p_wka_hi, g_wka_hi); cudaGetSymbolAddress(&p_wka_lo, g_wka_lo);
    cudaGetSymbolAddress(&p_wva_hi, g_wva_hi); cudaGetSymbolAddress(&p_wva_lo, g_wva_lo);
    cudaGetSymbolAddress(&p_wo_hi, g_wo_hi);   cudaGetSymbolAddress(&p_wo_lo, g_wo_lo);
    cudaGetSymbolAddress(&p_attn, g_attn);
    cudaGetSymbolAddress(&p_K, g_K);   cudaGetSymbolAddress(&p_q, g_q);
    cudaGetSymbolAddress(&p_Kh, g_Kh); cudaGetSymbolAddress(&p_Kl, g_Kl);
    cudaGetSymbolAddress(&p_qh, g_qh); cudaGetSymbolAddress(&p_ql, g_ql);

    cudaFuncSetAttribute(tc_gemm_multi, cudaFuncAttributeMaxDynamicSharedMemorySize, TCG_SMEM_BYTES);
    cudaFuncSetAttribute(score_hmma,    cudaFuncAttributeMaxDynamicSharedMemorySize, 65536);
    cudaFuncSetAttribute(pv_hmma,       cudaFuncAttributeMaxDynamicSharedMemorySize, 98304);

    // 1. zero + cache copy
    zero_copy_kernel<<<1024, 256>>>(out, k_cache, v_cache);

    // 2. activations -> bf16 hi/lo (h_vlm + h_act batched)
    {
        int n40 = 4096*2048/4, n41 = 256*2048/4;
        convA2_kernel<<<(n40 + n41 + 255)/256, 256>>>(
            (const float4*)h_vlm, (__nv_bfloat162*)p_hv_hi, (__nv_bfloat162*)p_hv_lo, n40,
            (const float4*)h_act, (__nv_bfloat162*)p_ha_hi, (__nv_bfloat162*)p_ha_lo, n41);
    }

    // 3. all 6 weight transposes+conversions in one launch
    convWT_all<<<12288, dim3(32, 8)>>>(
        Wk_vlm, Wv_vlm, Wq_act, Wk_act, Wv_act, Wo_act,
        (__nv_bfloat16*)p_wkv_hi, (__nv_bfloat16*)p_wkv_lo,
        (__nv_bfloat16*)p_wvv_hi, (__nv_bfloat16*)p_wvv_lo,
        (__nv_bfloat16*)p_wq_hi,  (__nv_bfloat16*)p_wq_lo,
        (__nv_bfloat16*)p_wka_hi, (__nv_bfloat16*)p_wka_lo,
        (__nv_bfloat16*)p_wva_hi, (__nv_bfloat16*)p_wva_lo,
        (__nv_bfloat16*)p_wo_hi,  (__nv_bfloat16*)p_wo_lo);

    // 4. vlm K+V projections fused (N = 512+512), no split-K
    tc_gemm_multi<<<dim3(8, 32, 1), 256, TCG_SMEM_BYTES>>>(
        (const __nv_bfloat16*)p_hv_hi, (const __nv_bfloat16*)p_hv_lo,
        (const __nv_bfloat16*)p_wkv_hi, (const __nv_bfloat16*)p_wkv_lo, 512, 1, 0,
        (const __nv_bfloat16*)p_wvv_hi, (const __nv_bfloat16*)p_wvv_lo, 512, 1, 1,
        nullptr, nullptr, 0, 0, 0,
        nullptr, 4096, 2048, 2048);

    // 5. action Q+K+V projections fused (N = 2048+512+512), split-K 4
    tc_gemm_multi<<<dim3(24, 2, 4), 256, TCG_SMEM_BYTES>>>(
        (const __nv_bfloat16*)p_ha_hi, (const __nv_bfloat16*)p_ha_lo,
        (const __nv_bfloat16*)p_wq_hi,  (const __nv_bfloat16*)p_wq_lo,  2048, 3, 2,
        (const __nv_bfloat16*)p_wka_hi, (const __nv_bfloat16*)p_wka_lo,  512, 2, 0,
        (const __nv_bfloat16*)p_wva_hi, (const __nv_bfloat16*)p_wva_lo,  512, 2, 1,
        nullptr, 256, 2048, 512);

    // 6. RoPE (all segments)
    rope_all<<<(ROPE_T0 + ROPE_T1 + ROPE_T2 + 255)/256, 256>>>(pos_vlm, pos_act);

    // 7. K + q -> bf16 hi/lo (batched)
    {
        int n40 = BB*NKV*STOT*HDIM/4, n41 = BB*NH*SQA*HDIM/4;
        convA2_kernel<<<(n40 + n41 + 255)/256, 256>>>(
            (const float4*)p_K, (__nv_bfloat162*)p_Kh, (__nv_bfloat162*)p_Kl, n40,
            (const float4*)p_q, (__nv_bfloat162*)p_qh, (__nv_bfloat162*)p_ql, n41);
    }
    // 8. V transpose + convert
    convVT_kernel<<<dim3(4, 42, 16), dim3(32, 8)>>>();

    // 9-11. attention on HMMA
    score_hmma<<<dim3(21, 64), 256, 65536>>>(mask);
    softmax_kernel<<<1024, 128>>>();
    pv_hmma<<<dim3(64, 7), 256, 98304>>>();

    // 12. attn -> bf16 hi/lo
    convA2_kernel<<<(256*2048/4 + 255)/256, 256>>>(
        (const float4*)p_attn, (__nv_bfloat162*)p_at_hi, (__nv_bfloat162*)p_at_lo, 256*2048/4,
        nullptr, nullptr, nullptr, 0);

    // 13. output projection, split-K 4
    tc_gemm_multi<<<dim3(16, 2, 4), 256, TCG_SMEM_BYTES>>>(
        (const __nv_bfloat16*)p_at_hi, (const __nv_bfloat16*)p_at_lo,
        (const __nv_bfloat16*)p_wo_hi, (const __nv_bfloat16*)p_wo_lo, 2048, 0, 3,
        nullptr, nullptr, 0, 0, 0,
        nullptr, nullptr, 0, 0, 0,
        out, 256, 2048, 512);
}

// round 11
// speedup vs baseline: 3.1937x; 1.0968x over previous
#include <cuda_runtime.h>
#include <cuda_bf16.h>
#include <math.h>
#include <stdint.h>

// ---------------- problem constants ----------------
#define BB      4
#define NH      16
#define NKV     4
#define HDIM    128
#define DMODEL  2048
#define SQV     1024
#define SQA     64
#define SCACHE  256
#define STOT    1344
#define NQROWS  (BB*NH*SQA)

// ---------------- fp32 scratch ----------------
__device__ float g_K[BB*NKV*STOT*HDIM];
__device__ float g_V[BB*NKV*STOT*HDIM];
__device__ float g_q[BB*NH*SQA*HDIM];
__device__ float g_scores[NQROWS*STOT];
__device__ float g_attn[BB*SQA*NH*HDIM];

// ---------------- bf16 split operands (hi + lo) ----------------
__device__ __nv_bfloat16 g_hv_hi[4096*2048], g_hv_lo[4096*2048];
__device__ __nv_bfloat16 g_ha_hi[256*2048],  g_ha_lo[256*2048];
__device__ __nv_bfloat16 g_at_hi[256*2048],  g_at_lo[256*2048];
__device__ __nv_bfloat16 g_wkv_hi[512*2048], g_wkv_lo[512*2048];
__device__ __nv_bfloat16 g_wvv_hi[512*2048], g_wvv_lo[512*2048];
__device__ __nv_bfloat16 g_wq_hi[2048*2048], g_wq_lo[2048*2048];
__device__ __nv_bfloat16 g_wka_hi[512*2048], g_wka_lo[512*2048];
__device__ __nv_bfloat16 g_wva_hi[512*2048], g_wva_lo[512*2048];
__device__ __nv_bfloat16 g_wo_hi[2048*2048], g_wo_lo[2048*2048];

// attention bf16 operands
__device__ __nv_bfloat16 g_qh[BB*NH*SQA*HDIM],  g_ql[BB*NH*SQA*HDIM];
__device__ __nv_bfloat16 g_Kh[BB*NKV*STOT*HDIM], g_Kl[BB*NKV*STOT*HDIM];
__device__ __nv_bfloat16 g_Vth[BB*NKV*HDIM*STOT], g_Vtl[BB*NKV*HDIM*STOT];
__device__ __nv_bfloat16 g_Ph[NQROWS*STOT], g_Pl[NQROWS*STOT];

// ================= PTX helpers (sm_80-baseline only: no tcgen05) =================
__device__ __forceinline__ uint32_t smem_to_u32(const void* p) {
    uint32_t a;
    asm("{ .reg .u64 t; cvta.to.shared.u64 t, %1; cvt.u32.u64 %0, t; }" : "=r"(a) : "l"(p));
    return a;
}
#define CP_ASYNC16(sm, gm) \
    asm volatile("cp.async.cg.shared.global [%0], [%1], 16;" :: "r"(sm), "l"(gm))
#define CP_COMMIT() asm volatile("cp.async.commit_group;" ::: "memory")
#define CP_WAIT(n)  asm volatile("cp.async.wait_group %0;" :: "n"(n) : "memory")

__device__ __forceinline__ void ldsm_x4(uint32_t* r, uint32_t addr) {
    asm volatile("ldmatrix.sync.aligned.m8n8.x4.shared.b16 {%0,%1,%2,%3}, [%4];"
        : "=r"(r[0]), "=r"(r[1]), "=r"(r[2]), "=r"(r[3]) : "r"(addr));
}
__device__ __forceinline__ void mma_bf16(float* d, const uint32_t* a, const uint32_t* b) {
    asm volatile("mma.sync.aligned.m16n8k16.row.col.f32.bf16.bf16.f32 "
        "{%0,%1,%2,%3}, {%4,%5,%6,%7}, {%8,%9}, {%0,%1,%2,%3};"
        : "+f"(d[0]), "+f"(d[1]), "+f"(d[2]), "+f"(d[3])
        : "r"(a[0]), "r"(a[1]), "r"(a[2]), "r"(a[3]), "r"(b[0]), "r"(b[1]));
}
__device__ __forceinline__ uint32_t swz(uint32_t off) { return off ^ ((off >> 3) & 0x70); }

// ---------------- output index mapping ----------------
__device__ __forceinline__ int out_index(int map, int r, int c, int N) {
    switch (map) {
        case 1: { int b=r>>10, s=r&1023, kv=c>>7, d=c&127;
                  return (((b*NKV+kv)*STOT) + SCACHE + s)*HDIM + d; }
        case 2: { int b=r>>6, s=r&63, kv=c>>7, d=c&127;
                  return (((b*NKV+kv)*STOT) + (SCACHE+SQV) + s)*HDIM + d; }
        case 3: { int b=r>>6, s=r&63, h=c>>7, d=c&127;
                  return (((b*NH+h)*SQA) + s)*HDIM + d; }
        default: return r*N + c;
    }
}

// ---------------- HMMA bf16-split GEMM, 64x128 CTA tile, 2 CTAs/SM ----------------
// C = A @ B^T. A: [M][K] hi/lo. Up to 3 N-ranges (Bi, map, dest).
// smem/stage 48KB: Ahi@0(8K), Alo@8K, Bhi@16K(16K), Blo@32K. 2 stages = 96KB.
// Warp layout (validated in pv_hmma): 8 warps, wm=wid&1 (32 rows), wn=wid>>1 (32 cols).
#define TCG_SMEM_BYTES (98304)
__global__ void __launch_bounds__(256, 2) tc_gemm_multi(
    const __nv_bfloat16* __restrict__ Ahi, const __nv_bfloat16* __restrict__ Alo,
    const __nv_bfloat16* B0h, const __nv_bfloat16* B0l, int N0, int map0, int dest0,
    const __nv_bfloat16* B1h, const __nv_bfloat16* B1l, int N1, int map1, int dest1,
    const __nv_bfloat16* B2h, const __nv_bfloat16* B2l, int N2, int map2, int dest2,
    float* Cext, int M, int K, int klen)
{
    extern __shared__ char smem[];
    uint32_t sbase = smem_to_u32(smem);

    const int tid = threadIdx.x, lane = tid & 31, wid = tid >> 5;
    const int wm = wid & 1, wn = wid >> 1;
    const int m0 = blockIdx.y * 64;
    const int n0g = blockIdx.x * 128;
    const int kstart = blockIdx.z * klen;
    const int nch = klen >> 6;

    const __nv_bfloat16 *Bh, *Bl;
    int nbase, map, dest, Nl;
    if (n0g < N0)            { Bh = B0h; Bl = B0l; nbase = 0;        map = map0; dest = dest0; Nl = N0; }
    else if (n0g < N0 + N1)  { Bh = B1h; Bl = B1l; nbase = N0;       map = map1; dest = dest1; Nl = N1; }
    else                     { Bh = B2h; Bl = B2l; nbase = N0 + N1;  map = map2; dest = dest2; Nl = N2; }
    const int n0 = n0g - nbase;

    auto load_stage = [&](int stage, int kof) {
        uint32_t stb = sbase + stage * 49152;
        // A tiles: 64 rows x 128B
#pragma unroll
        for (int it = 0; it < 2; ++it) {
            int idx = tid + it * 256;            // 0..511
            int r = idx >> 3, ch = idx & 7;
            uint32_t so = swz((uint32_t)(r * 128 + ch * 16));
            const __nv_bfloat16* ga = Ahi + (size_t)(m0 + r) * K + kof + ch * 8;
            const __nv_bfloat16* gl = Alo + (size_t)(m0 + r) * K + kof + ch * 8;
            CP_ASYNC16(stb + so, ga);
            CP_ASYNC16(stb + 8192 + so, gl);
        }
        // B tiles: 128 rows x 128B
#pragma unroll
        for (int it = 0; it < 4; ++it) {
            int idx = tid + it * 256;            // 0..1023
            int r = idx >> 3, ch = idx & 7;
            uint32_t so = swz((uint32_t)(r * 128 + ch * 16));
            const __nv_bfloat16* gb = Bh + (size_t)(n0 + r) * K + kof + ch * 8;
            const __nv_bfloat16* gc = Bl + (size_t)(n0 + r) * K + kof + ch * 8;
            CP_ASYNC16(stb + 16384 + so, gb);
            CP_ASYNC16(stb + 32768 + so, gc);
        }
    };

    float acc[2][4][4];
#pragma unroll
    for (int i = 0; i < 2; ++i)
#pragma unroll
        for (int j = 0; j < 4; ++j)
#pragma unroll
            for (int k = 0; k < 4; ++k) acc[i][j][k] = 0.f;

    load_stage(0, kstart);
    CP_COMMIT();

    const uint32_t aRow = wm * 32 + (lane & 15);
    const uint32_t aKof = (lane >> 4) * 8;
    const uint32_t bRow = wn * 32 + ((lane >> 4) * 8) + (lane & 7);
    const uint32_t bKof = ((lane >> 3) & 1) * 8;

    for (int c = 0; c < nch; ++c) {
        if (c + 1 < nch) { load_stage((c + 1) & 1, kstart + (c + 1) * 64); CP_COMMIT(); CP_WAIT(1); }
        else             { CP_WAIT(0); }
        __syncthreads();

        uint32_t st = sbase + (c & 1) * 49152;
        uint32_t tAhi = st, tAlo = st + 8192, tBhi = st + 16384, tBlo = st + 32768;

#pragma unroll
        for (int ks = 0; ks < 4; ++ks) {
            uint32_t ahi[2][4], alo[2][4];
#pragma unroll
            for (int mt = 0; mt < 2; ++mt) {
                uint32_t off = swz((aRow + mt * 16) * 128 + (ks * 16 + aKof) * 2);
                ldsm_x4(ahi[mt], tAhi + off);
                ldsm_x4(alo[mt], tAlo + off);
            }
            uint32_t bhi[2][4], blo[2][4];
#pragma unroll
            for (int g = 0; g < 2; ++g) {
                uint32_t off = swz((bRow + g * 16) * 128 + (ks * 16 + bKof) * 2);
                ldsm_x4(bhi[g], tBhi + off);
                ldsm_x4(blo[g], tBlo + off);
            }
#pragma unroll
            for (int mt = 0; mt < 2; ++mt)
#pragma unroll
                for (int nt = 0; nt < 4; ++nt) {
                    const uint32_t* bh4 = &bhi[nt >> 1][(nt & 1) * 2];
                    const uint32_t* bl4 = &blo[nt >> 1][(nt & 1) * 2];
                    mma_bf16(acc[mt][nt], ahi[mt], bh4);
                    mma_bf16(acc[mt][nt], ahi[mt], bl4);
                    mma_bf16(acc[mt][nt], alo[mt], bh4);
                }
        }
        __syncthreads();
    }

    float* C = (dest == 0) ? g_K : (dest == 1) ? g_V : (dest == 2) ? g_q : Cext;
    bool split = (gridDim.z > 1);
#pragma unroll
    for (int mt = 0; mt < 2; ++mt)
#pragma unroll
        for (int nt = 0; nt < 4; ++nt)
#pragma unroll
            for (int e = 0; e < 4; ++e) {
                int r = m0 + wm * 32 + mt * 16 + (lane >> 2) + (e >> 1) * 8;
                int cc = n0 + wn * 32 + nt * 8 + 2 * (lane & 3) + (e & 1);
                int idx = out_index(map, r, cc, Nl);
                if (split) atomicAdd(&C[idx], acc[mt][nt][e]);
                else       C[idx] = acc[mt][nt][e];
            }
}

// ---------------- HMMA attention scores (validated) ----------------
__global__ void __launch_bounds__(256) score_hmma(const float* __restrict__ mask)
{
    extern __shared__ char smem[];
    uint32_t sbase = smem_to_u32(smem);

    const int tid = threadIdx.x, lane = tid & 31, wid = tid >> 5;
    const int wm = wid & 1, wn = wid >> 1;
    int bh = blockIdx.y;
    int b = bh >> 4, h = bh & 15, kv = h >> 2;
    int s0 = blockIdx.x * 64;
    (void)h;

#pragma unroll
    for (int it = 0; it < 2; ++it) {
        int idx = tid + it * 256;
        int r = idx >> 3, ch = idx & 7;
        uint32_t so = swz((uint32_t)(r * 128 + ch * 16));
        size_t qoff = (size_t)(bh * 64 + r) * HDIM;
        size_t koff = (size_t)((b * NKV + kv) * STOT + s0 + r) * HDIM;
#pragma unroll
        for (int c = 0; c < 2; ++c) {
            CP_ASYNC16(sbase + (0 + c) * 8192 + so, g_qh + qoff + c * 64 + ch * 8);
            CP_ASYNC16(sbase + (2 + c) * 8192 + so, g_ql + qoff + c * 64 + ch * 8);
            CP_ASYNC16(sbase + (4 + c) * 8192 + so, g_Kh + koff + c * 64 + ch * 8);
            CP_ASYNC16(sbase + (6 + c) * 8192 + so, g_Kl + koff + c * 64 + ch * 8);
        }
    }
    CP_COMMIT();
    CP_WAIT(0);
    __syncthreads();

    float acc[2][2][4];
#pragma unroll
    for (int i = 0; i < 2; ++i)
#pragma unroll
        for (int j = 0; j < 2; ++j)
#pragma unroll
            for (int k = 0; k < 4; ++k) acc[i][j][k] = 0.f;

    const uint32_t aRow = wm * 32 + (lane & 15);
    const uint32_t aKof = (lane >> 4) * 8;
    const uint32_t bRow = wn * 16 + ((lane >> 4) * 8) + (lane & 7);
    const uint32_t bKof = ((lane >> 3) & 1) * 8;

#pragma unroll
    for (int c = 0; c < 2; ++c) {
        uint32_t tqh = sbase + (0 + c) * 8192, tql = sbase + (2 + c) * 8192;
        uint32_t tkh = sbase + (4 + c) * 8192, tkl = sbase + (6 + c) * 8192;
#pragma unroll
        for (int ks = 0; ks < 4; ++ks) {
            uint32_t ahi[2][4], alo[2][4];
#pragma unroll
            for (int mt = 0; mt < 2; ++mt) {
                uint32_t off = swz((aRow + mt * 16) * 128 + (ks * 16 + aKof) * 2);
                ldsm_x4(ahi[mt], tqh + off);
                ldsm_x4(alo[mt], tql + off);
            }
            uint32_t bh4[4], bl4[4];
            {
                uint32_t off = swz(bRow * 128 + (ks * 16 + bKof) * 2);
                ldsm_x4(bh4, tkh + off);
                ldsm_x4(bl4, tkl + off);
            }
#pragma unroll
            for (int mt = 0; mt < 2; ++mt)
#pragma unroll
                for (int nt = 0; nt < 2; ++nt) {
                    mma_bf16(acc[mt][nt], ahi[mt], &bh4[nt * 2]);
                    mma_bf16(acc[mt][nt], ahi[mt], &bl4[nt * 2]);
                    mma_bf16(acc[mt][nt], alo[mt], &bh4[nt * 2]);
                }
        }
    }

    const float scale = 0.08838834764831845f;
#pragma unroll
    for (int mt = 0; mt < 2; ++mt)
#pragma unroll
        for (int nt = 0; nt < 2; ++nt)
#pragma unroll
            for (int e = 0; e < 4; ++e) {
                int q = wm * 32 + mt * 16 + (lane >> 2) + (e >> 1) * 8;
                int s = s0 + wn * 16 + nt * 8 + 2 * (lane & 3) + (e & 1);
                float v = acc[mt][nt][e] * scale;
                v = tanhf(v * 0.02f) * 50.0f
                  + mask[(size_t)b * (1088 * 1344) + (size_t)(1024 + q) * 1344 + s];
                g_scores[(size_t)(bh * 64 + q) * STOT + s] = v;
            }
}

// ---------------- HMMA P @ V (validated) ----------------
__global__ void __launch_bounds__(256) pv_hmma()
{
    extern __shared__ char smem[];
    uint32_t sbase = smem_to_u32(smem);

    const int tid = threadIdx.x, lane = tid & 31, wid = tid >> 5;
    const int wm = wid & 1, wn = wid >> 1;
    int bh = blockIdx.x;
    int b = bh >> 4, h = bh & 15, kv = h >> 2;
    int kc0 = blockIdx.y * 192;

    size_t prow0 = (size_t)bh * 64;
    size_t vrow0 = (size_t)(b * NKV + kv) * HDIM;

    auto load_sub = [&](int stage, int kc) {
        uint32_t stb = sbase + stage * 49152;
#pragma unroll
        for (int it = 0; it < 2; ++it) {
            int idx = tid + it * 256;
            int r = idx >> 3, ch = idx & 7;
            uint32_t so = swz((uint32_t)(r * 128 + ch * 16));
            CP_ASYNC16(stb + so,        g_Ph + (prow0 + r) * STOT + kc + ch * 8);
            CP_ASYNC16(stb + 8192 + so, g_Pl + (prow0 + r) * STOT + kc + ch * 8);
        }
#pragma unroll
        for (int it = 0; it < 4; ++it) {
            int idx = tid + it * 256;
            int r = idx >> 3, ch = idx & 7;
            uint32_t so = swz((uint32_t)(r * 128 + ch * 16));
            CP_ASYNC16(stb + 16384 + so, g_Vth + (vrow0 + r) * STOT + kc + ch * 8);
            CP_ASYNC16(stb + 32768 + so, g_Vtl + (vrow0 + r) * STOT + kc + ch * 8);
        }
    };

    float acc[2][4][4];
#pragma unroll
    for (int i = 0; i < 2; ++i)
#pragma unroll
        for (int j = 0; j < 4; ++j)
#pragma unroll
            for (int k = 0; k < 4; ++k) acc[i][j][k] = 0.f;

    load_sub(0, kc0);
    CP_COMMIT();

    const uint32_t aRow = wm * 32 + (lane & 15);
    const uint32_t aKof = (lane >> 4) * 8;
    const uint32_t bRow = wn * 32 + ((lane >> 4) * 8) + (lane & 7);
    const uint32_t bKof = ((lane >> 3) & 1) * 8;

    for (int sub = 0; sub < 3; ++sub) {
        if (sub + 1 < 3) { load_sub((sub + 1) & 1, kc0 + (sub + 1) * 64); CP_COMMIT(); CP_WAIT(1); }
        else             { CP_WAIT(0); }
        __syncthreads();

        uint32_t st = sbase + (sub & 1) * 49152;
        uint32_t tph = st, tpl = st + 8192, tvh = st + 16384, tvl = st + 32768;

#pragma unroll
        for (int ks = 0; ks < 4; ++ks) {
            uint32_t ahi[2][4], alo[2][4];
#pragma unroll
            for (int mt = 0; mt < 2; ++mt) {
                uint32_t off = swz((aRow + mt * 16) * 128 + (ks * 16 + aKof) * 2);
                ldsm_x4(ahi[mt], tph + off);
                ldsm_x4(alo[mt], tpl + off);
            }
            uint32_t bhi[2][4], blo[2][4];
#pragma unroll
            for (int g = 0; g < 2; ++g) {
                uint32_t off = swz((bRow + g * 16) * 128 + (ks * 16 + bKof) * 2);
                ldsm_x4(bhi[g], tvh + off);
                ldsm_x4(blo[g], tvl + off);
            }
#pragma unroll
            for (int mt = 0; mt < 2; ++mt)
#pragma unroll
                for (int nt = 0; nt < 4; ++nt) {
                    const uint32_t* bh4 = &bhi[nt >> 1][(nt & 1) * 2];
                    const uint32_t* bl4 = &blo[nt >> 1][(nt & 1) * 2];
                    mma_bf16(acc[mt][nt], ahi[mt], bh4);
                    mma_bf16(acc[mt][nt], ahi[mt], bl4);
                    mma_bf16(acc[mt][nt], alo[mt], bh4);
                }
        }
        __syncthreads();
    }

#pragma unroll
    for (int mt = 0; mt < 2; ++mt)
#pragma unroll
        for (int nt = 0; nt < 4; ++nt)
#pragma unroll
            for (int e = 0; e < 4; ++e) {
                int q = wm * 32 + mt * 16 + (lane >> 2) + (e >> 1) * 8;
                int d = wn * 32 + nt * 8 + 2 * (lane & 3) + (e & 1);
                atomicAdd(&g_attn[(size_t)(b * SQA + q) * (NH * HDIM) + h * HDIM + d],
                          acc[mt][nt][e]);
            }
}

// ---------------- batched 2-tensor fp32 -> bf16 hi/lo conversion ----------------
__global__ void convA2_kernel(
    const float4* __restrict__ x0, __nv_bfloat162* hi0, __nv_bfloat162* lo0, int n40,
    const float4* __restrict__ x1, __nv_bfloat162* hi1, __nv_bfloat162* lo1, int n41)
{
    int i = blockIdx.x*blockDim.x + threadIdx.x;
    const float4* x; __nv_bfloat162 *hi, *lo;
    if (i < n40) { x = x0; hi = hi0; lo = lo0; }
    else if (i < n40 + n41) { i -= n40; x = x1; hi = hi1; lo = lo1; }
    else return;
    float4 v = x[i];
    __nv_bfloat16 h0 = __float2bfloat16(v.x), h1 = __float2bfloat16(v.y);
    __nv_bfloat16 h2 = __float2bfloat16(v.z), h3 = __float2bfloat16(v.w);
    __nv_bfloat16 l0 = __float2bfloat16(v.x - __bfloat162float(h0));
    __nv_bfloat16 l1 = __float2bfloat16(v.y - __bfloat162float(h1));
    __nv_bfloat16 l2 = __float2bfloat16(v.z - __bfloat162float(h2));
    __nv_bfloat16 l3 = __float2bfloat16(v.w - __bfloat162float(h3));
    hi[i*2+0] = __halves2bfloat162(h0, h1);
    hi[i*2+1] = __halves2bfloat162(h2, h3);
    lo[i*2+0] = __halves2bfloat162(l0, l1);
    lo[i*2+1] = __halves2bfloat162(l2, l3);
}

// ---------------- batched weight transpose+convert: all 6 weights ----------------
__device__ __forceinline__ void wt_tile(const float* __restrict__ W,
                                        __nv_bfloat16* bhi, __nv_bfloat16* blo,
                                        int Nd, int k0, int n0, int tx, int ty,
                                        float t[32][33])
{
#pragma unroll
    for (int i = 0; i < 4; ++i)
        t[ty + i*8][tx] = W[(size_t)(k0 + ty + i*8)*Nd + n0 + tx];
    __syncthreads();
#pragma unroll
    for (int i = 0; i < 4; ++i) {
        int n = ty + i*8;
        float v = t[tx][n];
        __nv_bfloat16 h = __float2bfloat16(v);
        __nv_bfloat16 l = __float2bfloat16(v - __bfloat162float(h));
        size_t o = (size_t)(n0 + n)*2048 + k0 + tx;
        bhi[o] = h; blo[o] = l;
    }
}

__global__ void convWT_all(
    const float* Wkv, const float* Wvv, const float* Wq,
    const float* Wka, const float* Wva, const float* Wo,
    __nv_bfloat16* kv_h, __nv_bfloat16* kv_l, __nv_bfloat16* vv_h, __nv_bfloat16* vv_l,
    __nv_bfloat16* q_h,  __nv_bfloat16* q_l,  __nv_bfloat16* ka_h, __nv_bfloat16* ka_l,
    __nv_bfloat16* va_h, __nv_bfloat16* va_l, __nv_bfloat16* o_h,  __nv_bfloat16* o_l)
{
    __shared__ float t[32][33];
    int bx = blockIdx.x;
    int tx = threadIdx.x, ty = threadIdx.y;
    if (bx < 1024)       { int l = bx;        wt_tile(Wkv, kv_h, kv_l,  512, (l>>4)*32, (l&15)*32, tx, ty, t); }
    else if (bx < 2048)  { int l = bx - 1024; wt_tile(Wvv, vv_h, vv_l,  512, (l>>4)*32, (l&15)*32, tx, ty, t); }
    else if (bx < 6144)  { int l = bx - 2048; wt_tile(Wq,  q_h,  q_l,  2048, (l>>6)*32, (l&63)*32, tx, ty, t); }
    else if (bx < 7168)  { int l = bx - 6144; wt_tile(Wka, ka_h, ka_l,  512, (l>>4)*32, (l&15)*32, tx, ty, t); }
    else if (bx < 8192)  { int l = bx - 7168; wt_tile(Wva, va_h, va_l,  512, (l>>4)*32, (l&15)*32, tx, ty, t); }
    else                 { int l = bx - 8192; wt_tile(Wo,  o_h,  o_l,  2048, (l>>6)*32, (l&63)*32, tx, ty, t); }
}

// V [bk][s][d] -> V^T [bk][d][s] bf16 hi/lo
__global__ void convVT_kernel()
{
    __shared__ float t[32][33];
    int z  = blockIdx.z;
    int s0 = blockIdx.y*32;
    int d0 = blockIdx.x*32;
    int tx = threadIdx.x, ty = threadIdx.y;
    const float* V = g_V + (size_t)z*STOT*HDIM;
#pragma unroll
    for (int i = 0; i < 4; ++i)
        t[ty + i*8][tx] = V[(size_t)(s0 + ty + i*8)*HDIM + d0 + tx];
    __syncthreads();
#pragma unroll
    for (int i = 0; i < 4; ++i) {
        int d = ty + i*8;
        float v = t[tx][d];
        __nv_bfloat16 h = __float2bfloat16(v);
        __nv_bfloat16 l = __float2bfloat16(v - __bfloat162float(h));
        size_t o = (size_t)z*HDIM*STOT + (size_t)(d0 + d)*STOT + s0 + tx;
        g_Vth[o] = h; g_Vtl[o] = l;
    }
}

// ---------------- zero-init + cache copy (merged) ----------------
__global__ void zero_copy_kernel(float* out, const float* __restrict__ kc,
                                 const float* __restrict__ vc)
{
    int tid = blockIdx.x*blockDim.x + threadIdx.x;
    int stride = gridDim.x*blockDim.x;
    const int nq = BB*NH*SQA*HDIM;
    const int na = BB*SQA*NH*HDIM;
    const int no = BB*SQA*DMODEL;
    const int nact = BB*NKV*SQA*HDIM;
    const int ncache = BB*NKV*SCACHE*HDIM;
    for (int i = tid; i < nq; i += stride) g_q[i] = 0.f;
    for (int i = tid; i < na; i += stride) g_attn[i] = 0.f;
    for (int i = tid; i < no; i += stride) out[i] = 0.f;
    for (int i = tid; i < nact; i += stride) {
        int d  = i & 127;
        int s  = (i >> 7) & 63;
        int bk = i >> 13;
        int idx = (bk*STOT + (SCACHE + SQV) + s)*HDIM + d;
        g_K[idx] = 0.f;
        g_V[idx] = 0.f;
    }
    for (int i = tid; i < ncache; i += stride) {
        int d  = i & 127;
        int s  = (i >> 7) & 255;
        int bk = i >> 15;
        int dst = (bk*STOT + s)*HDIM + d;
        g_K[dst] = kc[i];
        g_V[dst] = vc[i];
    }
}

// ---------------- fused RoPE: all 3 segments in one launch ----------------
#define ROPE_T0 (BB*NKV*SQV*64)
#define ROPE_T1 (BB*NKV*SQA*64)
#define ROPE_T2 (BB*NH*SQA*64)
__global__ void rope_all(const int* __restrict__ pos_vlm, const int* __restrict__ pos_act)
{
    int idx = blockIdx.x*blockDim.x + threadIdx.x;
    int which, nh, seqlen, s_off;
    const int* pos;
    if (idx < ROPE_T0) { which = 0; pos = pos_vlm; nh = NKV; seqlen = SQV; s_off = SCACHE; }
    else if (idx < ROPE_T0 + ROPE_T1) {
        idx -= ROPE_T0; which = 0; pos = pos_act; nh = NKV; seqlen = SQA; s_off = SCACHE + SQV;
    }
    else if (idx < ROPE_T0 + ROPE_T1 + ROPE_T2) {
        idx -= ROPE_T0 + ROPE_T1; which = 1; pos = pos_act; nh = NH; seqlen = SQA; s_off = 0;
    }
    else return;

    int i = idx & 63;
    int rest = idx >> 6;
    int s = rest % seqlen; rest /= seqlen;
    int hh = rest % nh;
    int b  = rest / nh;

    float* X = (which == 0) ? g_K : g_q;
    int stot = (which == 0) ? STOT : SQA;

    int p = pos[b*seqlen + s];
    float inv = exp2f(-0.20762050593046868f * (float)i);
    float ang = (float)p * inv;
    double ad  = (double)ang;
    double red = ad - rint(ad * 0.15915494309189535) * 6.283185307179586;
    float c  = cosf((float)red);
    float sn = sinf((float)red);

    size_t base = ((size_t)((b*nh + hh)*stot + s_off + s)) * HDIM;
    float x1 = X[base + i], x2 = X[base + 64 + i];
    X[base + i]      = x1*c - x2*sn;
    X[base + 64 + i] = x2*c + x1*sn;
}

// ---------------- row softmax -> P bf16 hi/lo ----------------
__global__ void softmax_kernel()
{
    int row  = blockIdx.x*4 + (threadIdx.x >> 5);
    int lane = threadIdx.x & 31;
    const float* p = g_scores + (size_t)row * STOT;

    float vals[42];
    float m = -1e30f;
#pragma unroll
    for (int i = 0; i < 42; i++) { vals[i] = p[i*32 + lane]; m = fmaxf(m, vals[i]); }
#pragma unroll
    for (int off = 16; off > 0; off >>= 1) m = fmaxf(m, __shfl_xor_sync(0xffffffffu, m, off));
    float sum = 0.f;
#pragma unroll
    for (int i = 0; i < 42; i++) { vals[i] = __expf(vals[i] - m); sum += vals[i]; }
#pragma unroll
    for (int off = 16; off > 0; off >>= 1) sum += __shfl_xor_sync(0xffffffffu, sum, off);
    float invs = 1.0f / sum;
    __nv_bfloat16* ph = g_Ph + (size_t)row * STOT;
    __nv_bfloat16* pl = g_Pl + (size_t)row * STOT;
#pragma unroll
    for (int i = 0; i < 42; i++) {
        float v = vals[i] * invs;
        __nv_bfloat16 h = __float2bfloat16(v);
        ph[i*32 + lane] = h;
        pl[i*32 + lane] = __float2bfloat16(v - __bfloat162float(h));
    }
}

// ---------------- launch ----------------
extern "C" void kernel_launch(void* const* d_in, const int* in_sizes, int n_in,
                              void* d_out, int out_size)
{
    (void)in_sizes; (void)n_in; (void)out_size;
    const float* mask    = (const float*)d_in[0];
    const int*   pos_vlm = (const int*)  d_in[1];
    const int*   pos_act = (const int*)  d_in[2];
    const float* h_vlm   = (const float*)d_in[3];
    const float* h_act   = (const float*)d_in[4];
    const float* k_cache = (const float*)d_in[5];
    const float* v_cache = (const float*)d_in[6];
    // d_in[7] = Wq_vlm: unused (q_vlm rows are discarded by reference)
    const float* Wk_vlm  = (const float*)d_in[8];
    const float* Wv_vlm  = (const float*)d_in[9];
    const float* Wq_act  = (const float*)d_in[10];
    const float* Wk_act  = (const float*)d_in[11];
    const float* Wv_act  = (const float*)d_in[12];
    const float* Wo_act  = (const float*)d_in[13];
    float* out = (float*)d_out;

    void *p_hv_hi, *p_hv_lo, *p_ha_hi, *p_ha_lo, *p_at_hi, *p_at_lo;
    void *p_wkv_hi, *p_wkv_lo, *p_wvv_hi, *p_wvv_lo, *p_wq_hi, *p_wq_lo;
    void *p_wka_hi, *p_wka_lo, *p_wva_hi, *p_wva_lo, *p_wo_hi, *p_wo_lo, *p_attn;
    void *p_K, *p_q, *p_Kh, *p_Kl, *p_qh, *p_ql;
    cudaGetSymbolAddress(&p_hv_hi, g_hv_hi);   cudaGetSymbolAddress(&p_hv_lo, g_hv_lo);
    cudaGetSymbolAddress(&p_ha_hi, g_ha_hi);   cudaGetSymbolAddress(&p_ha_lo, g_ha_lo);
    cudaGetSymbolAddress(&p_at_hi, g_at_hi);   cudaGetSymbolAddress(&p_at_lo, g_at_lo);
    cudaGetSymbolAddress(&p_wkv_hi, g_wkv_hi); cudaGetSymbolAddress(&p_wkv_lo, g_wkv_lo);
    cudaGetSymbolAddress(&p_wvv_hi, g_wvv_hi); cudaGetSymbolAddress(&p_wvv_lo, g_wvv_lo);
    cudaGetSymbolAddress(&p_wq_hi, g_wq_hi);   cudaGetSymbolAddress(&p_wq_lo, g_wq_lo);
    cudaGetSymbolAddress(&p_wka_hi, g_wka_hi); cudaGetSymbolAddress(&p_wka_lo, g_wka_lo);
    cudaGetSymbolAddress(&p_wva_hi, g_wva_hi); cudaGetSymbolAddress(&p_wva_lo, g_wva_lo);
    cudaGetSymbolAddress(&p_wo_hi, g_wo_hi);   cudaGetSymbolAddress(&p_wo_lo, g_wo_lo);
    cudaGetSymbolAddress(&p_attn, g_attn);
    cudaGetSymbolAddress(&p_K, g_K);   cudaGetSymbolAddress(&p_q, g_q);
    cudaGetSymbolAddress(&p_Kh, g_Kh); cudaGetSymbolAddress(&p_Kl, g_Kl);
    cudaGetSymbolAddress(&p_qh, g_qh); cudaGetSymbolAddress(&p_ql, g_ql);

    cudaFuncSetAttribute(tc_gemm_multi, cudaFuncAttributeMaxDynamicSharedMemorySize, TCG_SMEM_BYTES);
    cudaFuncSetAttribute(score_hmma,    cudaFuncAttributeMaxDynamicSharedMemorySize, 65536);
    cudaFuncSetAttribute(pv_hmma,       cudaFuncAttributeMaxDynamicSharedMemorySize, 98304);

    // 1. zero + cache copy
    zero_copy_kernel<<<1024, 256>>>(out, k_cache, v_cache);

    // 2. activations -> bf16 hi/lo (h_vlm + h_act batched)
    {
        int n40 = 4096*2048/4, n41 = 256*2048/4;
        convA2_kernel<<<(n40 + n41 + 255)/256, 256>>>(
            (const float4*)h_vlm, (__nv_bfloat162*)p_hv_hi, (__nv_bfloat162*)p_hv_lo, n40,
            (const float4*)h_act, (__nv_bfloat162*)p_ha_hi, (__nv_bfloat162*)p_ha_lo, n41);
    }

    // 3. all 6 weight transposes+conversions in one launch
    convWT_all<<<12288, dim3(32, 8)>>>(
        Wk_vlm, Wv_vlm, Wq_act, Wk_act, Wv_act, Wo_act,
        (__nv_bfloat16*)p_wkv_hi, (__nv_bfloat16*)p_wkv_lo,
        (__nv_bfloat16*)p_wvv_hi, (__nv_bfloat16*)p_wvv_lo,
        (__nv_bfloat16*)p_wq_hi,  (__nv_bfloat16*)p_wq_lo,
        (__nv_bfloat16*)p_wka_hi, (__nv_bfloat16*)p_wka_lo,
        (__nv_bfloat16*)p_wva_hi, (__nv_bfloat16*)p_wva_lo,
        (__nv_bfloat16*)p_wo_hi,  (__nv_bfloat16*)p_wo_lo);

    // 4. vlm K+V projections fused (N = 512+512), 64x128 tiles, 2 CTAs/SM
    tc_gemm_multi<<<dim3(8, 64, 1), 256, TCG_SMEM_BYTES>>>(
        (const __nv_bfloat16*)p_hv_hi, (const __nv_bfloat16*)p_hv_lo,
        (const __nv_bfloat16*)p_wkv_hi, (const __nv_bfloat16*)p_wkv_lo, 512, 1, 0,
        (const __nv_bfloat16*)p_wvv_hi, (const __nv_bfloat16*)p_wvv_lo, 512, 1, 1,
        nullptr, nullptr, 0, 0, 0,
        nullptr, 4096, 2048, 2048);

    // 5. action Q+K+V projections fused (N = 2048+512+512), split-K 4
    tc_gemm_multi<<<dim3(24, 4, 4), 256, TCG_SMEM_BYTES>>>(
        (const __nv_bfloat16*)p_ha_hi, (const __nv_bfloat16*)p_ha_lo,
        (const __nv_bfloat16*)p_wq_hi,  (const __nv_bfloat16*)p_wq_lo,  2048, 3, 2,
        (const __nv_bfloat16*)p_wka_hi, (const __nv_bfloat16*)p_wka_lo,  512, 2, 0,
        (const __nv_bfloat16*)p_wva_hi, (const __nv_bfloat16*)p_wva_lo,  512, 2, 1,
        nullptr, 256, 2048, 512);

    // 6. RoPE (all segments)
    rope_all<<<(ROPE_T0 + ROPE_T1 + ROPE_T2 + 255)/256, 256>>>(pos_vlm, pos_act);

    // 7. K + q -> bf16 hi/lo (batched)
    {
        int n40 = BB*NKV*STOT*HDIM/4, n41 = BB*NH*SQA*HDIM/4;
        convA2_kernel<<<(n40 + n41 + 255)/256, 256>>>(
            (const float4*)p_K, (__nv_bfloat162*)p_Kh, (__nv_bfloat162*)p_Kl, n40,
            (const float4*)p_q, (__nv_bfloat162*)p_qh, (__nv_bfloat162*)p_ql, n41);
    }
    // 8. V transpose + convert
    convVT_kernel<<<dim3(4, 42, 16), dim3(32, 8)>>>();

    // 9-11. attention on HMMA
    score_hmma<<<dim3(21, 64), 256, 65536>>>(mask);
    softmax_kernel<<<1024, 128>>>();
    pv_hmma<<<dim3(64, 7), 256, 98304>>>();

    // 12. attn -> bf16 hi/lo
    convA2_kernel<<<(256*2048/4 + 255)/256, 256>>>(
        (const float4*)p_attn, (__nv_bfloat162*)p_at_hi, (__nv_bfloat162*)p_at_lo, 256*2048/4,
        nullptr, nullptr, nullptr, 0);

    // 13. output projection, split-K 4
    tc_gemm_multi<<<dim3(16, 4, 4), 256, TCG_SMEM_BYTES>>>(
        (const __nv_bfloat16*)p_at_hi, (const __nv_bfloat16*)p_at_lo,
        (const __nv_bfloat16*)p_wo_hi, (const __nv_bfloat16*)p_wo_lo, 2048, 0, 3,
        nullptr, nullptr, 0, 0, 0,
        nullptr, nullptr, 0, 0, 0,
        out, 256, 2048, 512);
}

// round 12
// speedup vs baseline: 3.4938x; 1.0939x over previous
#include <cuda_runtime.h>
#include <cuda_bf16.h>
#include <math.h>
#include <stdint.h>

// ---------------- problem constants ----------------
#define BB      4
#define NH      16
#define NKV     4
#define HDIM    128
#define DMODEL  2048
#define SQV     1024
#define SQA     64
#define SCACHE  256
#define STOT    1344
#define NQROWS  (BB*NH*SQA)

// ---------------- fp32 scratch ----------------
__device__ float g_K[BB*NKV*STOT*HDIM];    // only vlm+act rows used (GEMM -> rope)
__device__ float g_V[BB*NKV*STOT*HDIM];
__device__ float g_q[BB*NH*SQA*HDIM];
__device__ float g_scores[NQROWS*STOT];
__device__ float g_attn[BB*SQA*NH*HDIM];

// ---------------- bf16 split operands (hi + lo) ----------------
__device__ __nv_bfloat16 g_hv_hi[4096*2048], g_hv_lo[4096*2048];
__device__ __nv_bfloat16 g_ha_hi[256*2048],  g_ha_lo[256*2048];
__device__ __nv_bfloat16 g_at_hi[256*2048],  g_at_lo[256*2048];
__device__ __nv_bfloat16 g_wkv_hi[512*2048], g_wkv_lo[512*2048];
__device__ __nv_bfloat16 g_wvv_hi[512*2048], g_wvv_lo[512*2048];
__device__ __nv_bfloat16 g_wq_hi[2048*2048], g_wq_lo[2048*2048];
__device__ __nv_bfloat16 g_wka_hi[512*2048], g_wka_lo[512*2048];
__device__ __nv_bfloat16 g_wva_hi[512*2048], g_wva_lo[512*2048];
__device__ __nv_bfloat16 g_wo_hi[2048*2048], g_wo_lo[2048*2048];

// attention bf16 operands
__device__ __nv_bfloat16 g_qh[BB*NH*SQA*HDIM],  g_ql[BB*NH*SQA*HDIM];
__device__ __nv_bfloat16 g_Kh[BB*NKV*STOT*HDIM], g_Kl[BB*NKV*STOT*HDIM];
__device__ __nv_bfloat16 g_Vth[BB*NKV*HDIM*STOT], g_Vtl[BB*NKV*HDIM*STOT];
__device__ __nv_bfloat16 g_Ph[NQROWS*STOT], g_Pl[NQROWS*STOT];

// ================= PTX helpers =================
__device__ __forceinline__ uint32_t smem_to_u32(const void* p) {
    uint32_t a;
    asm("{ .reg .u64 t; cvta.to.shared.u64 t, %1; cvt.u32.u64 %0, t; }" : "=r"(a) : "l"(p));
    return a;
}
#define CP_ASYNC16(sm, gm) \
    asm volatile("cp.async.cg.shared.global [%0], [%1], 16;" :: "r"(sm), "l"(gm))
#define CP_COMMIT() asm volatile("cp.async.commit_group;" ::: "memory")
#define CP_WAIT(n)  asm volatile("cp.async.wait_group %0;" :: "n"(n) : "memory")

__device__ __forceinline__ void ldsm_x4(uint32_t* r, uint32_t addr) {
    asm volatile("ldmatrix.sync.aligned.m8n8.x4.shared.b16 {%0,%1,%2,%3}, [%4];"
        : "=r"(r[0]), "=r"(r[1]), "=r"(r[2]), "=r"(r[3]) : "r"(addr));
}
__device__ __forceinline__ void mma_bf16(float* d, const uint32_t* a, const uint32_t* b) {
    asm volatile("mma.sync.aligned.m16n8k16.row.col.f32.bf16.bf16.f32 "
        "{%0,%1,%2,%3}, {%4,%5,%6,%7}, {%8,%9}, {%0,%1,%2,%3};"
        : "+f"(d[0]), "+f"(d[1]), "+f"(d[2]), "+f"(d[3])
        : "r"(a[0]), "r"(a[1]), "r"(a[2]), "r"(a[3]), "r"(b[0]), "r"(b[1]));
}
__device__ __forceinline__ uint32_t swz(uint32_t off) { return off ^ ((off >> 3) & 0x70); }

__device__ __forceinline__ void split_bf16(float v, __nv_bfloat16& h, __nv_bfloat16& l) {
    h = __float2bfloat16(v);
    l = __float2bfloat16(v - __bfloat162float(h));
}

// ---------------- output index mapping ----------------
__device__ __forceinline__ int out_index(int map, int r, int c, int N) {
    switch (map) {
        case 1: { int b=r>>10, s=r&1023, kv=c>>7, d=c&127;
                  return (((b*NKV+kv)*STOT) + SCACHE + s)*HDIM + d; }
        case 2: { int b=r>>6, s=r&63, kv=c>>7, d=c&127;
                  return (((b*NKV+kv)*STOT) + (SCACHE+SQV) + s)*HDIM + d; }
        case 3: { int b=r>>6, s=r&63, h=c>>7, d=c&127;
                  return (((b*NH+h)*SQA) + s)*HDIM + d; }
        default: return r*N + c;
    }
}

// ---------------- merged projection GEMM: vlm KV + action QKV in one launch ----------
// 64x128 CTA tile, 2 CTAs/SM. smem/stage 48KB x 2 stages = 96KB.
// Blocks [0,512): vlm  — A=g_hv, n over {wkv 512 | wvv 512}, m in [0,64), K=2048 full.
// Blocks [512,896): act — A=g_ha, n over {wq 2048 | wka 512 | wva 512}, m in [0,4),
//                         split-K 4 (atomicAdd epilogue).
#define TCG_SMEM_BYTES (98304)
__global__ void __launch_bounds__(256, 2) tc_proj()
{
    extern __shared__ char smem[];
    uint32_t sbase = smem_to_u32(smem);

    const int tid = threadIdx.x, lane = tid & 31, wid = tid >> 5;
    const int wm = wid & 1, wn = wid >> 1;

    int bid = blockIdx.x;
    const __nv_bfloat16 *Ahi, *Alo, *Bh, *Bl;
    int m0, n0, kstart, nch, map, dest, Nl;
    bool split;
    const int K = 2048;

    if (bid < 512) {
        // vlm segment: 8 n-blocks x 64 m-blocks
        int n = bid & 7, m = bid >> 3;
        m0 = m * 64; kstart = 0; nch = 32; split = false;
        Ahi = g_hv_hi; Alo = g_hv_lo;
        int n0g = n * 128;
        if (n0g < 512) { Bh = g_wkv_hi; Bl = g_wkv_lo; n0 = n0g;       map = 1; dest = 0; Nl = 512; }
        else           { Bh = g_wvv_hi; Bl = g_wvv_lo; n0 = n0g - 512; map = 1; dest = 1; Nl = 512; }
    } else {
        // act segment: 24 n-blocks x 4 m-blocks x 4 k-slices
        int l = bid - 512;
        int n = l % 24; l /= 24;
        int m = l & 3;  int z = l >> 2;
        m0 = m * 64; kstart = z * 512; nch = 8; split = true;
        Ahi = g_ha_hi; Alo = g_ha_lo;
        int n0g = n * 128;
        if (n0g < 2048)      { Bh = g_wq_hi;  Bl = g_wq_lo;  n0 = n0g;        map = 3; dest = 2; Nl = 2048; }
        else if (n0g < 2560) { Bh = g_wka_hi; Bl = g_wka_lo; n0 = n0g - 2048; map = 2; dest = 0; Nl = 512; }
        else                 { Bh = g_wva_hi; Bl = g_wva_lo; n0 = n0g - 2560; map = 2; dest = 1; Nl = 512; }
    }

    auto load_stage = [&](int stage, int kof) {
        uint32_t stb = sbase + stage * 49152;
#pragma unroll
        for (int it = 0; it < 2; ++it) {
            int idx = tid + it * 256;
            int r = idx >> 3, ch = idx & 7;
            uint32_t so = swz((uint32_t)(r * 128 + ch * 16));
            CP_ASYNC16(stb + so,        Ahi + (size_t)(m0 + r) * K + kof + ch * 8);
            CP_ASYNC16(stb + 8192 + so, Alo + (size_t)(m0 + r) * K + kof + ch * 8);
        }
#pragma unroll
        for (int it = 0; it < 4; ++it) {
            int idx = tid + it * 256;
            int r = idx >> 3, ch = idx & 7;
            uint32_t so = swz((uint32_t)(r * 128 + ch * 16));
            CP_ASYNC16(stb + 16384 + so, Bh + (size_t)(n0 + r) * K + kof + ch * 8);
            CP_ASYNC16(stb + 32768 + so, Bl + (size_t)(n0 + r) * K + kof + ch * 8);
        }
    };

    float acc[2][4][4];
#pragma unroll
    for (int i = 0; i < 2; ++i)
#pragma unroll
        for (int j = 0; j < 4; ++j)
#pragma unroll
            for (int k = 0; k < 4; ++k) acc[i][j][k] = 0.f;

    load_stage(0, kstart);
    CP_COMMIT();

    const uint32_t aRow = wm * 32 + (lane & 15);
    const uint32_t aKof = (lane >> 4) * 8;
    const uint32_t bRow = wn * 32 + ((lane >> 4) * 8) + (lane & 7);
    const uint32_t bKof = ((lane >> 3) & 1) * 8;

    for (int c = 0; c < nch; ++c) {
        if (c + 1 < nch) { load_stage((c + 1) & 1, kstart + (c + 1) * 64); CP_COMMIT(); CP_WAIT(1); }
        else             { CP_WAIT(0); }
        __syncthreads();

        uint32_t st = sbase + (c & 1) * 49152;
        uint32_t tAhi = st, tAlo = st + 8192, tBhi = st + 16384, tBlo = st + 32768;

#pragma unroll
        for (int ks = 0; ks < 4; ++ks) {
            uint32_t ahi[2][4], alo[2][4];
#pragma unroll
            for (int mt = 0; mt < 2; ++mt) {
                uint32_t off = swz((aRow + mt * 16) * 128 + (ks * 16 + aKof) * 2);
                ldsm_x4(ahi[mt], tAhi + off);
                ldsm_x4(alo[mt], tAlo + off);
            }
            uint32_t bhi[2][4], blo[2][4];
#pragma unroll
            for (int g = 0; g < 2; ++g) {
                uint32_t off = swz((bRow + g * 16) * 128 + (ks * 16 + bKof) * 2);
                ldsm_x4(bhi[g], tBhi + off);
                ldsm_x4(blo[g], tBlo + off);
            }
#pragma unroll
            for (int mt = 0; mt < 2; ++mt)
#pragma unroll
                for (int nt = 0; nt < 4; ++nt) {
                    const uint32_t* bh4 = &bhi[nt >> 1][(nt & 1) * 2];
                    const uint32_t* bl4 = &blo[nt >> 1][(nt & 1) * 2];
                    mma_bf16(acc[mt][nt], ahi[mt], bh4);
                    mma_bf16(acc[mt][nt], ahi[mt], bl4);
                    mma_bf16(acc[mt][nt], alo[mt], bh4);
                }
        }
        __syncthreads();
    }

    float* C = (dest == 0) ? g_K : (dest == 1) ? g_V : g_q;
#pragma unroll
    for (int mt = 0; mt < 2; ++mt)
#pragma unroll
        for (int nt = 0; nt < 4; ++nt)
#pragma unroll
            for (int e = 0; e < 4; ++e) {
                int r = m0 + wm * 32 + mt * 16 + (lane >> 2) + (e >> 1) * 8;
                int cc = n0 + wn * 32 + nt * 8 + 2 * (lane & 3) + (e & 1);
                int idx = out_index(map, r, cc, Nl);
                if (split) atomicAdd(&C[idx], acc[mt][nt][e]);
                else       C[idx] = acc[mt][nt][e];
            }
}

// ---------------- Wo GEMM: out = attn @ Wo^T, split-K 4 ----------------
__global__ void __launch_bounds__(256, 2) tc_wo(float* __restrict__ Cext)
{
    extern __shared__ char smem[];
    uint32_t sbase = smem_to_u32(smem);

    const int tid = threadIdx.x, lane = tid & 31, wid = tid >> 5;
    const int wm = wid & 1, wn = wid >> 1;
    const int m0 = blockIdx.y * 64;
    const int n0 = blockIdx.x * 128;
    const int kstart = blockIdx.z * 512;
    const int K = 2048, nch = 8;

    auto load_stage = [&](int stage, int kof) {
        uint32_t stb = sbase + stage * 49152;
#pragma unroll
        for (int it = 0; it < 2; ++it) {
            int idx = tid + it * 256;
            int r = idx >> 3, ch = idx & 7;
            uint32_t so = swz((uint32_t)(r * 128 + ch * 16));
            CP_ASYNC16(stb + so,        g_at_hi + (size_t)(m0 + r) * K + kof + ch * 8);
            CP_ASYNC16(stb + 8192 + so, g_at_lo + (size_t)(m0 + r) * K + kof + ch * 8);
        }
#pragma unroll
        for (int it = 0; it < 4; ++it) {
            int idx = tid + it * 256;
            int r = idx >> 3, ch = idx & 7;
            uint32_t so = swz((uint32_t)(r * 128 + ch * 16));
            CP_ASYNC16(stb + 16384 + so, g_wo_hi + (size_t)(n0 + r) * K + kof + ch * 8);
            CP_ASYNC16(stb + 32768 + so, g_wo_lo + (size_t)(n0 + r) * K + kof + ch * 8);
        }
    };

    float acc[2][4][4];
#pragma unroll
    for (int i = 0; i < 2; ++i)
#pragma unroll
        for (int j = 0; j < 4; ++j)
#pragma unroll
            for (int k = 0; k < 4; ++k) acc[i][j][k] = 0.f;

    load_stage(0, kstart);
    CP_COMMIT();

    const uint32_t aRow = wm * 32 + (lane & 15);
    const uint32_t aKof = (lane >> 4) * 8;
    const uint32_t bRow = wn * 32 + ((lane >> 4) * 8) + (lane & 7);
    const uint32_t bKof = ((lane >> 3) & 1) * 8;

    for (int c = 0; c < nch; ++c) {
        if (c + 1 < nch) { load_stage((c + 1) & 1, kstart + (c + 1) * 64); CP_COMMIT(); CP_WAIT(1); }
        else             { CP_WAIT(0); }
        __syncthreads();

        uint32_t st = sbase + (c & 1) * 49152;
        uint32_t tAhi = st, tAlo = st + 8192, tBhi = st + 16384, tBlo = st + 32768;

#pragma unroll
        for (int ks = 0; ks < 4; ++ks) {
            uint32_t ahi[2][4], alo[2][4];
#pragma unroll
            for (int mt = 0; mt < 2; ++mt) {
                uint32_t off = swz((aRow + mt * 16) * 128 + (ks * 16 + aKof) * 2);
                ldsm_x4(ahi[mt], tAhi + off);
                ldsm_x4(alo[mt], tAlo + off);
            }
            uint32_t bhi[2][4], blo[2][4];
#pragma unroll
            for (int g = 0; g < 2; ++g) {
                uint32_t off = swz((bRow + g * 16) * 128 + (ks * 16 + bKof) * 2);
                ldsm_x4(bhi[g], tBhi + off);
                ldsm_x4(blo[g], tBlo + off);
            }
#pragma unroll
            for (int mt = 0; mt < 2; ++mt)
#pragma unroll
                for (int nt = 0; nt < 4; ++nt) {
                    const uint32_t* bh4 = &bhi[nt >> 1][(nt & 1) * 2];
                    const uint32_t* bl4 = &blo[nt >> 1][(nt & 1) * 2];
                    mma_bf16(acc[mt][nt], ahi[mt], bh4);
                    mma_bf16(acc[mt][nt], ahi[mt], bl4);
                    mma_bf16(acc[mt][nt], alo[mt], bh4);
                }
        }
        __syncthreads();
    }

#pragma unroll
    for (int mt = 0; mt < 2; ++mt)
#pragma unroll
        for (int nt = 0; nt < 4; ++nt)
#pragma unroll
            for (int e = 0; e < 4; ++e) {
                int r = m0 + wm * 32 + mt * 16 + (lane >> 2) + (e >> 1) * 8;
                int cc = n0 + wn * 32 + nt * 8 + 2 * (lane & 3) + (e & 1);
                atomicAdd(&Cext[(size_t)r * 2048 + cc], acc[mt][nt][e]);
            }
}

// ---------------- HMMA attention scores (validated) ----------------
__global__ void __launch_bounds__(256) score_hmma(const float* __restrict__ mask)
{
    extern __shared__ char smem[];
    uint32_t sbase = smem_to_u32(smem);

    const int tid = threadIdx.x, lane = tid & 31, wid = tid >> 5;
    const int wm = wid & 1, wn = wid >> 1;
    int bh = blockIdx.y;
    int b = bh >> 4, h = bh & 15, kv = h >> 2;
    int s0 = blockIdx.x * 64;
    (void)h;

#pragma unroll
    for (int it = 0; it < 2; ++it) {
        int idx = tid + it * 256;
        int r = idx >> 3, ch = idx & 7;
        uint32_t so = swz((uint32_t)(r * 128 + ch * 16));
        size_t qoff = (size_t)(bh * 64 + r) * HDIM;
        size_t koff = (size_t)((b * NKV + kv) * STOT + s0 + r) * HDIM;
#pragma unroll
        for (int c = 0; c < 2; ++c) {
            CP_ASYNC16(sbase + (0 + c) * 8192 + so, g_qh + qoff + c * 64 + ch * 8);
            CP_ASYNC16(sbase + (2 + c) * 8192 + so, g_ql + qoff + c * 64 + ch * 8);
            CP_ASYNC16(sbase + (4 + c) * 8192 + so, g_Kh + koff + c * 64 + ch * 8);
            CP_ASYNC16(sbase + (6 + c) * 8192 + so, g_Kl + koff + c * 64 + ch * 8);
        }
    }
    CP_COMMIT();
    CP_WAIT(0);
    __syncthreads();

    float acc[2][2][4];
#pragma unroll
    for (int i = 0; i < 2; ++i)
#pragma unroll
        for (int j = 0; j < 2; ++j)
#pragma unroll
            for (int k = 0; k < 4; ++k) acc[i][j][k] = 0.f;

    const uint32_t aRow = wm * 32 + (lane & 15);
    const uint32_t aKof = (lane >> 4) * 8;
    const uint32_t bRow = wn * 16 + ((lane >> 4) * 8) + (lane & 7);
    const uint32_t bKof = ((lane >> 3) & 1) * 8;

#pragma unroll
    for (int c = 0; c < 2; ++c) {
        uint32_t tqh = sbase + (0 + c) * 8192, tql = sbase + (2 + c) * 8192;
        uint32_t tkh = sbase + (4 + c) * 8192, tkl = sbase + (6 + c) * 8192;
#pragma unroll
        for (int ks = 0; ks < 4; ++ks) {
            uint32_t ahi[2][4], alo[2][4];
#pragma unroll
            for (int mt = 0; mt < 2; ++mt) {
                uint32_t off = swz((aRow + mt * 16) * 128 + (ks * 16 + aKof) * 2);
                ldsm_x4(ahi[mt], tqh + off);
                ldsm_x4(alo[mt], tql + off);
            }
            uint32_t bh4[4], bl4[4];
            {
                uint32_t off = swz(bRow * 128 + (ks * 16 + bKof) * 2);
                ldsm_x4(bh4, tkh + off);
                ldsm_x4(bl4, tkl + off);
            }
#pragma unroll
            for (int mt = 0; mt < 2; ++mt)
#pragma unroll
                for (int nt = 0; nt < 2; ++nt) {
                    mma_bf16(acc[mt][nt], ahi[mt], &bh4[nt * 2]);
                    mma_bf16(acc[mt][nt], ahi[mt], &bl4[nt * 2]);
                    mma_bf16(acc[mt][nt], alo[mt], &bh4[nt * 2]);
                }
        }
    }

    const float scale = 0.08838834764831845f;
#pragma unroll
    for (int mt = 0; mt < 2; ++mt)
#pragma unroll
        for (int nt = 0; nt < 2; ++nt)
#pragma unroll
            for (int e = 0; e < 4; ++e) {
                int q = wm * 32 + mt * 16 + (lane >> 2) + (e >> 1) * 8;
                int s = s0 + wn * 16 + nt * 8 + 2 * (lane & 3) + (e & 1);
                float v = acc[mt][nt][e] * scale;
                v = tanhf(v * 0.02f) * 50.0f
                  + mask[(size_t)b * (1088 * 1344) + (size_t)(1024 + q) * 1344 + s];
                g_scores[(size_t)(bh * 64 + q) * STOT + s] = v;
            }
}

// ---------------- HMMA P @ V (validated) ----------------
__global__ void __launch_bounds__(256) pv_hmma()
{
    extern __shared__ char smem[];
    uint32_t sbase = smem_to_u32(smem);

    const int tid = threadIdx.x, lane = tid & 31, wid = tid >> 5;
    const int wm = wid & 1, wn = wid >> 1;
    int bh = blockIdx.x;
    int b = bh >> 4, h = bh & 15, kv = h >> 2;
    int kc0 = blockIdx.y * 192;

    size_t prow0 = (size_t)bh * 64;
    size_t vrow0 = (size_t)(b * NKV + kv) * HDIM;

    auto load_sub = [&](int stage, int kc) {
        uint32_t stb = sbase + stage * 49152;
#pragma unroll
        for (int it = 0; it < 2; ++it) {
            int idx = tid + it * 256;
            int r = idx >> 3, ch = idx & 7;
            uint32_t so = swz((uint32_t)(r * 128 + ch * 16));
            CP_ASYNC16(stb + so,        g_Ph + (prow0 + r) * STOT + kc + ch * 8);
            CP_ASYNC16(stb + 8192 + so, g_Pl + (prow0 + r) * STOT + kc + ch * 8);
        }
#pragma unroll
        for (int it = 0; it < 4; ++it) {
            int idx = tid + it * 256;
            int r = idx >> 3, ch = idx & 7;
            uint32_t so = swz((uint32_t)(r * 128 + ch * 16));
            CP_ASYNC16(stb + 16384 + so, g_Vth + (vrow0 + r) * STOT + kc + ch * 8);
            CP_ASYNC16(stb + 32768 + so, g_Vtl + (vrow0 + r) * STOT + kc + ch * 8);
        }
    };

    float acc[2][4][4];
#pragma unroll
    for (int i = 0; i < 2; ++i)
#pragma unroll
        for (int j = 0; j < 4; ++j)
#pragma unroll
            for (int k = 0; k < 4; ++k) acc[i][j][k] = 0.f;

    load_sub(0, kc0);
    CP_COMMIT();

    const uint32_t aRow = wm * 32 + (lane & 15);
    const uint32_t aKof = (lane >> 4) * 8;
    const uint32_t bRow = wn * 32 + ((lane >> 4) * 8) + (lane & 7);
    const uint32_t bKof = ((lane >> 3) & 1) * 8;

    for (int sub = 0; sub < 3; ++sub) {
        if (sub + 1 < 3) { load_sub((sub + 1) & 1, kc0 + (sub + 1) * 64); CP_COMMIT(); CP_WAIT(1); }
        else             { CP_WAIT(0); }
        __syncthreads();

        uint32_t st = sbase + (sub & 1) * 49152;
        uint32_t tph = st, tpl = st + 8192, tvh = st + 16384, tvl = st + 32768;

#pragma unroll
        for (int ks = 0; ks < 4; ++ks) {
            uint32_t ahi[2][4], alo[2][4];
#pragma unroll
            for (int mt = 0; mt < 2; ++mt) {
                uint32_t off = swz((aRow + mt * 16) * 128 + (ks * 16 + aKof) * 2);
                ldsm_x4(ahi[mt], tph + off);
                ldsm_x4(alo[mt], tpl + off);
            }
            uint32_t bhi[2][4], blo[2][4];
#pragma unroll
            for (int g = 0; g < 2; ++g) {
                uint32_t off = swz((bRow + g * 16) * 128 + (ks * 16 + bKof) * 2);
                ldsm_x4(bhi[g], tvh + off);
                ldsm_x4(blo[g], tvl + off);
            }
#pragma unroll
            for (int mt = 0; mt < 2; ++mt)
#pragma unroll
                for (int nt = 0; nt < 4; ++nt) {
                    const uint32_t* bh4 = &bhi[nt >> 1][(nt & 1) * 2];
                    const uint32_t* bl4 = &blo[nt >> 1][(nt & 1) * 2];
                    mma_bf16(acc[mt][nt], ahi[mt], bh4);
                    mma_bf16(acc[mt][nt], ahi[mt], bl4);
                    mma_bf16(acc[mt][nt], alo[mt], bh4);
                }
        }
        __syncthreads();
    }

#pragma unroll
    for (int mt = 0; mt < 2; ++mt)
#pragma unroll
        for (int nt = 0; nt < 4; ++nt)
#pragma unroll
            for (int e = 0; e < 4; ++e) {
                int q = wm * 32 + mt * 16 + (lane >> 2) + (e >> 1) * 8;
                int d = wn * 32 + nt * 8 + 2 * (lane & 3) + (e & 1);
                atomicAdd(&g_attn[(size_t)(b * SQA + q) * (NH * HDIM) + h * HDIM + d],
                          acc[mt][nt][e]);
            }
}

// ---------------- batched 2-tensor fp32 -> bf16 hi/lo conversion ----------------
__global__ void convA2_kernel(
    const float4* __restrict__ x0, __nv_bfloat162* hi0, __nv_bfloat162* lo0, int n40,
    const float4* __restrict__ x1, __nv_bfloat162* hi1, __nv_bfloat162* lo1, int n41)
{
    int i = blockIdx.x*blockDim.x + threadIdx.x;
    const float4* x; __nv_bfloat162 *hi, *lo;
    if (i < n40) { x = x0; hi = hi0; lo = lo0; }
    else if (i < n40 + n41) { i -= n40; x = x1; hi = hi1; lo = lo1; }
    else return;
    float4 v = x[i];
    __nv_bfloat16 h0, h1, h2, h3, l0, l1, l2, l3;
    split_bf16(v.x, h0, l0); split_bf16(v.y, h1, l1);
    split_bf16(v.z, h2, l2); split_bf16(v.w, h3, l3);
    hi[i*2+0] = __halves2bfloat162(h0, h1);
    hi[i*2+1] = __halves2bfloat162(h2, h3);
    lo[i*2+0] = __halves2bfloat162(l0, l1);
    lo[i*2+1] = __halves2bfloat162(l2, l3);
}

// ---------------- batched weight transpose+convert: all 6 weights ----------------
__device__ __forceinline__ void wt_tile(const float* __restrict__ W,
                                        __nv_bfloat16* bhi, __nv_bfloat16* blo,
                                        int Nd, int k0, int n0, int tx, int ty,
                                        float t[32][33])
{
#pragma unroll
    for (int i = 0; i < 4; ++i)
        t[ty + i*8][tx] = W[(size_t)(k0 + ty + i*8)*Nd + n0 + tx];
    __syncthreads();
#pragma unroll
    for (int i = 0; i < 4; ++i) {
        int n = ty + i*8;
        float v = t[tx][n];
        __nv_bfloat16 h, l; split_bf16(v, h, l);
        size_t o = (size_t)(n0 + n)*2048 + k0 + tx;
        bhi[o] = h; blo[o] = l;
    }
}

__global__ void convWT_all(
    const float* Wkv, const float* Wvv, const float* Wq,
    const float* Wka, const float* Wva, const float* Wo)
{
    __shared__ float t[32][33];
    int bx = blockIdx.x;
    int tx = threadIdx.x, ty = threadIdx.y;
    if (bx < 1024)       { int l = bx;        wt_tile(Wkv, g_wkv_hi, g_wkv_lo,  512, (l>>4)*32, (l&15)*32, tx, ty, t); }
    else if (bx < 2048)  { int l = bx - 1024; wt_tile(Wvv, g_wvv_hi, g_wvv_lo,  512, (l>>4)*32, (l&15)*32, tx, ty, t); }
    else if (bx < 6144)  { int l = bx - 2048; wt_tile(Wq,  g_wq_hi,  g_wq_lo,  2048, (l>>6)*32, (l&63)*32, tx, ty, t); }
    else if (bx < 7168)  { int l = bx - 6144; wt_tile(Wka, g_wka_hi, g_wka_lo,  512, (l>>4)*32, (l&15)*32, tx, ty, t); }
    else if (bx < 8192)  { int l = bx - 7168; wt_tile(Wva, g_wva_hi, g_wva_lo,  512, (l>>4)*32, (l&15)*32, tx, ty, t); }
    else                 { int l = bx - 8192; wt_tile(Wo,  g_wo_hi,  g_wo_lo,  2048, (l>>6)*32, (l&63)*32, tx, ty, t); }
}

// V [bk][s][d] -> V^T [bk][d][s] bf16 hi/lo
__global__ void convVT_kernel()
{
    __shared__ float t[32][33];
    int z  = blockIdx.z;
    int s0 = blockIdx.y*32;
    int d0 = blockIdx.x*32;
    int tx = threadIdx.x, ty = threadIdx.y;
    const float* V = g_V + (size_t)z*STOT*HDIM;
#pragma unroll
    for (int i = 0; i < 4; ++i)
        t[ty + i*8][tx] = V[(size_t)(s0 + ty + i*8)*HDIM + d0 + tx];
    __syncthreads();
#pragma unroll
    for (int i = 0; i < 4; ++i) {
        int d = ty + i*8;
        float v = t[tx][d];
        __nv_bfloat16 h, l; split_bf16(v, h, l);
        size_t o = (size_t)z*HDIM*STOT + (size_t)(d0 + d)*STOT + s0 + tx;
        g_Vth[o] = h; g_Vtl[o] = l;
    }
}

// ---------------- zero-init + cache copy; cache K goes straight to bf16 ----------
__global__ void zero_copy_kernel(float* out, const float* __restrict__ kc,
                                 const float* __restrict__ vc)
{
    int tid = blockIdx.x*blockDim.x + threadIdx.x;
    int stride = gridDim.x*blockDim.x;
    const int nq = BB*NH*SQA*HDIM;
    const int na = BB*SQA*NH*HDIM;
    const int no = BB*SQA*DMODEL;
    const int nact = BB*NKV*SQA*HDIM;
    const int ncache = BB*NKV*SCACHE*HDIM;
    for (int i = tid; i < nq; i += stride) g_q[i] = 0.f;
    for (int i = tid; i < na; i += stride) g_attn[i] = 0.f;
    for (int i = tid; i < no; i += stride) out[i] = 0.f;
    for (int i = tid; i < nact; i += stride) {
        int d  = i & 127;
        int s  = (i >> 7) & 63;
        int bk = i >> 13;
        int idx = (bk*STOT + (SCACHE + SQV) + s)*HDIM + d;
        g_K[idx] = 0.f;
        g_V[idx] = 0.f;
    }
    for (int i = tid; i < ncache; i += stride) {
        int d  = i & 127;
        int s  = (i >> 7) & 255;
        int bk = i >> 15;
        int dst = (bk*STOT + s)*HDIM + d;
        // cache keys are NOT roped: convert directly to bf16 hi/lo
        __nv_bfloat16 h, l; split_bf16(kc[i], h, l);
        g_Kh[dst] = h; g_Kl[dst] = l;
        g_V[dst] = vc[i];
    }
}

// ---------------- fused RoPE + bf16 conversion (writes hi/lo, not fp32) ---------
#define ROPE_T0 (BB*NKV*SQV*64)
#define ROPE_T1 (BB*NKV*SQA*64)
#define ROPE_T2 (BB*NH*SQA*64)
__global__ void rope_all(const int* __restrict__ pos_vlm, const int* __restrict__ pos_act)
{
    int idx = blockIdx.x*blockDim.x + threadIdx.x;
    int which, nh, seqlen, s_off;
    const int* pos;
    if (idx < ROPE_T0) { which = 0; pos = pos_vlm; nh = NKV; seqlen = SQV; s_off = SCACHE; }
    else if (idx < ROPE_T0 + ROPE_T1) {
        idx -= ROPE_T0; which = 0; pos = pos_act; nh = NKV; seqlen = SQA; s_off = SCACHE + SQV;
    }
    else if (idx < ROPE_T0 + ROPE_T1 + ROPE_T2) {
        idx -= ROPE_T0 + ROPE_T1; which = 1; pos = pos_act; nh = NH; seqlen = SQA; s_off = 0;
    }
    else return;

    int i = idx & 63;
    int rest = idx >> 6;
    int s = rest % seqlen; rest /= seqlen;
    int hh = rest % nh;
    int b  = rest / nh;

    const float* X = (which == 0) ? g_K : g_q;
    __nv_bfloat16* Xh = (which == 0) ? g_Kh : g_qh;
    __nv_bfloat16* Xl = (which == 0) ? g_Kl : g_ql;
    int stot = (which == 0) ? STOT : SQA;

    int p = pos[b*seqlen + s];
    float inv = exp2f(-0.20762050593046868f * (float)i);
    float ang = (float)p * inv;
    double ad  = (double)ang;
    double red = ad - rint(ad * 0.15915494309189535) * 6.283185307179586;
    float c  = cosf((float)red);
    float sn = sinf((float)red);

    size_t base = ((size_t)((b*nh + hh)*stot + s_off + s)) * HDIM;
    float x1 = X[base + i], x2 = X[base + 64 + i];
    float r1 = x1*c - x2*sn;
    float r2 = x2*c + x1*sn;
    __nv_bfloat16 h, l;
    split_bf16(r1, h, l); Xh[base + i] = h;       Xl[base + i] = l;
    split_bf16(r2, h, l); Xh[base + 64 + i] = h;  Xl[base + 64 + i] = l;
}

// ---------------- row softmax -> P bf16 hi/lo ----------------
__global__ void softmax_kernel()
{
    int row  = blockIdx.x*4 + (threadIdx.x >> 5);
    int lane = threadIdx.x & 31;
    const float* p = g_scores + (size_t)row * STOT;

    float vals[42];
    float m = -1e30f;
#pragma unroll
    for (int i = 0; i < 42; i++) { vals[i] = p[i*32 + lane]; m = fmaxf(m, vals[i]); }
#pragma unroll
    for (int off = 16; off > 0; off >>= 1) m = fmaxf(m, __shfl_xor_sync(0xffffffffu, m, off));
    float sum = 0.f;
#pragma unroll
    for (int i = 0; i < 42; i++) { vals[i] = __expf(vals[i] - m); sum += vals[i]; }
#pragma unroll
    for (int off = 16; off > 0; off >>= 1) sum += __shfl_xor_sync(0xffffffffu, sum, off);
    float invs = 1.0f / sum;
    __nv_bfloat16* ph = g_Ph + (size_t)row * STOT;
    __nv_bfloat16* pl = g_Pl + (size_t)row * STOT;
#pragma unroll
    for (int i = 0; i < 42; i++) {
        float v = vals[i] * invs;
        __nv_bfloat16 h, l; split_bf16(v, h, l);
        ph[i*32 + lane] = h;
        pl[i*32 + lane] = l;
    }
}

// ---------------- launch ----------------
extern "C" void kernel_launch(void* const* d_in, const int* in_sizes, int n_in,
                              void* d_out, int out_size)
{
    (void)in_sizes; (void)n_in; (void)out_size;
    const float* mask    = (const float*)d_in[0];
    const int*   pos_vlm = (const int*)  d_in[1];
    const int*   pos_act = (const int*)  d_in[2];
    const float* h_vlm   = (const float*)d_in[3];
    const float* h_act   = (const float*)d_in[4];
    const float* k_cache = (const float*)d_in[5];
    const float* v_cache = (const float*)d_in[6];
    // d_in[7] = Wq_vlm: unused (q_vlm rows are discarded by reference)
    const float* Wk_vlm  = (const float*)d_in[8];
    const float* Wv_vlm  = (const float*)d_in[9];
    const float* Wq_act  = (const float*)d_in[10];
    const float* Wk_act  = (const float*)d_in[11];
    const float* Wv_act  = (const float*)d_in[12];
    const float* Wo_act  = (const float*)d_in[13];
    float* out = (float*)d_out;

    void *p_hv_hi, *p_hv_lo, *p_ha_hi, *p_ha_lo, *p_at_hi, *p_at_lo, *p_attn;
    cudaGetSymbolAddress(&p_hv_hi, g_hv_hi);   cudaGetSymbolAddress(&p_hv_lo, g_hv_lo);
    cudaGetSymbolAddress(&p_ha_hi, g_ha_hi);   cudaGetSymbolAddress(&p_ha_lo, g_ha_lo);
    cudaGetSymbolAddress(&p_at_hi, g_at_hi);   cudaGetSymbolAddress(&p_at_lo, g_at_lo);
    cudaGetSymbolAddress(&p_attn, g_attn);

    cudaFuncSetAttribute(tc_proj,    cudaFuncAttributeMaxDynamicSharedMemorySize, TCG_SMEM_BYTES);
    cudaFuncSetAttribute(tc_wo,      cudaFuncAttributeMaxDynamicSharedMemorySize, TCG_SMEM_BYTES);
    cudaFuncSetAttribute(score_hmma, cudaFuncAttributeMaxDynamicSharedMemorySize, 65536);
    cudaFuncSetAttribute(pv_hmma,    cudaFuncAttributeMaxDynamicSharedMemorySize, 98304);

    // 1. zero + cache copy (cache K straight to bf16 hi/lo)
    zero_copy_kernel<<<1024, 256>>>(out, k_cache, v_cache);

    // 2. activations -> bf16 hi/lo (h_vlm + h_act batched)
    {
        int n40 = 4096*2048/4, n41 = 256*2048/4;
        convA2_kernel<<<(n40 + n41 + 255)/256, 256>>>(
            (const float4*)h_vlm, (__nv_bfloat162*)p_hv_hi, (__nv_bfloat162*)p_hv_lo, n40,
            (const float4*)h_act, (__nv_bfloat162*)p_ha_hi, (__nv_bfloat162*)p_ha_lo, n41);
    }

    // 3. all 6 weight transposes+conversions in one launch
    convWT_all<<<12288, dim3(32, 8)>>>(Wk_vlm, Wv_vlm, Wq_act, Wk_act, Wv_act, Wo_act);

    // 4. ALL projections (vlm KV + act QKV) in ONE launch: 512 + 384 blocks
    tc_proj<<<896, 256, TCG_SMEM_BYTES>>>();

    // 5. RoPE + bf16 conversion fused (writes g_Kh/Kl, g_qh/ql)
    rope_all<<<(ROPE_T0 + ROPE_T1 + ROPE_T2 + 255)/256, 256>>>(pos_vlm, pos_act);

    // 6. V transpose + convert
    convVT_kernel<<<dim3(4, 42, 16), dim3(32, 8)>>>();

    // 7-9. attention on HMMA
    score_hmma<<<dim3(21, 64), 256, 65536>>>(mask);
    softmax_kernel<<<1024, 128>>>();
    pv_hmma<<<dim3(64, 7), 256, 98304>>>();

    // 10. attn -> bf16 hi/lo
    convA2_kernel<<<(256*2048/4 + 255)/256, 256>>>(
        (const float4*)p_attn, (__nv_bfloat162*)p_at_hi, (__nv_bfloat162*)p_at_lo, 256*2048/4,
        nullptr, nullptr, nullptr, 0);

    // 11. output projection, split-K 4
    tc_wo<<<dim3(16, 4, 4), 256, TCG_SMEM_BYTES>>>(out);
}

// round 13
// speedup vs baseline: 3.6049x; 1.0318x over previous
#include <cuda_runtime.h>
#include <cuda_bf16.h>
#include <math.h>
#include <stdint.h>

// ---------------- problem constants ----------------
#define BB      4
#define NH      16
#define NKV     4
#define HDIM    128
#define DMODEL  2048
#define SQV     1024
#define SQA     64
#define SCACHE  256
#define STOT    1344
#define NQROWS  (BB*NH*SQA)

// ---------------- fp32 scratch ----------------
__device__ float g_K[BB*NKV*STOT*HDIM];
__device__ float g_V[BB*NKV*STOT*HDIM];
__device__ float g_q[BB*NH*SQA*HDIM];
__device__ float g_scores[NQROWS*STOT];
__device__ float g_attn[BB*SQA*NH*HDIM];

// ---------------- bf16 split operands (hi + lo) ----------------
__device__ __nv_bfloat16 g_hv_hi[4096*2048], g_hv_lo[4096*2048];
__device__ __nv_bfloat16 g_ha_hi[256*2048],  g_ha_lo[256*2048];
__device__ __nv_bfloat16 g_at_hi[256*2048],  g_at_lo[256*2048];
__device__ __nv_bfloat16 g_wkv_hi[512*2048], g_wkv_lo[512*2048];
__device__ __nv_bfloat16 g_wvv_hi[512*2048], g_wvv_lo[512*2048];
__device__ __nv_bfloat16 g_wq_hi[2048*2048], g_wq_lo[2048*2048];
__device__ __nv_bfloat16 g_wka_hi[512*2048], g_wka_lo[512*2048];
__device__ __nv_bfloat16 g_wva_hi[512*2048], g_wva_lo[512*2048];
__device__ __nv_bfloat16 g_wo_hi[2048*2048], g_wo_lo[2048*2048];

// attention bf16 operands
__device__ __nv_bfloat16 g_qh[BB*NH*SQA*HDIM],  g_ql[BB*NH*SQA*HDIM];
__device__ __nv_bfloat16 g_Kh[BB*NKV*STOT*HDIM], g_Kl[BB*NKV*STOT*HDIM];
__device__ __nv_bfloat16 g_Vth[BB*NKV*HDIM*STOT], g_Vtl[BB*NKV*HDIM*STOT];
__device__ __nv_bfloat16 g_Ph[NQROWS*STOT], g_Pl[NQROWS*STOT];

// ================= PTX helpers =================
__device__ __forceinline__ uint32_t smem_to_u32(const void* p) {
    uint32_t a;
    asm("{ .reg .u64 t; cvta.to.shared.u64 t, %1; cvt.u32.u64 %0, t; }" : "=r"(a) : "l"(p));
    return a;
}
#define CP_ASYNC16(sm, gm) \
    asm volatile("cp.async.cg.shared.global [%0], [%1], 16;" :: "r"(sm), "l"(gm))
#define CP_COMMIT() asm volatile("cp.async.commit_group;" ::: "memory")
#define CP_WAIT(n)  asm volatile("cp.async.wait_group %0;" :: "n"(n) : "memory")

__device__ __forceinline__ void ldsm_x4(uint32_t* r, uint32_t addr) {
    asm volatile("ldmatrix.sync.aligned.m8n8.x4.shared.b16 {%0,%1,%2,%3}, [%4];"
        : "=r"(r[0]), "=r"(r[1]), "=r"(r[2]), "=r"(r[3]) : "r"(addr));
}
__device__ __forceinline__ void mma_bf16(float* d, const uint32_t* a, const uint32_t* b) {
    asm volatile("mma.sync.aligned.m16n8k16.row.col.f32.bf16.bf16.f32 "
        "{%0,%1,%2,%3}, {%4,%5,%6,%7}, {%8,%9}, {%0,%1,%2,%3};"
        : "+f"(d[0]), "+f"(d[1]), "+f"(d[2]), "+f"(d[3])
        : "r"(a[0]), "r"(a[1]), "r"(a[2]), "r"(a[3]), "r"(b[0]), "r"(b[1]));
}
__device__ __forceinline__ uint32_t swz(uint32_t off) { return off ^ ((off >> 3) & 0x70); }

__device__ __forceinline__ void split_bf16(float v, __nv_bfloat16& h, __nv_bfloat16& l) {
    h = __float2bfloat16(v);
    l = __float2bfloat16(v - __bfloat162float(h));
}

// ---------------- output index mapping ----------------
__device__ __forceinline__ int out_index(int map, int r, int c, int N) {
    switch (map) {
        case 1: { int b=r>>10, s=r&1023, kv=c>>7, d=c&127;
                  return (((b*NKV+kv)*STOT) + SCACHE + s)*HDIM + d; }
        case 2: { int b=r>>6, s=r&63, kv=c>>7, d=c&127;
                  return (((b*NKV+kv)*STOT) + (SCACHE+SQV) + s)*HDIM + d; }
        case 3: { int b=r>>6, s=r&63, h=c>>7, d=c&127;
                  return (((b*NH+h)*SQA) + s)*HDIM + d; }
        default: return r*N + c;
    }
}

// ---------------- merged projection GEMM (validated round 12) ----------------
#define TCG_SMEM_BYTES (98304)
__global__ void __launch_bounds__(256, 2) tc_proj()
{
    extern __shared__ char smem[];
    uint32_t sbase = smem_to_u32(smem);

    const int tid = threadIdx.x, lane = tid & 31, wid = tid >> 5;
    const int wm = wid & 1, wn = wid >> 1;

    int bid = blockIdx.x;
    const __nv_bfloat16 *Ahi, *Alo, *Bh, *Bl;
    int m0, n0, kstart, nch, map, dest, Nl;
    bool split;
    const int K = 2048;

    if (bid < 512) {
        int n = bid & 7, m = bid >> 3;
        m0 = m * 64; kstart = 0; nch = 32; split = false;
        Ahi = g_hv_hi; Alo = g_hv_lo;
        int n0g = n * 128;
        if (n0g < 512) { Bh = g_wkv_hi; Bl = g_wkv_lo; n0 = n0g;       map = 1; dest = 0; Nl = 512; }
        else           { Bh = g_wvv_hi; Bl = g_wvv_lo; n0 = n0g - 512; map = 1; dest = 1; Nl = 512; }
    } else {
        int l = bid - 512;
        int n = l % 24; l /= 24;
        int m = l & 3;  int z = l >> 2;
        m0 = m * 64; kstart = z * 512; nch = 8; split = true;
        Ahi = g_ha_hi; Alo = g_ha_lo;
        int n0g = n * 128;
        if (n0g < 2048)      { Bh = g_wq_hi;  Bl = g_wq_lo;  n0 = n0g;        map = 3; dest = 2; Nl = 2048; }
        else if (n0g < 2560) { Bh = g_wka_hi; Bl = g_wka_lo; n0 = n0g - 2048; map = 2; dest = 0; Nl = 512; }
        else                 { Bh = g_wva_hi; Bl = g_wva_lo; n0 = n0g - 2560; map = 2; dest = 1; Nl = 512; }
    }

    auto load_stage = [&](int stage, int kof) {
        uint32_t stb = sbase + stage * 49152;
#pragma unroll
        for (int it = 0; it < 2; ++it) {
            int idx = tid + it * 256;
            int r = idx >> 3, ch = idx & 7;
            uint32_t so = swz((uint32_t)(r * 128 + ch * 16));
            CP_ASYNC16(stb + so,        Ahi + (size_t)(m0 + r) * K + kof + ch * 8);
            CP_ASYNC16(stb + 8192 + so, Alo + (size_t)(m0 + r) * K + kof + ch * 8);
        }
#pragma unroll
        for (int it = 0; it < 4; ++it) {
            int idx = tid + it * 256;
            int r = idx >> 3, ch = idx & 7;
            uint32_t so = swz((uint32_t)(r * 128 + ch * 16));
            CP_ASYNC16(stb + 16384 + so, Bh + (size_t)(n0 + r) * K + kof + ch * 8);
            CP_ASYNC16(stb + 32768 + so, Bl + (size_t)(n0 + r) * K + kof + ch * 8);
        }
    };

    float acc[2][4][4];
#pragma unroll
    for (int i = 0; i < 2; ++i)
#pragma unroll
        for (int j = 0; j < 4; ++j)
#pragma unroll
            for (int k = 0; k < 4; ++k) acc[i][j][k] = 0.f;

    load_stage(0, kstart);
    CP_COMMIT();

    const uint32_t aRow = wm * 32 + (lane & 15);
    const uint32_t aKof = (lane >> 4) * 8;
    const uint32_t bRow = wn * 32 + ((lane >> 4) * 8) + (lane & 7);
    const uint32_t bKof = ((lane >> 3) & 1) * 8;

    for (int c = 0; c < nch; ++c) {
        if (c + 1 < nch) { load_stage((c + 1) & 1, kstart + (c + 1) * 64); CP_COMMIT(); CP_WAIT(1); }
        else             { CP_WAIT(0); }
        __syncthreads();

        uint32_t st = sbase + (c & 1) * 49152;
        uint32_t tAhi = st, tAlo = st + 8192, tBhi = st + 16384, tBlo = st + 32768;

#pragma unroll
        for (int ks = 0; ks < 4; ++ks) {
            uint32_t ahi[2][4], alo[2][4];
#pragma unroll
            for (int mt = 0; mt < 2; ++mt) {
                uint32_t off = swz((aRow + mt * 16) * 128 + (ks * 16 + aKof) * 2);
                ldsm_x4(ahi[mt], tAhi + off);
                ldsm_x4(alo[mt], tAlo + off);
            }
            uint32_t bhi[2][4], blo[2][4];
#pragma unroll
            for (int g = 0; g < 2; ++g) {
                uint32_t off = swz((bRow + g * 16) * 128 + (ks * 16 + bKof) * 2);
                ldsm_x4(bhi[g], tBhi + off);
                ldsm_x4(blo[g], tBlo + off);
            }
#pragma unroll
            for (int mt = 0; mt < 2; ++mt)
#pragma unroll
                for (int nt = 0; nt < 4; ++nt) {
                    const uint32_t* bh4 = &bhi[nt >> 1][(nt & 1) * 2];
                    const uint32_t* bl4 = &blo[nt >> 1][(nt & 1) * 2];
                    mma_bf16(acc[mt][nt], ahi[mt], bh4);
                    mma_bf16(acc[mt][nt], ahi[mt], bl4);
                    mma_bf16(acc[mt][nt], alo[mt], bh4);
                }
        }
        __syncthreads();
    }

    float* C = (dest == 0) ? g_K : (dest == 1) ? g_V : g_q;
#pragma unroll
    for (int mt = 0; mt < 2; ++mt)
#pragma unroll
        for (int nt = 0; nt < 4; ++nt)
#pragma unroll
            for (int e = 0; e < 4; ++e) {
                int r = m0 + wm * 32 + mt * 16 + (lane >> 2) + (e >> 1) * 8;
                int cc = n0 + wn * 32 + nt * 8 + 2 * (lane & 3) + (e & 1);
                int idx = out_index(map, r, cc, Nl);
                if (split) atomicAdd(&C[idx], acc[mt][nt][e]);
                else       C[idx] = acc[mt][nt][e];
            }
}

// ---------------- Wo GEMM (validated round 12) ----------------
__global__ void __launch_bounds__(256, 2) tc_wo(float* __restrict__ Cext)
{
    extern __shared__ char smem[];
    uint32_t sbase = smem_to_u32(smem);

    const int tid = threadIdx.x, lane = tid & 31, wid = tid >> 5;
    const int wm = wid & 1, wn = wid >> 1;
    const int m0 = blockIdx.y * 64;
    const int n0 = blockIdx.x * 128;
    const int kstart = blockIdx.z * 512;
    const int K = 2048, nch = 8;

    auto load_stage = [&](int stage, int kof) {
        uint32_t stb = sbase + stage * 49152;
#pragma unroll
        for (int it = 0; it < 2; ++it) {
            int idx = tid + it * 256;
            int r = idx >> 3, ch = idx & 7;
            uint32_t so = swz((uint32_t)(r * 128 + ch * 16));
            CP_ASYNC16(stb + so,        g_at_hi + (size_t)(m0 + r) * K + kof + ch * 8);
            CP_ASYNC16(stb + 8192 + so, g_at_lo + (size_t)(m0 + r) * K + kof + ch * 8);
        }
#pragma unroll
        for (int it = 0; it < 4; ++it) {
            int idx = tid + it * 256;
            int r = idx >> 3, ch = idx & 7;
            uint32_t so = swz((uint32_t)(r * 128 + ch * 16));
            CP_ASYNC16(stb + 16384 + so, g_wo_hi + (size_t)(n0 + r) * K + kof + ch * 8);
            CP_ASYNC16(stb + 32768 + so, g_wo_lo + (size_t)(n0 + r) * K + kof + ch * 8);
        }
    };

    float acc[2][4][4];
#pragma unroll
    for (int i = 0; i < 2; ++i)
#pragma unroll
        for (int j = 0; j < 4; ++j)
#pragma unroll
            for (int k = 0; k < 4; ++k) acc[i][j][k] = 0.f;

    load_stage(0, kstart);
    CP_COMMIT();

    const uint32_t aRow = wm * 32 + (lane & 15);
    const uint32_t aKof = (lane >> 4) * 8;
    const uint32_t bRow = wn * 32 + ((lane >> 4) * 8) + (lane & 7);
    const uint32_t bKof = ((lane >> 3) & 1) * 8;

    for (int c = 0; c < nch; ++c) {
        if (c + 1 < nch) { load_stage((c + 1) & 1, kstart + (c + 1) * 64); CP_COMMIT(); CP_WAIT(1); }
        else             { CP_WAIT(0); }
        __syncthreads();

        uint32_t st = sbase + (c & 1) * 49152;
        uint32_t tAhi = st, tAlo = st + 8192, tBhi = st + 16384, tBlo = st + 32768;

#pragma unroll
        for (int ks = 0; ks < 4; ++ks) {
            uint32_t ahi[2][4], alo[2][4];
#pragma unroll
            for (int mt = 0; mt < 2; ++mt) {
                uint32_t off = swz((aRow + mt * 16) * 128 + (ks * 16 + aKof) * 2);
                ldsm_x4(ahi[mt], tAhi + off);
                ldsm_x4(alo[mt], tAlo + off);
            }
            uint32_t bhi[2][4], blo[2][4];
#pragma unroll
            for (int g = 0; g < 2; ++g) {
                uint32_t off = swz((bRow + g * 16) * 128 + (ks * 16 + bKof) * 2);
                ldsm_x4(bhi[g], tBhi + off);
                ldsm_x4(blo[g], tBlo + off);
            }
#pragma unroll
            for (int mt = 0; mt < 2; ++mt)
#pragma unroll
                for (int nt = 0; nt < 4; ++nt) {
                    const uint32_t* bh4 = &bhi[nt >> 1][(nt & 1) * 2];
                    const uint32_t* bl4 = &blo[nt >> 1][(nt & 1) * 2];
                    mma_bf16(acc[mt][nt], ahi[mt], bh4);
                    mma_bf16(acc[mt][nt], ahi[mt], bl4);
                    mma_bf16(acc[mt][nt], alo[mt], bh4);
                }
        }
        __syncthreads();
    }

#pragma unroll
    for (int mt = 0; mt < 2; ++mt)
#pragma unroll
        for (int nt = 0; nt < 4; ++nt)
#pragma unroll
            for (int e = 0; e < 4; ++e) {
                int r = m0 + wm * 32 + mt * 16 + (lane >> 2) + (e >> 1) * 8;
                int cc = n0 + wn * 32 + nt * 8 + 2 * (lane & 3) + (e & 1);
                atomicAdd(&Cext[(size_t)r * 2048 + cc], acc[mt][nt][e]);
            }
}

// ---------------- HMMA attention scores (validated) ----------------
__global__ void __launch_bounds__(256) score_hmma(const float* __restrict__ mask)
{
    extern __shared__ char smem[];
    uint32_t sbase = smem_to_u32(smem);

    const int tid = threadIdx.x, lane = tid & 31, wid = tid >> 5;
    const int wm = wid & 1, wn = wid >> 1;
    int bh = blockIdx.y;
    int b = bh >> 4, h = bh & 15, kv = h >> 2;
    int s0 = blockIdx.x * 64;
    (void)h;

#pragma unroll
    for (int it = 0; it < 2; ++it) {
        int idx = tid + it * 256;
        int r = idx >> 3, ch = idx & 7;
        uint32_t so = swz((uint32_t)(r * 128 + ch * 16));
        size_t qoff = (size_t)(bh * 64 + r) * HDIM;
        size_t koff = (size_t)((b * NKV + kv) * STOT + s0 + r) * HDIM;
#pragma unroll
        for (int c = 0; c < 2; ++c) {
            CP_ASYNC16(sbase + (0 + c) * 8192 + so, g_qh + qoff + c * 64 + ch * 8);
            CP_ASYNC16(sbase + (2 + c) * 8192 + so, g_ql + qoff + c * 64 + ch * 8);
            CP_ASYNC16(sbase + (4 + c) * 8192 + so, g_Kh + koff + c * 64 + ch * 8);
            CP_ASYNC16(sbase + (6 + c) * 8192 + so, g_Kl + koff + c * 64 + ch * 8);
        }
    }
    CP_COMMIT();
    CP_WAIT(0);
    __syncthreads();

    float acc[2][2][4];
#pragma unroll
    for (int i = 0; i < 2; ++i)
#pragma unroll
        for (int j = 0; j < 2; ++j)
#pragma unroll
            for (int k = 0; k < 4; ++k) acc[i][j][k] = 0.f;

    const uint32_t aRow = wm * 32 + (lane & 15);
    const uint32_t aKof = (lane >> 4) * 8;
    const uint32_t bRow = wn * 16 + ((lane >> 4) * 8) + (lane & 7);
    const uint32_t bKof = ((lane >> 3) & 1) * 8;

#pragma unroll
    for (int c = 0; c < 2; ++c) {
        uint32_t tqh = sbase + (0 + c) * 8192, tql = sbase + (2 + c) * 8192;
        uint32_t tkh = sbase + (4 + c) * 8192, tkl = sbase + (6 + c) * 8192;
#pragma unroll
        for (int ks = 0; ks < 4; ++ks) {
            uint32_t ahi[2][4], alo[2][4];
#pragma unroll
            for (int mt = 0; mt < 2; ++mt) {
                uint32_t off = swz((aRow + mt * 16) * 128 + (ks * 16 + aKof) * 2);
                ldsm_x4(ahi[mt], tqh + off);
                ldsm_x4(alo[mt], tql + off);
            }
            uint32_t bh4[4], bl4[4];
            {
                uint32_t off = swz(bRow * 128 + (ks * 16 + bKof) * 2);
                ldsm_x4(bh4, tkh + off);
                ldsm_x4(bl4, tkl + off);
            }
#pragma unroll
            for (int mt = 0; mt < 2; ++mt)
#pragma unroll
                for (int nt = 0; nt < 2; ++nt) {
                    mma_bf16(acc[mt][nt], ahi[mt], &bh4[nt * 2]);
                    mma_bf16(acc[mt][nt], ahi[mt], &bl4[nt * 2]);
                    mma_bf16(acc[mt][nt], alo[mt], &bh4[nt * 2]);
                }
        }
    }

    const float scale = 0.08838834764831845f;
#pragma unroll
    for (int mt = 0; mt < 2; ++mt)
#pragma unroll
        for (int nt = 0; nt < 2; ++nt)
#pragma unroll
            for (int e = 0; e < 4; ++e) {
                int q = wm * 32 + mt * 16 + (lane >> 2) + (e >> 1) * 8;
                int s = s0 + wn * 16 + nt * 8 + 2 * (lane & 3) + (e & 1);
                float v = acc[mt][nt][e] * scale;
                v = tanhf(v * 0.02f) * 50.0f
                  + mask[(size_t)b * (1088 * 1344) + (size_t)(1024 + q) * 1344 + s];
                g_scores[(size_t)(bh * 64 + q) * STOT + s] = v;
            }
}

// ---------------- HMMA P @ V (validated) ----------------
__global__ void __launch_bounds__(256) pv_hmma()
{
    extern __shared__ char smem[];
    uint32_t sbase = smem_to_u32(smem);

    const int tid = threadIdx.x, lane = tid & 31, wid = tid >> 5;
    const int wm = wid & 1, wn = wid >> 1;
    int bh = blockIdx.x;
    int b = bh >> 4, h = bh & 15, kv = h >> 2;
    int kc0 = blockIdx.y * 192;

    size_t prow0 = (size_t)bh * 64;
    size_t vrow0 = (size_t)(b * NKV + kv) * HDIM;

    auto load_sub = [&](int stage, int kc) {
        uint32_t stb = sbase + stage * 49152;
#pragma unroll
        for (int it = 0; it < 2; ++it) {
            int idx = tid + it * 256;
            int r = idx >> 3, ch = idx & 7;
            uint32_t so = swz((uint32_t)(r * 128 + ch * 16));
            CP_ASYNC16(stb + so,        g_Ph + (prow0 + r) * STOT + kc + ch * 8);
            CP_ASYNC16(stb + 8192 + so, g_Pl + (prow0 + r) * STOT + kc + ch * 8);
        }
#pragma unroll
        for (int it = 0; it < 4; ++it) {
            int idx = tid + it * 256;
            int r = idx >> 3, ch = idx & 7;
            uint32_t so = swz((uint32_t)(r * 128 + ch * 16));
            CP_ASYNC16(stb + 16384 + so, g_Vth + (vrow0 + r) * STOT + kc + ch * 8);
            CP_ASYNC16(stb + 32768 + so, g_Vtl + (vrow0 + r) * STOT + kc + ch * 8);
        }
    };

    float acc[2][4][4];
#pragma unroll
    for (int i = 0; i < 2; ++i)
#pragma unroll
        for (int j = 0; j < 4; ++j)
#pragma unroll
            for (int k = 0; k < 4; ++k) acc[i][j][k] = 0.f;

    load_sub(0, kc0);
    CP_COMMIT();

    const uint32_t aRow = wm * 32 + (lane & 15);
    const uint32_t aKof = (lane >> 4) * 8;
    const uint32_t bRow = wn * 32 + ((lane >> 4) * 8) + (lane & 7);
    const uint32_t bKof = ((lane >> 3) & 1) * 8;

    for (int sub = 0; sub < 3; ++sub) {
        if (sub + 1 < 3) { load_sub((sub + 1) & 1, kc0 + (sub + 1) * 64); CP_COMMIT(); CP_WAIT(1); }
        else             { CP_WAIT(0); }
        __syncthreads();

        uint32_t st = sbase + (sub & 1) * 49152;
        uint32_t tph = st, tpl = st + 8192, tvh = st + 16384, tvl = st + 32768;

#pragma unroll
        for (int ks = 0; ks < 4; ++ks) {
            uint32_t ahi[2][4], alo[2][4];
#pragma unroll
            for (int mt = 0; mt < 2; ++mt) {
                uint32_t off = swz((aRow + mt * 16) * 128 + (ks * 16 + aKof) * 2);
                ldsm_x4(ahi[mt], tph + off);
                ldsm_x4(alo[mt], tpl + off);
            }
            uint32_t bhi[2][4], blo[2][4];
#pragma unroll
            for (int g = 0; g < 2; ++g) {
                uint32_t off = swz((bRow + g * 16) * 128 + (ks * 16 + bKof) * 2);
                ldsm_x4(bhi[g], tvh + off);
                ldsm_x4(blo[g], tvl + off);
            }
#pragma unroll
            for (int mt = 0; mt < 2; ++mt)
#pragma unroll
                for (int nt = 0; nt < 4; ++nt) {
                    const uint32_t* bh4 = &bhi[nt >> 1][(nt & 1) * 2];
                    const uint32_t* bl4 = &blo[nt >> 1][(nt & 1) * 2];
                    mma_bf16(acc[mt][nt], ahi[mt], bh4);
                    mma_bf16(acc[mt][nt], ahi[mt], bl4);
                    mma_bf16(acc[mt][nt], alo[mt], bh4);
                }
        }
        __syncthreads();
    }

#pragma unroll
    for (int mt = 0; mt < 2; ++mt)
#pragma unroll
        for (int nt = 0; nt < 4; ++nt)
#pragma unroll
            for (int e = 0; e < 4; ++e) {
                int q = wm * 32 + mt * 16 + (lane >> 2) + (e >> 1) * 8;
                int d = wn * 32 + nt * 8 + 2 * (lane & 3) + (e & 1);
                atomicAdd(&g_attn[(size_t)(b * SQA + q) * (NH * HDIM) + h * HDIM + d],
                          acc[mt][nt][e]);
            }
}

// ---------------- conversion helpers ----------------
__device__ __forceinline__ void convA_elem(const float4* x, __nv_bfloat162* hi,
                                           __nv_bfloat162* lo, int i)
{
    float4 v = x[i];
    __nv_bfloat16 h0, h1, h2, h3, l0, l1, l2, l3;
    split_bf16(v.x, h0, l0); split_bf16(v.y, h1, l1);
    split_bf16(v.z, h2, l2); split_bf16(v.w, h3, l3);
    hi[i*2+0] = __halves2bfloat162(h0, h1);
    hi[i*2+1] = __halves2bfloat162(h2, h3);
    lo[i*2+0] = __halves2bfloat162(l0, l1);
    lo[i*2+1] = __halves2bfloat162(l2, l3);
}

__device__ __forceinline__ void wt_tile(const float* __restrict__ W,
                                        __nv_bfloat16* bhi, __nv_bfloat16* blo,
                                        int Nd, int k0, int n0, int tx, int ty,
                                        float t[32][33])
{
#pragma unroll
    for (int i = 0; i < 4; ++i)
        t[ty + i*8][tx] = W[(size_t)(k0 + ty + i*8)*Nd + n0 + tx];
    __syncthreads();
#pragma unroll
    for (int i = 0; i < 4; ++i) {
        int n = ty + i*8;
        float v = t[tx][n];
        __nv_bfloat16 h, l; split_bf16(v, h, l);
        size_t o = (size_t)(n0 + n)*2048 + k0 + tx;
        bhi[o] = h; blo[o] = l;
    }
}

// ================= prep1: zero_copy + convA2(hv,ha) + convWT_all in one launch =====
// Block ranges:
//   [0, 1024)               zero + cache copy (grid-stride over fixed 1024-block range)
//   [1024, 1024+8192)       convA h_vlm   (2,097,152 float4)
//   [9216, 9216+512)        convA h_act   (131,072 float4)
//   [9728, 9728+12288)      convWT all 6 weights
#define PREP1_BLOCKS (1024 + 8192 + 512 + 12288)
__global__ void __launch_bounds__(256) prep1_kernel(
    float* out, const float* __restrict__ kc, const float* __restrict__ vc,
    const float* __restrict__ h_vlm, const float* __restrict__ h_act,
    const float* Wkv, const float* Wvv, const float* Wq,
    const float* Wka, const float* Wva, const float* Wo)
{
    __shared__ float t[32][33];
    int bid = blockIdx.x;

    if (bid < 1024) {
        int tid = bid * 256 + threadIdx.x;
        const int stride = 1024 * 256;
        const int nq = BB*NH*SQA*HDIM;
        const int na = BB*SQA*NH*HDIM;
        const int no = BB*SQA*DMODEL;
        const int nact = BB*NKV*SQA*HDIM;
        const int ncache = BB*NKV*SCACHE*HDIM;
        for (int i = tid; i < nq; i += stride) g_q[i] = 0.f;
        for (int i = tid; i < na; i += stride) g_attn[i] = 0.f;
        for (int i = tid; i < no; i += stride) out[i] = 0.f;
        for (int i = tid; i < nact; i += stride) {
            int d  = i & 127;
            int s  = (i >> 7) & 63;
            int bk = i >> 13;
            int idx = (bk*STOT + (SCACHE + SQV) + s)*HDIM + d;
            g_K[idx] = 0.f;
            g_V[idx] = 0.f;
        }
        for (int i = tid; i < ncache; i += stride) {
            int d  = i & 127;
            int s  = (i >> 7) & 255;
            int bk = i >> 15;
            int dst = (bk*STOT + s)*HDIM + d;
            __nv_bfloat16 h, l; split_bf16(kc[i], h, l);
            g_Kh[dst] = h; g_Kl[dst] = l;     // cache keys NOT roped
            g_V[dst] = vc[i];
        }
    } else if (bid < 9216) {
        int i = (bid - 1024) * 256 + threadIdx.x;   // < 2097152 always
        convA_elem((const float4*)h_vlm, (__nv_bfloat162*)g_hv_hi, (__nv_bfloat162*)g_hv_lo, i);
    } else if (bid < 9728) {
        int i = (bid - 9216) * 256 + threadIdx.x;   // < 131072 always
        convA_elem((const float4*)h_act, (__nv_bfloat162*)g_ha_hi, (__nv_bfloat162*)g_ha_lo, i);
    } else {
        int bx = bid - 9728;
        int tx = threadIdx.x & 31, ty = threadIdx.x >> 5;
        if (bx < 1024)       { int l = bx;        wt_tile(Wkv, g_wkv_hi, g_wkv_lo,  512, (l>>4)*32, (l&15)*32, tx, ty, t); }
        else if (bx < 2048)  { int l = bx - 1024; wt_tile(Wvv, g_wvv_hi, g_wvv_lo,  512, (l>>4)*32, (l&15)*32, tx, ty, t); }
        else if (bx < 6144)  { int l = bx - 2048; wt_tile(Wq,  g_wq_hi,  g_wq_lo,  2048, (l>>6)*32, (l&63)*32, tx, ty, t); }
        else if (bx < 7168)  { int l = bx - 6144; wt_tile(Wka, g_wka_hi, g_wka_lo,  512, (l>>4)*32, (l&15)*32, tx, ty, t); }
        else if (bx < 8192)  { int l = bx - 7168; wt_tile(Wva, g_wva_hi, g_wva_lo,  512, (l>>4)*32, (l&15)*32, tx, ty, t); }
        else                 { int l = bx - 8192; wt_tile(Wo,  g_wo_hi,  g_wo_lo,  2048, (l>>6)*32, (l&63)*32, tx, ty, t); }
    }
}

// ================= prep2: rope_all + convVT in one launch =====
// Block ranges: [0, 5376) rope (1,376,256 threads); [5376, 5376+2688) convVT tiles.
#define ROPE_T0 (BB*NKV*SQV*64)
#define ROPE_T1 (BB*NKV*SQA*64)
#define ROPE_T2 (BB*NH*SQA*64)
#define PREP2_BLOCKS (5376 + 2688)
__global__ void __launch_bounds__(256) prep2_kernel(
    const int* __restrict__ pos_vlm, const int* __restrict__ pos_act)
{
    __shared__ float t[32][33];
    int bid = blockIdx.x;

    if (bid < 5376) {
        int idx = bid * 256 + threadIdx.x;
        int which, nh, seqlen, s_off;
        const int* pos;
        if (idx < ROPE_T0) { which = 0; pos = pos_vlm; nh = NKV; seqlen = SQV; s_off = SCACHE; }
        else if (idx < ROPE_T0 + ROPE_T1) {
            idx -= ROPE_T0; which = 0; pos = pos_act; nh = NKV; seqlen = SQA; s_off = SCACHE + SQV;
        }
        else {
            idx -= ROPE_T0 + ROPE_T1; which = 1; pos = pos_act; nh = NH; seqlen = SQA; s_off = 0;
        }
        // total = 1376256 = 5376*256 exactly, no overflow check needed

        int i = idx & 63;
        int rest = idx >> 6;
        int s = rest % seqlen; rest /= seqlen;
        int hh = rest % nh;
        int b  = rest / nh;

        const float* X = (which == 0) ? g_K : g_q;
        __nv_bfloat16* Xh = (which == 0) ? g_Kh : g_qh;
        __nv_bfloat16* Xl = (which == 0) ? g_Kl : g_ql;
        int stot = (which == 0) ? STOT : SQA;

        int p = pos[b*seqlen + s];
        float inv = exp2f(-0.20762050593046868f * (float)i);
        float ang = (float)p * inv;
        double ad  = (double)ang;
        double red = ad - rint(ad * 0.15915494309189535) * 6.283185307179586;
        float c  = cosf((float)red);
        float sn = sinf((float)red);

        size_t base = ((size_t)((b*nh + hh)*stot + s_off + s)) * HDIM;
        float x1 = X[base + i], x2 = X[base + 64 + i];
        float r1 = x1*c - x2*sn;
        float r2 = x2*c + x1*sn;
        __nv_bfloat16 h, l;
        split_bf16(r1, h, l); Xh[base + i] = h;       Xl[base + i] = l;
        split_bf16(r2, h, l); Xh[base + 64 + i] = h;  Xl[base + 64 + i] = l;
    } else {
        // convVT: 2688 tiles = 4 d-blocks x 42 s-blocks x 16 bk
        int l = bid - 5376;
        int d0 = (l & 3) * 32;
        int s0 = ((l >> 2) % 42) * 32;
        int z  = l / 168;
        int tx = threadIdx.x & 31, ty = threadIdx.x >> 5;
        const float* V = g_V + (size_t)z*STOT*HDIM;
#pragma unroll
        for (int i = 0; i < 4; ++i)
            t[ty + i*8][tx] = V[(size_t)(s0 + ty + i*8)*HDIM + d0 + tx];
        __syncthreads();
#pragma unroll
        for (int i = 0; i < 4; ++i) {
            int d = ty + i*8;
            float v = t[tx][d];
            __nv_bfloat16 h, l2; split_bf16(v, h, l2);
            size_t o = (size_t)z*HDIM*STOT + (size_t)(d0 + d)*STOT + s0 + tx;
            g_Vth[o] = h; g_Vtl[o] = l2;
        }
    }
}

// ---------------- attn -> bf16 hi/lo ----------------
__global__ void convAT_kernel()
{
    int i = blockIdx.x*blockDim.x + threadIdx.x;
    if (i >= 256*2048/4) return;
    convA_elem((const float4*)g_attn, (__nv_bfloat162*)g_at_hi, (__nv_bfloat162*)g_at_lo, i);
}

// ---------------- row softmax -> P bf16 hi/lo ----------------
__global__ void softmax_kernel()
{
    int row  = blockIdx.x*4 + (threadIdx.x >> 5);
    int lane = threadIdx.x & 31;
    const float* p = g_scores + (size_t)row * STOT;

    float vals[42];
    float m = -1e30f;
#pragma unroll
    for (int i = 0; i < 42; i++) { vals[i] = p[i*32 + lane]; m = fmaxf(m, vals[i]); }
#pragma unroll
    for (int off = 16; off > 0; off >>= 1) m = fmaxf(m, __shfl_xor_sync(0xffffffffu, m, off));
    float sum = 0.f;
#pragma unroll
    for (int i = 0; i < 42; i++) { vals[i] = __expf(vals[i] - m); sum += vals[i]; }
#pragma unroll
    for (int off = 16; off > 0; off >>= 1) sum += __shfl_xor_sync(0xffffffffu, sum, off);
    float invs = 1.0f / sum;
    __nv_bfloat16* ph = g_Ph + (size_t)row * STOT;
    __nv_bfloat16* pl = g_Pl + (size_t)row * STOT;
#pragma unroll
    for (int i = 0; i < 42; i++) {
        float v = vals[i] * invs;
        __nv_bfloat16 h, l; split_bf16(v, h, l);
        ph[i*32 + lane] = h;
        pl[i*32 + lane] = l;
    }
}

// ---------------- launch ----------------
extern "C" void kernel_launch(void* const* d_in, const int* in_sizes, int n_in,
                              void* d_out, int out_size)
{
    (void)in_sizes; (void)n_in; (void)out_size;
    const float* mask    = (const float*)d_in[0];
    const int*   pos_vlm = (const int*)  d_in[1];
    const int*   pos_act = (const int*)  d_in[2];
    const float* h_vlm   = (const float*)d_in[3];
    const float* h_act   = (const float*)d_in[4];
    const float* k_cache = (const float*)d_in[5];
    const float* v_cache = (const float*)d_in[6];
    // d_in[7] = Wq_vlm: unused (q_vlm rows are discarded by reference)
    const float* Wk_vlm  = (const float*)d_in[8];
    const float* Wv_vlm  = (const float*)d_in[9];
    const float* Wq_act  = (const float*)d_in[10];
    const float* Wk_act  = (const float*)d_in[11];
    const float* Wv_act  = (const float*)d_in[12];
    const float* Wo_act  = (const float*)d_in[13];
    float* out = (float*)d_out;

    cudaFuncSetAttribute(tc_proj,    cudaFuncAttributeMaxDynamicSharedMemorySize, TCG_SMEM_BYTES);
    cudaFuncSetAttribute(tc_wo,      cudaFuncAttributeMaxDynamicSharedMemorySize, TCG_SMEM_BYTES);
    cudaFuncSetAttribute(score_hmma, cudaFuncAttributeMaxDynamicSharedMemorySize, 65536);
    cudaFuncSetAttribute(pv_hmma,    cudaFuncAttributeMaxDynamicSharedMemorySize, 98304);

    // 1. prep1: zero/copy + activation conversions + weight transposes (one launch)
    prep1_kernel<<<PREP1_BLOCKS, 256>>>(out, k_cache, v_cache, h_vlm, h_act,
                                        Wk_vlm, Wv_vlm, Wq_act, Wk_act, Wv_act, Wo_act);

    // 2. ALL projections (vlm KV + act QKV) in ONE launch
    tc_proj<<<896, 256, TCG_SMEM_BYTES>>>();

    // 3. prep2: RoPE+bf16 conversion + V transpose (one launch)
    prep2_kernel<<<PREP2_BLOCKS, 256>>>(pos_vlm, pos_act);

    // 4-6. attention on HMMA
    score_hmma<<<dim3(21, 64), 256, 65536>>>(mask);
    softmax_kernel<<<1024, 128>>>();
    pv_hmma<<<dim3(64, 7), 256, 98304>>>();

    // 7. attn -> bf16 hi/lo
    convAT_kernel<<<(256*2048/4 + 255)/256, 256>>>();

    // 8. output projection, split-K 4
    tc_wo<<<dim3(16, 4, 4), 256, TCG_SMEM_BYTES>>>(out);
}